// round 1
// baseline (speedup 1.0000x reference)
#include <cuda_runtime.h>
#include <math.h>
#include <stdint.h>

// Problem constants
#define Bk   4
#define Lk   2048
#define Dk   256
#define Hk   4
#define NLk  4
#define Vk   32000
#define DHk  64
#define MR   (Bk*Lk)      // 8192 rows
#define FFD  (4*Dk)       // 1024

// ---------------- scratch (static __device__, no allocation) ----------------
__device__ float g_X [MR*Dk];
__device__ float g_XN[MR*Dk];
__device__ float g_Q [MR*Dk];
__device__ float g_K [MR*Dk];
__device__ float g_V [MR*Dk];
__device__ float g_AO[MR*Dk];
__device__ float g_F1[MR*FFD];

// ---------------- embedding: X = tok_emb[ids] + type_emb[tts] ----------------
__global__ void embed_kernel(const int* __restrict__ ids, const int* __restrict__ tts,
                             const float* __restrict__ te, const float* __restrict__ ye,
                             float* __restrict__ X)
{
    int i = blockIdx.x * 256 + threadIdx.x;          // < MR*Dk
    int row = i >> 8;
    int d   = i & 255;
    X[i] = te[(size_t)ids[row] * Dk + d] + ye[(size_t)tts[row] * Dk + d];
}

// ---------------- RMSNorm: one block (256 thr) per row ----------------
__global__ __launch_bounds__(256) void rmsnorm_kernel(const float* __restrict__ X,
                                                      const float* __restrict__ w,
                                                      float* __restrict__ Y)
{
    int r = blockIdx.x;
    int t = threadIdx.x;
    float v = X[(size_t)r * Dk + t];
    float s = v * v;
    #pragma unroll
    for (int o = 16; o > 0; o >>= 1) s += __shfl_down_sync(0xffffffffu, s, o);
    __shared__ float ws[8];
    __shared__ float tot;
    int lane = t & 31, wi = t >> 5;
    if (lane == 0) ws[wi] = s;
    __syncthreads();
    if (t == 0) {
        float a = 0.f;
        #pragma unroll
        for (int i = 0; i < 8; i++) a += ws[i];
        tot = a;
    }
    __syncthreads();
    float rs = rsqrtf(tot * (1.0f / Dk) + 1.1920929e-07f);
    Y[(size_t)r * Dk + t] = v * rs * w[t];
}

// ---------------- RoPE (in place on Q or K) ----------------
// thread handles pair (j, j+32) within one head; i over MR*Hk*32
__global__ void rope_kernel(float* __restrict__ P)
{
    int i   = blockIdx.x * 256 + threadIdx.x;
    int t   = i & 31;
    int h   = (i >> 5) & 3;
    int row = i >> 7;                 // b*L + l
    int pos = row & (Lk - 1);         // l (L is power of 2)
    float inv = exp2f(-(float)t * (13.287712379549449f / 32.0f)); // 10000^(-t/32)
    float ang = (float)pos * inv;
    float sn, cs;
    sincosf(ang, &sn, &cs);
    size_t base = (size_t)row * Dk + h * DHk;
    float a = P[base + t];
    float b = P[base + t + 32];
    P[base + t]      = a * cs - b * sn;
    P[base + t + 32] = b * cs + a * sn;
}

// ---------------- causal flash attention (fp32, 1 thread = 1 query) ----------------
__global__ __launch_bounds__(128) void attn_kernel(const float* __restrict__ Q,
                                                   const float* __restrict__ K,
                                                   const float* __restrict__ V,
                                                   const int*   __restrict__ mask,
                                                   float* __restrict__ O)
{
    int b  = blockIdx.z;
    int h  = blockIdx.y;
    int qi = blockIdx.x * 128 + threadIdx.x;

    float q[64], acc[64];
    {
        const float4* Qp = (const float4*)(Q + ((size_t)(b * Lk + qi)) * Dk + h * DHk);
        #pragma unroll
        for (int d4 = 0; d4 < 16; d4++) {
            float4 tq = Qp[d4];
            q[4*d4+0] = tq.x; q[4*d4+1] = tq.y; q[4*d4+2] = tq.z; q[4*d4+3] = tq.w;
        }
    }
    #pragma unroll
    for (int d = 0; d < 64; d++) acc[d] = 0.f;
    float m = -1e30f, l = 0.f;

    __shared__ float4 Ks[512];   // 32 keys x 16 float4
    __shared__ float4 Vs[512];

    int nkt = 4 * (blockIdx.x + 1);          // key tiles covering keys <= qmax
    const int* mrow = mask + (size_t)b * Lk;

    for (int kt = 0; kt < nkt; kt++) {
        int key0 = kt * 32;
        __syncthreads();
        for (int i = threadIdx.x; i < 512; i += 128) {
            int kr = key0 + (i >> 4);
            size_t base4 = (size_t)(b * Lk + kr) * 64 + h * 16;   // float4 units
            Ks[i] = ((const float4*)K)[base4 + (i & 15)];
            Vs[i] = ((const float4*)V)[base4 + (i & 15)];
        }
        __syncthreads();

        int jmax = qi - key0 + 1;
        if (jmax > 32) jmax = 32;
        for (int j = 0; j < jmax; j++) {
            if (mrow[key0 + j] == 0) continue;
            const float4* kk = &Ks[j * 16];
            float s = 0.f;
            #pragma unroll
            for (int d4 = 0; d4 < 16; d4++) {
                float4 kv = kk[d4];
                s += q[4*d4+0]*kv.x + q[4*d4+1]*kv.y + q[4*d4+2]*kv.z + q[4*d4+3]*kv.w;
            }
            s *= 0.125f;                     // DH^-0.5
            float mn   = fmaxf(m, s);
            float corr = __expf(m - mn);
            float p    = __expf(s - mn);
            l = l * corr + p;
            const float4* vv = &Vs[j * 16];
            #pragma unroll
            for (int d4 = 0; d4 < 16; d4++) {
                float4 vx = vv[d4];
                acc[4*d4+0] = acc[4*d4+0]*corr + p*vx.x;
                acc[4*d4+1] = acc[4*d4+1]*corr + p*vx.y;
                acc[4*d4+2] = acc[4*d4+2]*corr + p*vx.z;
                acc[4*d4+3] = acc[4*d4+3]*corr + p*vx.w;
            }
            m = mn;
        }
    }

    float invl = 1.0f / l;
    float4* Op = (float4*)(O + ((size_t)(b * Lk + qi)) * Dk + h * DHk);
    #pragma unroll
    for (int d4 = 0; d4 < 16; d4++) {
        float4 o;
        o.x = acc[4*d4+0]*invl; o.y = acc[4*d4+1]*invl;
        o.z = acc[4*d4+2]*invl; o.w = acc[4*d4+3]*invl;
        Op[d4] = o;
    }
}

// ---------------- SGEMM: C[m,n] = sum_k A[m,k]*B[n,k]  (both row-major, "NT") ------
// 128x128 block tile, BK=8, 256 threads, 8x8 per thread.
// epi: 0 = store, 1 = C = R + AB (residual), 2 = C = silu(AB)
__global__ __launch_bounds__(256, 2) void gemm_nt(const float* __restrict__ A,
                                                  const float* __restrict__ B,
                                                  const float* __restrict__ R,
                                                  float* __restrict__ C,
                                                  int N, int K, int epi)
{
    __shared__ float As[8][132];
    __shared__ float Bs[8][132];

    int bm0 = blockIdx.y * 128;
    int bn0 = blockIdx.x * 128;
    int t   = threadIdx.x;
    int tx  = t & 15;        // 0..15 -> 8 cols each
    int ty  = t >> 4;        // 0..15 -> 8 rows each
    int lrow = t >> 1;       // 0..127
    int lk4  = (t & 1) * 4;  // 0 or 4

    const float* Ap = A + (size_t)(bm0 + lrow) * K + lk4;
    const float* Bp = B + (size_t)(bn0 + lrow) * K + lk4;

    float acc[8][8];
    #pragma unroll
    for (int i = 0; i < 8; i++)
        #pragma unroll
        for (int j = 0; j < 8; j++) acc[i][j] = 0.f;

    for (int k0 = 0; k0 < K; k0 += 8) {
        float4 av = *(const float4*)(Ap + k0);
        float4 bv = *(const float4*)(Bp + k0);
        __syncthreads();
        As[lk4+0][lrow] = av.x; As[lk4+1][lrow] = av.y;
        As[lk4+2][lrow] = av.z; As[lk4+3][lrow] = av.w;
        Bs[lk4+0][lrow] = bv.x; Bs[lk4+1][lrow] = bv.y;
        Bs[lk4+2][lrow] = bv.z; Bs[lk4+3][lrow] = bv.w;
        __syncthreads();
        #pragma unroll
        for (int kk = 0; kk < 8; kk++) {
            float4 a0 = *(const float4*)&As[kk][ty * 8];
            float4 a1 = *(const float4*)&As[kk][ty * 8 + 4];
            float4 b0 = *(const float4*)&Bs[kk][tx * 8];
            float4 b1 = *(const float4*)&Bs[kk][tx * 8 + 4];
            float ra[8] = {a0.x, a0.y, a0.z, a0.w, a1.x, a1.y, a1.z, a1.w};
            float rb[8] = {b0.x, b0.y, b0.z, b0.w, b1.x, b1.y, b1.z, b1.w};
            #pragma unroll
            for (int i = 0; i < 8; i++)
                #pragma unroll
                for (int j = 0; j < 8; j++)
                    acc[i][j] += ra[i] * rb[j];
        }
    }

    #pragma unroll
    for (int i = 0; i < 8; i++) {
        size_t base = (size_t)(bm0 + ty * 8 + i) * N + bn0 + tx * 8;
        #pragma unroll
        for (int j4 = 0; j4 < 2; j4++) {
            float4 v;
            v.x = acc[i][j4*4+0]; v.y = acc[i][j4*4+1];
            v.z = acc[i][j4*4+2]; v.w = acc[i][j4*4+3];
            if (epi == 1) {
                float4 r = *(const float4*)(R + base + j4 * 4);
                v.x += r.x; v.y += r.y; v.z += r.z; v.w += r.w;
            } else if (epi == 2) {
                v.x = v.x / (1.f + __expf(-v.x));
                v.y = v.y / (1.f + __expf(-v.y));
                v.z = v.z / (1.f + __expf(-v.z));
                v.w = v.w / (1.f + __expf(-v.w));
            }
            *(float4*)(C + base + j4 * 4) = v;
        }
    }
}

// ---------------- classifier heads: cls = XN[b, 0, :] ----------------
__global__ void heads_kernel(const float* __restrict__ XN,
                             const float* __restrict__ rw, const float* __restrict__ rb,
                             const float* __restrict__ mw, const float* __restrict__ mb,
                             float* __restrict__ out)
{
    int w = threadIdx.x >> 5, lane = threadIdx.x & 31;
    if (w >= Bk) return;
    const float* x = XN + (size_t)w * Lk * Dk;
    float sr = 0.f, sm = 0.f;
    for (int d = lane; d < Dk; d += 32) {
        float xv = x[d];
        sr += xv * rw[d];
        sm += xv * mw[d];
    }
    #pragma unroll
    for (int o = 16; o > 0; o >>= 1) {
        sr += __shfl_down_sync(0xffffffffu, sr, o);
        sm += __shfl_down_sync(0xffffffffu, sm, o);
    }
    if (lane == 0) {
        out[w]      = sr + rb[0];
        out[Bk + w] = sm + mb[0];
    }
}

// ---------------- launch ----------------
extern "C" void kernel_launch(void* const* d_in, const int* in_sizes, int n_in,
                              void* d_out, int out_size)
{
    const int*   ids      = (const int*)d_in[0];
    const int*   tts      = (const int*)d_in[1];
    const int*   mask     = (const int*)d_in[2];
    const float* tok_emb  = (const float*)d_in[3];
    const float* type_emb = (const float*)d_in[4];
    const float* norm1    = (const float*)d_in[5];
    const float* wq       = (const float*)d_in[6];
    const float* wk       = (const float*)d_in[7];
    const float* wv       = (const float*)d_in[8];
    const float* wo       = (const float*)d_in[9];
    const float* norm2    = (const float*)d_in[10];
    const float* fw1      = (const float*)d_in[11];
    const float* fw2      = (const float*)d_in[12];
    const float* fnorm    = (const float*)d_in[13];
    const float* lmw      = (const float*)d_in[14];
    const float* rw       = (const float*)d_in[15];
    const float* rbias    = (const float*)d_in[16];
    const float* mw       = (const float*)d_in[17];
    const float* mbias    = (const float*)d_in[18];
    float* out = (float*)d_out;

    float *X, *XN, *Q, *K, *V, *AO, *F1;
    cudaGetSymbolAddress((void**)&X,  g_X);
    cudaGetSymbolAddress((void**)&XN, g_XN);
    cudaGetSymbolAddress((void**)&Q,  g_Q);
    cudaGetSymbolAddress((void**)&K,  g_K);
    cudaGetSymbolAddress((void**)&V,  g_V);
    cudaGetSymbolAddress((void**)&AO, g_AO);
    cudaGetSymbolAddress((void**)&F1, g_F1);

    embed_kernel<<<(MR * Dk) / 256, 256>>>(ids, tts, tok_emb, type_emb, X);

    dim3 gs (Dk  / 128, MR / 128);   // N=256   -> (2, 64)
    dim3 gf1(FFD / 128, MR / 128);   // N=1024  -> (8, 64)
    dim3 glm(Vk  / 128, MR / 128);   // N=32000 -> (250, 64)
    dim3 ga (Lk / 128, Hk, Bk);

    for (int i = 0; i < NLk; i++) {
        rmsnorm_kernel<<<MR, 256>>>(X, norm1 + (size_t)i * Dk, XN);
        gemm_nt<<<gs, 256>>>(XN, wq + (size_t)i * Dk * Dk, nullptr, Q, Dk, Dk, 0);
        gemm_nt<<<gs, 256>>>(XN, wk + (size_t)i * Dk * Dk, nullptr, K, Dk, Dk, 0);
        gemm_nt<<<gs, 256>>>(XN, wv + (size_t)i * Dk * Dk, nullptr, V, Dk, Dk, 0);
        rope_kernel<<<(MR * Hk * 32) / 256, 256>>>(Q);
        rope_kernel<<<(MR * Hk * 32) / 256, 256>>>(K);
        attn_kernel<<<ga, 128>>>(Q, K, V, mask, AO);
        gemm_nt<<<gs, 256>>>(AO, wo + (size_t)i * Dk * Dk, X, X, Dk, Dk, 1);
        rmsnorm_kernel<<<MR, 256>>>(X, norm2 + (size_t)i * Dk, XN);
        gemm_nt<<<gf1, 256>>>(XN, fw1 + (size_t)i * FFD * Dk, nullptr, F1, FFD, Dk, 2);
        gemm_nt<<<gs, 256>>>(F1, fw2 + (size_t)i * Dk * FFD, X, X, Dk, FFD, 1);
    }

    rmsnorm_kernel<<<MR, 256>>>(X, fnorm, XN);
    gemm_nt<<<glm, 256>>>(XN, lmw, nullptr, out, Vk, Dk, 0);
    heads_kernel<<<1, 128>>>(XN, rw, rbias, mw, mbias, out + (size_t)Bk * Lk * Vk);
}

// round 2
// speedup vs baseline: 1.2978x; 1.2978x over previous
#include <cuda_runtime.h>
#include <math.h>
#include <stdint.h>

// Problem constants
#define Bk   4
#define Lk   2048
#define Dk   256
#define Hk   4
#define NLk  4
#define Vk   32000
#define DHk  64
#define MR   (Bk*Lk)      // 8192 rows
#define FFD  (4*Dk)       // 1024

// ---------------- scratch (static __device__, no allocation) ----------------
__device__ float g_X [MR*Dk];
__device__ float g_XN[MR*Dk];
__device__ float g_Q [MR*Dk];
__device__ float g_K [MR*Dk];
__device__ float g_V [MR*Dk];
__device__ float g_AO[MR*Dk];
__device__ float g_F1[MR*FFD];

// ---------------- helpers ----------------
__device__ __forceinline__ uint32_t cvt_tf32(float x) {
    uint32_t r;
    asm("cvt.rna.tf32.f32 %0, %1;" : "=r"(r) : "f"(x));
    return r;
}

__device__ __forceinline__ void mma_tf32(float& c0, float& c1, float& c2, float& c3,
                                         uint32_t a0, uint32_t a1, uint32_t a2, uint32_t a3,
                                         uint32_t b0, uint32_t b1)
{
    asm volatile("mma.sync.aligned.m16n8k8.row.col.f32.tf32.tf32.f32 "
                 "{%0,%1,%2,%3},{%4,%5,%6,%7},{%8,%9},{%0,%1,%2,%3};"
                 : "+f"(c0), "+f"(c1), "+f"(c2), "+f"(c3)
                 : "r"(a0), "r"(a1), "r"(a2), "r"(a3), "r"(b0), "r"(b1));
}

// ---------------- embedding ----------------
__global__ void embed_kernel(const int* __restrict__ ids, const int* __restrict__ tts,
                             const float* __restrict__ te, const float* __restrict__ ye,
                             float* __restrict__ X)
{
    int i = blockIdx.x * 256 + threadIdx.x;
    int row = i >> 8;
    int d   = i & 255;
    X[i] = te[(size_t)ids[row] * Dk + d] + ye[(size_t)tts[row] * Dk + d];
}

// ---------------- RMSNorm ----------------
__global__ __launch_bounds__(256) void rmsnorm_kernel(const float* __restrict__ X,
                                                      const float* __restrict__ w,
                                                      float* __restrict__ Y)
{
    int r = blockIdx.x;
    int t = threadIdx.x;
    float v = X[(size_t)r * Dk + t];
    float s = v * v;
    #pragma unroll
    for (int o = 16; o > 0; o >>= 1) s += __shfl_down_sync(0xffffffffu, s, o);
    __shared__ float ws[8];
    __shared__ float tot;
    int lane = t & 31, wi = t >> 5;
    if (lane == 0) ws[wi] = s;
    __syncthreads();
    if (t == 0) {
        float a = 0.f;
        #pragma unroll
        for (int i = 0; i < 8; i++) a += ws[i];
        tot = a;
    }
    __syncthreads();
    float rs = rsqrtf(tot * (1.0f / Dk) + 1.1920929e-07f);
    Y[(size_t)r * Dk + t] = v * rs * w[t];
}

// ---------------- RoPE ----------------
__global__ void rope_kernel(float* __restrict__ P)
{
    int i   = blockIdx.x * 256 + threadIdx.x;
    int t   = i & 31;
    int h   = (i >> 5) & 3;
    int row = i >> 7;
    int pos = row & (Lk - 1);
    float inv = exp2f(-(float)t * (13.287712379549449f / 32.0f));
    float ang = (float)pos * inv;
    float sn, cs;
    sincosf(ang, &sn, &cs);
    size_t base = (size_t)row * Dk + h * DHk;
    float a = P[base + t];
    float b = P[base + t + 32];
    P[base + t]      = a * cs - b * sn;
    P[base + t + 32] = b * cs + a * sn;
}

// ---------------- causal flash attention (fp32) ----------------
__global__ __launch_bounds__(128) void attn_kernel(const float* __restrict__ Q,
                                                   const float* __restrict__ K,
                                                   const float* __restrict__ V,
                                                   const int*   __restrict__ mask,
                                                   float* __restrict__ O)
{
    int b  = blockIdx.z;
    int h  = blockIdx.y;
    int qi = blockIdx.x * 128 + threadIdx.x;

    float q[64], acc[64];
    {
        const float4* Qp = (const float4*)(Q + ((size_t)(b * Lk + qi)) * Dk + h * DHk);
        #pragma unroll
        for (int d4 = 0; d4 < 16; d4++) {
            float4 tq = Qp[d4];
            q[4*d4+0] = tq.x; q[4*d4+1] = tq.y; q[4*d4+2] = tq.z; q[4*d4+3] = tq.w;
        }
    }
    #pragma unroll
    for (int d = 0; d < 64; d++) acc[d] = 0.f;
    float m = -1e30f, l = 0.f;

    __shared__ float4 Ks[512];
    __shared__ float4 Vs[512];

    int nkt = 4 * (blockIdx.x + 1);
    const int* mrow = mask + (size_t)b * Lk;

    for (int kt = 0; kt < nkt; kt++) {
        int key0 = kt * 32;
        __syncthreads();
        for (int i = threadIdx.x; i < 512; i += 128) {
            int kr = key0 + (i >> 4);
            size_t base4 = (size_t)(b * Lk + kr) * 64 + h * 16;
            Ks[i] = ((const float4*)K)[base4 + (i & 15)];
            Vs[i] = ((const float4*)V)[base4 + (i & 15)];
        }
        __syncthreads();

        int jmax = qi - key0 + 1;
        if (jmax > 32) jmax = 32;
        for (int j = 0; j < jmax; j++) {
            if (mrow[key0 + j] == 0) continue;
            const float4* kk = &Ks[j * 16];
            float s = 0.f;
            #pragma unroll
            for (int d4 = 0; d4 < 16; d4++) {
                float4 kv = kk[d4];
                s += q[4*d4+0]*kv.x + q[4*d4+1]*kv.y + q[4*d4+2]*kv.z + q[4*d4+3]*kv.w;
            }
            s *= 0.125f;
            float mn   = fmaxf(m, s);
            float corr = __expf(m - mn);
            float p    = __expf(s - mn);
            l = l * corr + p;
            const float4* vv = &Vs[j * 16];
            #pragma unroll
            for (int d4 = 0; d4 < 16; d4++) {
                float4 vx = vv[d4];
                acc[4*d4+0] = acc[4*d4+0]*corr + p*vx.x;
                acc[4*d4+1] = acc[4*d4+1]*corr + p*vx.y;
                acc[4*d4+2] = acc[4*d4+2]*corr + p*vx.z;
                acc[4*d4+3] = acc[4*d4+3]*corr + p*vx.w;
            }
            m = mn;
        }
    }

    float invl = 1.0f / l;
    float4* Op = (float4*)(O + ((size_t)(b * Lk + qi)) * Dk + h * DHk);
    #pragma unroll
    for (int d4 = 0; d4 < 16; d4++) {
        float4 o;
        o.x = acc[4*d4+0]*invl; o.y = acc[4*d4+1]*invl;
        o.z = acc[4*d4+2]*invl; o.w = acc[4*d4+3]*invl;
        Op[d4] = o;
    }
}

// ================= tf32 tensor-core GEMM =================
// C[m,n] = sum_k A[m,k] * B[n,k]  (both row-major, NT)
// Block tile 128x128, BK=16, 256 threads = 8 warps (4 along M x 2 along N),
// warp tile 32x64 -> 2 m16 tiles x 8 n8 tiles of mma.m16n8k8.tf32.
// SPLIT=true: 3-pass tf32 split (hi/lo) for ~fp32 accuracy.
// EPI: 0 = store, 1 = C = R + AB, 2 = C = silu(AB)
template<bool SPLIT, int EPI>
__global__ __launch_bounds__(256) void gemm_tf32(const float* __restrict__ A,
                                                 const float* __restrict__ B,
                                                 const float* __restrict__ R,
                                                 float* __restrict__ C,
                                                 int N, int K)
{
    __shared__ uint32_t Ah[128][20];
    __shared__ uint32_t Bh[128][20];
    __shared__ uint32_t Al[SPLIT ? 128 : 1][20];
    __shared__ uint32_t Bl[SPLIT ? 128 : 1][20];

    int t    = threadIdx.x;
    int lane = t & 31;
    int wid  = t >> 5;
    int bm0  = blockIdx.y * 128;
    int bn0  = blockIdx.x * 128;
    int wm0  = (wid & 3) * 32;
    int wn0  = (wid >> 2) * 64;

    int lrow = t >> 1;          // 0..127
    int lk   = (t & 1) * 8;     // 0 or 8

    const float* Ap = A + (size_t)(bm0 + lrow) * K + lk;
    const float* Bp = B + (size_t)(bn0 + lrow) * K + lk;

    float c[2][8][4];
    #pragma unroll
    for (int i = 0; i < 2; i++)
        #pragma unroll
        for (int j = 0; j < 8; j++)
            #pragma unroll
            for (int q = 0; q < 4; q++) c[i][j][q] = 0.f;

    // prefetch first tile
    float4 ra0 = *(const float4*)(Ap);
    float4 ra1 = *(const float4*)(Ap + 4);
    float4 rb0 = *(const float4*)(Bp);
    float4 rb1 = *(const float4*)(Bp + 4);

    int gr = lane >> 2;   // 0..7
    int gc = lane & 3;    // 0..3

    for (int k0 = 0; k0 < K; k0 += 16) {
        __syncthreads();
        // convert + store staged tile to smem
        {
            uint4 h0 = { cvt_tf32(ra0.x), cvt_tf32(ra0.y), cvt_tf32(ra0.z), cvt_tf32(ra0.w) };
            uint4 h1 = { cvt_tf32(ra1.x), cvt_tf32(ra1.y), cvt_tf32(ra1.z), cvt_tf32(ra1.w) };
            *(uint4*)&Ah[lrow][lk]     = h0;
            *(uint4*)&Ah[lrow][lk + 4] = h1;
            if (SPLIT) {
                uint4 l0 = { cvt_tf32(ra0.x - __uint_as_float(h0.x)),
                             cvt_tf32(ra0.y - __uint_as_float(h0.y)),
                             cvt_tf32(ra0.z - __uint_as_float(h0.z)),
                             cvt_tf32(ra0.w - __uint_as_float(h0.w)) };
                uint4 l1 = { cvt_tf32(ra1.x - __uint_as_float(h1.x)),
                             cvt_tf32(ra1.y - __uint_as_float(h1.y)),
                             cvt_tf32(ra1.z - __uint_as_float(h1.z)),
                             cvt_tf32(ra1.w - __uint_as_float(h1.w)) };
                *(uint4*)&Al[lrow][lk]     = l0;
                *(uint4*)&Al[lrow][lk + 4] = l1;
            }
            uint4 g0 = { cvt_tf32(rb0.x), cvt_tf32(rb0.y), cvt_tf32(rb0.z), cvt_tf32(rb0.w) };
            uint4 g1 = { cvt_tf32(rb1.x), cvt_tf32(rb1.y), cvt_tf32(rb1.z), cvt_tf32(rb1.w) };
            *(uint4*)&Bh[lrow][lk]     = g0;
            *(uint4*)&Bh[lrow][lk + 4] = g1;
            if (SPLIT) {
                uint4 l0 = { cvt_tf32(rb0.x - __uint_as_float(g0.x)),
                             cvt_tf32(rb0.y - __uint_as_float(g0.y)),
                             cvt_tf32(rb0.z - __uint_as_float(g0.z)),
                             cvt_tf32(rb0.w - __uint_as_float(g0.w)) };
                uint4 l1 = { cvt_tf32(rb1.x - __uint_as_float(g1.x)),
                             cvt_tf32(rb1.y - __uint_as_float(g1.y)),
                             cvt_tf32(rb1.z - __uint_as_float(g1.z)),
                             cvt_tf32(rb1.w - __uint_as_float(g1.w)) };
                *(uint4*)&Bl[lrow][lk]     = l0;
                *(uint4*)&Bl[lrow][lk + 4] = l1;
            }
        }
        __syncthreads();

        // prefetch next tile (hidden under mma work)
        if (k0 + 16 < K) {
            ra0 = *(const float4*)(Ap + k0 + 16);
            ra1 = *(const float4*)(Ap + k0 + 20);
            rb0 = *(const float4*)(Bp + k0 + 16);
            rb1 = *(const float4*)(Bp + k0 + 20);
        }

        #pragma unroll
        for (int kk = 0; kk < 16; kk += 8) {
            uint32_t afh[2][4], bfh[8][2];
            uint32_t afl[2][4], bfl[8][2];
            #pragma unroll
            for (int mt = 0; mt < 2; mt++) {
                int r0 = wm0 + mt * 16 + gr;
                afh[mt][0] = Ah[r0][kk + gc];
                afh[mt][1] = Ah[r0 + 8][kk + gc];
                afh[mt][2] = Ah[r0][kk + 4 + gc];
                afh[mt][3] = Ah[r0 + 8][kk + 4 + gc];
                if (SPLIT) {
                    afl[mt][0] = Al[r0][kk + gc];
                    afl[mt][1] = Al[r0 + 8][kk + gc];
                    afl[mt][2] = Al[r0][kk + 4 + gc];
                    afl[mt][3] = Al[r0 + 8][kk + 4 + gc];
                }
            }
            #pragma unroll
            for (int nt = 0; nt < 8; nt++) {
                int n0 = wn0 + nt * 8 + gr;
                bfh[nt][0] = Bh[n0][kk + gc];
                bfh[nt][1] = Bh[n0][kk + 4 + gc];
                if (SPLIT) {
                    bfl[nt][0] = Bl[n0][kk + gc];
                    bfl[nt][1] = Bl[n0][kk + 4 + gc];
                }
            }
            #pragma unroll
            for (int mt = 0; mt < 2; mt++)
                #pragma unroll
                for (int nt = 0; nt < 8; nt++) {
                    mma_tf32(c[mt][nt][0], c[mt][nt][1], c[mt][nt][2], c[mt][nt][3],
                             afh[mt][0], afh[mt][1], afh[mt][2], afh[mt][3],
                             bfh[nt][0], bfh[nt][1]);
                    if (SPLIT) {
                        mma_tf32(c[mt][nt][0], c[mt][nt][1], c[mt][nt][2], c[mt][nt][3],
                                 afh[mt][0], afh[mt][1], afh[mt][2], afh[mt][3],
                                 bfl[nt][0], bfl[nt][1]);
                        mma_tf32(c[mt][nt][0], c[mt][nt][1], c[mt][nt][2], c[mt][nt][3],
                                 afl[mt][0], afl[mt][1], afl[mt][2], afl[mt][3],
                                 bfh[nt][0], bfh[nt][1]);
                    }
                }
        }
    }

    // epilogue: c0,c1 at (row, col..col+1); c2,c3 at (row+8, col..col+1)
    #pragma unroll
    for (int mt = 0; mt < 2; mt++) {
        #pragma unroll
        for (int nt = 0; nt < 8; nt++) {
            int row = bm0 + wm0 + mt * 16 + gr;
            int col = bn0 + wn0 + nt * 8 + gc * 2;
            #pragma unroll
            for (int half = 0; half < 2; half++) {
                int r = row + half * 8;
                float vx = c[mt][nt][half * 2 + 0];
                float vy = c[mt][nt][half * 2 + 1];
                size_t idx = (size_t)r * N + col;
                if (EPI == 1) {
                    float2 rr = *(const float2*)(R + idx);
                    vx += rr.x; vy += rr.y;
                } else if (EPI == 2) {
                    vx = vx / (1.f + __expf(-vx));
                    vy = vy / (1.f + __expf(-vy));
                }
                float2 o; o.x = vx; o.y = vy;
                *(float2*)(C + idx) = o;
            }
        }
    }
}

// ---------------- classifier heads ----------------
__global__ void heads_kernel(const float* __restrict__ XN,
                             const float* __restrict__ rw, const float* __restrict__ rb,
                             const float* __restrict__ mw, const float* __restrict__ mb,
                             float* __restrict__ out)
{
    int w = threadIdx.x >> 5, lane = threadIdx.x & 31;
    if (w >= Bk) return;
    const float* x = XN + (size_t)w * Lk * Dk;
    float sr = 0.f, sm = 0.f;
    for (int d = lane; d < Dk; d += 32) {
        float xv = x[d];
        sr += xv * rw[d];
        sm += xv * mw[d];
    }
    #pragma unroll
    for (int o = 16; o > 0; o >>= 1) {
        sr += __shfl_down_sync(0xffffffffu, sr, o);
        sm += __shfl_down_sync(0xffffffffu, sm, o);
    }
    if (lane == 0) {
        out[w]      = sr + rb[0];
        out[Bk + w] = sm + mb[0];
    }
}

// ---------------- launch ----------------
extern "C" void kernel_launch(void* const* d_in, const int* in_sizes, int n_in,
                              void* d_out, int out_size)
{
    const int*   ids      = (const int*)d_in[0];
    const int*   tts      = (const int*)d_in[1];
    const int*   mask     = (const int*)d_in[2];
    const float* tok_emb  = (const float*)d_in[3];
    const float* type_emb = (const float*)d_in[4];
    const float* norm1    = (const float*)d_in[5];
    const float* wq       = (const float*)d_in[6];
    const float* wk       = (const float*)d_in[7];
    const float* wv       = (const float*)d_in[8];
    const float* wo       = (const float*)d_in[9];
    const float* norm2    = (const float*)d_in[10];
    const float* fw1      = (const float*)d_in[11];
    const float* fw2      = (const float*)d_in[12];
    const float* fnorm    = (const float*)d_in[13];
    const float* lmw      = (const float*)d_in[14];
    const float* rw       = (const float*)d_in[15];
    const float* rbias    = (const float*)d_in[16];
    const float* mw       = (const float*)d_in[17];
    const float* mbias    = (const float*)d_in[18];
    float* out = (float*)d_out;

    float *X, *XN, *Q, *K, *V, *AO, *F1;
    cudaGetSymbolAddress((void**)&X,  g_X);
    cudaGetSymbolAddress((void**)&XN, g_XN);
    cudaGetSymbolAddress((void**)&Q,  g_Q);
    cudaGetSymbolAddress((void**)&K,  g_K);
    cudaGetSymbolAddress((void**)&V,  g_V);
    cudaGetSymbolAddress((void**)&AO, g_AO);
    cudaGetSymbolAddress((void**)&F1, g_F1);

    embed_kernel<<<(MR * Dk) / 256, 256>>>(ids, tts, tok_emb, type_emb, X);

    dim3 gs (Dk  / 128, MR / 128);   // (2, 64)
    dim3 gf1(FFD / 128, MR / 128);   // (8, 64)
    dim3 glm(Vk  / 128, MR / 128);   // (250, 64)
    dim3 ga (Lk / 128, Hk, Bk);

    for (int i = 0; i < NLk; i++) {
        rmsnorm_kernel<<<MR, 256>>>(X, norm1 + (size_t)i * Dk, XN);
        gemm_tf32<true, 0><<<gs, 256>>>(XN, wq + (size_t)i * Dk * Dk, nullptr, Q, Dk, Dk);
        gemm_tf32<true, 0><<<gs, 256>>>(XN, wk + (size_t)i * Dk * Dk, nullptr, K, Dk, Dk);
        gemm_tf32<true, 0><<<gs, 256>>>(XN, wv + (size_t)i * Dk * Dk, nullptr, V, Dk, Dk);
        rope_kernel<<<(MR * Hk * 32) / 256, 256>>>(Q);
        rope_kernel<<<(MR * Hk * 32) / 256, 256>>>(K);
        attn_kernel<<<ga, 128>>>(Q, K, V, mask, AO);
        gemm_tf32<true, 1><<<gs, 256>>>(AO, wo + (size_t)i * Dk * Dk, X, X, Dk, Dk);
        rmsnorm_kernel<<<MR, 256>>>(X, norm2 + (size_t)i * Dk, XN);
        gemm_tf32<true, 2><<<gf1, 256>>>(XN, fw1 + (size_t)i * FFD * Dk, nullptr, F1, FFD, Dk);
        gemm_tf32<true, 1><<<gs, 256>>>(F1, fw2 + (size_t)i * Dk * FFD, X, X, Dk, FFD);
    }

    rmsnorm_kernel<<<MR, 256>>>(X, fnorm, XN);
    gemm_tf32<false, 0><<<glm, 256>>>(XN, lmw, nullptr, out, Vk, Dk);
    heads_kernel<<<1, 128>>>(XN, rw, rbias, mw, mbias, out + (size_t)Bk * Lk * Vk);
}

// round 3
// speedup vs baseline: 2.4488x; 1.8868x over previous
#include <cuda_runtime.h>
#include <math.h>
#include <stdint.h>

// Problem constants
#define Bk   4
#define Lk   2048
#define Dk   256
#define Hk   4
#define NLk  4
#define Vk   32000
#define DHk  64
#define MR   (Bk*Lk)      // 8192 rows
#define FFD  (4*Dk)       // 1024

// ---------------- scratch ----------------
__device__ float g_X [MR*Dk];
__device__ float g_XN[MR*Dk];
__device__ float g_Q [MR*Dk];
__device__ float g_K [MR*Dk];
__device__ float g_V [MR*Dk];
__device__ float g_AO[MR*Dk];
__device__ float g_F1[MR*FFD];

// ---------------- helpers ----------------
__device__ __forceinline__ uint32_t cvt_tf32(float x) {
    uint32_t r;
    asm("cvt.rna.tf32.f32 %0, %1;" : "=r"(r) : "f"(x));
    return r;
}

__device__ __forceinline__ void mma_tf32(float& c0, float& c1, float& c2, float& c3,
                                         uint32_t a0, uint32_t a1, uint32_t a2, uint32_t a3,
                                         uint32_t b0, uint32_t b1)
{
    asm volatile("mma.sync.aligned.m16n8k8.row.col.f32.tf32.tf32.f32 "
                 "{%0,%1,%2,%3},{%4,%5,%6,%7},{%8,%9},{%0,%1,%2,%3};"
                 : "+f"(c0), "+f"(c1), "+f"(c2), "+f"(c3)
                 : "r"(a0), "r"(a1), "r"(a2), "r"(a3), "r"(b0), "r"(b1));
}

// ---------------- embedding ----------------
__global__ void embed_kernel(const int* __restrict__ ids, const int* __restrict__ tts,
                             const float* __restrict__ te, const float* __restrict__ ye,
                             float* __restrict__ X)
{
    int i = blockIdx.x * 256 + threadIdx.x;
    int row = i >> 8;
    int d   = i & 255;
    X[i] = te[(size_t)ids[row] * Dk + d] + ye[(size_t)tts[row] * Dk + d];
}

// ---------------- RMSNorm ----------------
__global__ __launch_bounds__(256) void rmsnorm_kernel(const float* __restrict__ X,
                                                      const float* __restrict__ w,
                                                      float* __restrict__ Y)
{
    int r = blockIdx.x;
    int t = threadIdx.x;
    float v = X[(size_t)r * Dk + t];
    float s = v * v;
    #pragma unroll
    for (int o = 16; o > 0; o >>= 1) s += __shfl_down_sync(0xffffffffu, s, o);
    __shared__ float ws[8];
    __shared__ float tot;
    int lane = t & 31, wi = t >> 5;
    if (lane == 0) ws[wi] = s;
    __syncthreads();
    if (t == 0) {
        float a = 0.f;
        #pragma unroll
        for (int i = 0; i < 8; i++) a += ws[i];
        tot = a;
    }
    __syncthreads();
    float rs = rsqrtf(tot * (1.0f / Dk) + 1.1920929e-07f);
    Y[(size_t)r * Dk + t] = v * rs * w[t];
}

// ---------------- RoPE (Q and K in one launch via blockIdx.y) ----------------
__global__ void rope2_kernel(float* __restrict__ Q, float* __restrict__ K)
{
    float* P = blockIdx.y ? K : Q;
    int i   = blockIdx.x * 256 + threadIdx.x;
    int t   = i & 31;
    int h   = (i >> 5) & 3;
    int row = i >> 7;
    int pos = row & (Lk - 1);
    float inv = exp2f(-(float)t * (13.287712379549449f / 32.0f));
    float ang = (float)pos * inv;
    float sn, cs;
    sincosf(ang, &sn, &cs);
    size_t base = (size_t)row * Dk + h * DHk;
    float a = P[base + t];
    float b = P[base + t + 32];
    P[base + t]      = a * cs - b * sn;
    P[base + t + 32] = b * cs + a * sn;
}

// ---------------- tensor-core flash attention ----------------
// 64 queries/block (4 warps x 16 rows), 64-key tiles, DH=64, tf32 mma.
#define APAD 68
__global__ __launch_bounds__(128) void attn_fa(const float* __restrict__ Q,
                                               const float* __restrict__ K,
                                               const float* __restrict__ V,
                                               const int*   __restrict__ mask,
                                               float* __restrict__ O)
{
    __shared__ uint32_t KP[64][APAD];   // K tile, later aliased as P
    __shared__ uint32_t Vs[64][APAD];   // V transposed: Vs[d][key]
    __shared__ float    mkf[64];

    int b  = blockIdx.z, h = blockIdx.y;
    int q0 = blockIdx.x * 64;
    int tid = threadIdx.x;
    int lane = tid & 31, wid = tid >> 5;
    int gr = lane >> 2, gc = lane & 3;
    int wr = wid * 16;

    const int* mrow = mask + (size_t)b * Lk;

    // stage Q tile (scaled by DH^-0.5, tf32) into KP, then read frags
    #pragma unroll
    for (int it = 0; it < 8; it++) {
        int pos = tid + it * 128;
        int row = pos >> 4, d4 = pos & 15;
        float4 qv = *(const float4*)(Q + ((size_t)(b*Lk + q0 + row))*Dk + h*DHk + d4*4);
        uint4 u = { cvt_tf32(qv.x*0.125f), cvt_tf32(qv.y*0.125f),
                    cvt_tf32(qv.z*0.125f), cvt_tf32(qv.w*0.125f) };
        *(uint4*)&KP[row][d4*4] = u;
    }
    __syncthreads();
    uint32_t qa[8][4];
    #pragma unroll
    for (int kk = 0; kk < 8; kk++) {
        qa[kk][0] = KP[wr+gr  ][kk*8+gc];
        qa[kk][1] = KP[wr+gr+8][kk*8+gc];
        qa[kk][2] = KP[wr+gr  ][kk*8+gc+4];
        qa[kk][3] = KP[wr+gr+8][kk*8+gc+4];
    }

    float o[8][4];
    #pragma unroll
    for (int nt = 0; nt < 8; nt++)
        #pragma unroll
        for (int j = 0; j < 4; j++) o[nt][j] = 0.f;
    float m0 = -1e30f, m1 = -1e30f, l0 = 0.f, l1 = 0.f;
    int r0 = q0 + wr + gr, r1 = r0 + 8;

    int ntile = blockIdx.x + 1;
    for (int kt = 0; kt < ntile; kt++) {
        int key0 = kt * 64;
        __syncthreads();   // previous iteration's PV reads done
        #pragma unroll
        for (int it = 0; it < 8; it++) {
            int pos = tid + it * 128;
            int key = pos >> 4, d4 = pos & 15;
            size_t gbase = ((size_t)(b*Lk + key0 + key))*Dk + h*DHk + d4*4;
            float4 kv = *(const float4*)(K + gbase);
            uint4 u = { cvt_tf32(kv.x), cvt_tf32(kv.y), cvt_tf32(kv.z), cvt_tf32(kv.w) };
            *(uint4*)&KP[key][d4*4] = u;
            float4 vv = *(const float4*)(V + gbase);
            Vs[d4*4+0][key] = cvt_tf32(vv.x);
            Vs[d4*4+1][key] = cvt_tf32(vv.y);
            Vs[d4*4+2][key] = cvt_tf32(vv.z);
            Vs[d4*4+3][key] = cvt_tf32(vv.w);
        }
        if (tid < 64) mkf[tid] = mrow[key0 + tid] ? 0.0f : -1e30f;
        __syncthreads();

        // S = Q K^T
        float s[8][4];
        #pragma unroll
        for (int nt = 0; nt < 8; nt++)
            #pragma unroll
            for (int j = 0; j < 4; j++) s[nt][j] = 0.f;
        #pragma unroll
        for (int kk = 0; kk < 8; kk++) {
            #pragma unroll
            for (int nt = 0; nt < 8; nt++) {
                uint32_t b0 = KP[nt*8+gr][kk*8+gc];
                uint32_t b1 = KP[nt*8+gr][kk*8+gc+4];
                mma_tf32(s[nt][0], s[nt][1], s[nt][2], s[nt][3],
                         qa[kk][0], qa[kk][1], qa[kk][2], qa[kk][3], b0, b1);
            }
        }

        // masks
        bool last = (kt == ntile - 1);
        #pragma unroll
        for (int nt = 0; nt < 8; nt++) {
            float mk0 = mkf[nt*8+gc*2], mk1 = mkf[nt*8+gc*2+1];
            s[nt][0] += mk0; s[nt][1] += mk1;
            s[nt][2] += mk0; s[nt][3] += mk1;
            if (last) {
                int c = key0 + nt*8 + gc*2;
                if (c     > r0) s[nt][0] = -1e30f;
                if (c + 1 > r0) s[nt][1] = -1e30f;
                if (c     > r1) s[nt][2] = -1e30f;
                if (c + 1 > r1) s[nt][3] = -1e30f;
            }
        }

        // row max (over 64 cols: nt-local then quad shfl)
        float rm0 = -1e30f, rm1 = -1e30f;
        #pragma unroll
        for (int nt = 0; nt < 8; nt++) {
            rm0 = fmaxf(rm0, fmaxf(s[nt][0], s[nt][1]));
            rm1 = fmaxf(rm1, fmaxf(s[nt][2], s[nt][3]));
        }
        rm0 = fmaxf(rm0, __shfl_xor_sync(0xffffffffu, rm0, 1));
        rm0 = fmaxf(rm0, __shfl_xor_sync(0xffffffffu, rm0, 2));
        rm1 = fmaxf(rm1, __shfl_xor_sync(0xffffffffu, rm1, 1));
        rm1 = fmaxf(rm1, __shfl_xor_sync(0xffffffffu, rm1, 2));

        float mn0 = fmaxf(m0, rm0), mn1 = fmaxf(m1, rm1);
        float cor0 = __expf(m0 - mn0), cor1 = __expf(m1 - mn1);
        m0 = mn0; m1 = mn1;

        __syncthreads();   // everyone done reading K before P overwrites KP

        float ps0 = 0.f, ps1 = 0.f;
        #pragma unroll
        for (int nt = 0; nt < 8; nt++) {
            float p00 = __expf(s[nt][0] - mn0);
            float p01 = __expf(s[nt][1] - mn0);
            float p10 = __expf(s[nt][2] - mn1);
            float p11 = __expf(s[nt][3] - mn1);
            ps0 += p00 + p01;
            ps1 += p10 + p11;
            KP[wr+gr  ][nt*8+gc*2  ] = cvt_tf32(p00);
            KP[wr+gr  ][nt*8+gc*2+1] = cvt_tf32(p01);
            KP[wr+gr+8][nt*8+gc*2  ] = cvt_tf32(p10);
            KP[wr+gr+8][nt*8+gc*2+1] = cvt_tf32(p11);
        }
        ps0 += __shfl_xor_sync(0xffffffffu, ps0, 1);
        ps0 += __shfl_xor_sync(0xffffffffu, ps0, 2);
        ps1 += __shfl_xor_sync(0xffffffffu, ps1, 1);
        ps1 += __shfl_xor_sync(0xffffffffu, ps1, 2);
        l0 = l0 * cor0 + ps0;
        l1 = l1 * cor1 + ps1;
        #pragma unroll
        for (int nt = 0; nt < 8; nt++) {
            o[nt][0] *= cor0; o[nt][1] *= cor0;
            o[nt][2] *= cor1; o[nt][3] *= cor1;
        }
        __syncwarp();      // P rows are read cross-lane within this warp only

        // O += P V
        #pragma unroll
        for (int kk = 0; kk < 8; kk++) {
            uint32_t pa0 = KP[wr+gr  ][kk*8+gc];
            uint32_t pa1 = KP[wr+gr+8][kk*8+gc];
            uint32_t pa2 = KP[wr+gr  ][kk*8+gc+4];
            uint32_t pa3 = KP[wr+gr+8][kk*8+gc+4];
            #pragma unroll
            for (int nt = 0; nt < 8; nt++) {
                uint32_t vb0 = Vs[nt*8+gr][kk*8+gc];
                uint32_t vb1 = Vs[nt*8+gr][kk*8+gc+4];
                mma_tf32(o[nt][0], o[nt][1], o[nt][2], o[nt][3],
                         pa0, pa1, pa2, pa3, vb0, vb1);
            }
        }
    }

    float inv0 = 1.0f / l0, inv1 = 1.0f / l1;
    #pragma unroll
    for (int nt = 0; nt < 8; nt++) {
        int d = nt*8 + gc*2;
        float2 a; a.x = o[nt][0]*inv0; a.y = o[nt][1]*inv0;
        float2 c; c.x = o[nt][2]*inv1; c.y = o[nt][3]*inv1;
        *(float2*)(O + ((size_t)(b*Lk + r0))*Dk + h*DHk + d) = a;
        *(float2*)(O + ((size_t)(b*Lk + r1))*Dk + h*DHk + d) = c;
    }
}

// ================= tf32 split GEMM (layers), QKV-batchable via blockIdx.z ===========
// C[m,n] = sum_k A[m,k] * B[n,k]. EPI: 0 store, 1 +R, 2 silu
template<int EPI>
__global__ __launch_bounds__(256) void gemm_tf32(const float* __restrict__ A,
                                                 const float* __restrict__ B0,
                                                 const float* __restrict__ B1,
                                                 const float* __restrict__ B2,
                                                 const float* __restrict__ R,
                                                 float* __restrict__ C0,
                                                 float* __restrict__ C1,
                                                 float* __restrict__ C2,
                                                 int N, int K)
{
    const float* B = (blockIdx.z == 0) ? B0 : (blockIdx.z == 1 ? B1 : B2);
    float*       C = (blockIdx.z == 0) ? C0 : (blockIdx.z == 1 ? C1 : C2);

    __shared__ uint32_t Ah[128][20];
    __shared__ uint32_t Bh[128][20];
    __shared__ uint32_t Al[128][20];
    __shared__ uint32_t Bl[128][20];

    int t    = threadIdx.x;
    int lane = t & 31;
    int wid  = t >> 5;
    int bm0  = blockIdx.y * 128;
    int bn0  = blockIdx.x * 128;
    int wm0  = (wid & 3) * 32;
    int wn0  = (wid >> 2) * 64;

    int lrow = t >> 1;
    int lk   = (t & 1) * 8;

    const float* Ap = A + (size_t)(bm0 + lrow) * K + lk;
    const float* Bp = B + (size_t)(bn0 + lrow) * K + lk;

    float c[2][8][4];
    #pragma unroll
    for (int i = 0; i < 2; i++)
        #pragma unroll
        for (int j = 0; j < 8; j++)
            #pragma unroll
            for (int q = 0; q < 4; q++) c[i][j][q] = 0.f;

    float4 ra0 = *(const float4*)(Ap);
    float4 ra1 = *(const float4*)(Ap + 4);
    float4 rb0 = *(const float4*)(Bp);
    float4 rb1 = *(const float4*)(Bp + 4);

    int gr = lane >> 2;
    int gc = lane & 3;

    for (int k0 = 0; k0 < K; k0 += 16) {
        __syncthreads();
        {
            uint4 h0 = { cvt_tf32(ra0.x), cvt_tf32(ra0.y), cvt_tf32(ra0.z), cvt_tf32(ra0.w) };
            uint4 h1 = { cvt_tf32(ra1.x), cvt_tf32(ra1.y), cvt_tf32(ra1.z), cvt_tf32(ra1.w) };
            *(uint4*)&Ah[lrow][lk]     = h0;
            *(uint4*)&Ah[lrow][lk + 4] = h1;
            uint4 a0 = { cvt_tf32(ra0.x - __uint_as_float(h0.x)),
                         cvt_tf32(ra0.y - __uint_as_float(h0.y)),
                         cvt_tf32(ra0.z - __uint_as_float(h0.z)),
                         cvt_tf32(ra0.w - __uint_as_float(h0.w)) };
            uint4 a1 = { cvt_tf32(ra1.x - __uint_as_float(h1.x)),
                         cvt_tf32(ra1.y - __uint_as_float(h1.y)),
                         cvt_tf32(ra1.z - __uint_as_float(h1.z)),
                         cvt_tf32(ra1.w - __uint_as_float(h1.w)) };
            *(uint4*)&Al[lrow][lk]     = a0;
            *(uint4*)&Al[lrow][lk + 4] = a1;
            uint4 g0 = { cvt_tf32(rb0.x), cvt_tf32(rb0.y), cvt_tf32(rb0.z), cvt_tf32(rb0.w) };
            uint4 g1 = { cvt_tf32(rb1.x), cvt_tf32(rb1.y), cvt_tf32(rb1.z), cvt_tf32(rb1.w) };
            *(uint4*)&Bh[lrow][lk]     = g0;
            *(uint4*)&Bh[lrow][lk + 4] = g1;
            uint4 b0 = { cvt_tf32(rb0.x - __uint_as_float(g0.x)),
                         cvt_tf32(rb0.y - __uint_as_float(g0.y)),
                         cvt_tf32(rb0.z - __uint_as_float(g0.z)),
                         cvt_tf32(rb0.w - __uint_as_float(g0.w)) };
            uint4 b1 = { cvt_tf32(rb1.x - __uint_as_float(g1.x)),
                         cvt_tf32(rb1.y - __uint_as_float(g1.y)),
                         cvt_tf32(rb1.z - __uint_as_float(g1.z)),
                         cvt_tf32(rb1.w - __uint_as_float(g1.w)) };
            *(uint4*)&Bl[lrow][lk]     = b0;
            *(uint4*)&Bl[lrow][lk + 4] = b1;
        }
        __syncthreads();

        if (k0 + 16 < K) {
            ra0 = *(const float4*)(Ap + k0 + 16);
            ra1 = *(const float4*)(Ap + k0 + 20);
            rb0 = *(const float4*)(Bp + k0 + 16);
            rb1 = *(const float4*)(Bp + k0 + 20);
        }

        #pragma unroll
        for (int kk = 0; kk < 16; kk += 8) {
            uint32_t afh[2][4], bfh[8][2];
            uint32_t afl[2][4], bfl[8][2];
            #pragma unroll
            for (int mt = 0; mt < 2; mt++) {
                int rr = wm0 + mt * 16 + gr;
                afh[mt][0] = Ah[rr][kk + gc];
                afh[mt][1] = Ah[rr + 8][kk + gc];
                afh[mt][2] = Ah[rr][kk + 4 + gc];
                afh[mt][3] = Ah[rr + 8][kk + 4 + gc];
                afl[mt][0] = Al[rr][kk + gc];
                afl[mt][1] = Al[rr + 8][kk + gc];
                afl[mt][2] = Al[rr][kk + 4 + gc];
                afl[mt][3] = Al[rr + 8][kk + 4 + gc];
            }
            #pragma unroll
            for (int nt = 0; nt < 8; nt++) {
                int n0 = wn0 + nt * 8 + gr;
                bfh[nt][0] = Bh[n0][kk + gc];
                bfh[nt][1] = Bh[n0][kk + 4 + gc];
                bfl[nt][0] = Bl[n0][kk + gc];
                bfl[nt][1] = Bl[n0][kk + 4 + gc];
            }
            #pragma unroll
            for (int mt = 0; mt < 2; mt++)
                #pragma unroll
                for (int nt = 0; nt < 8; nt++) {
                    mma_tf32(c[mt][nt][0], c[mt][nt][1], c[mt][nt][2], c[mt][nt][3],
                             afh[mt][0], afh[mt][1], afh[mt][2], afh[mt][3],
                             bfh[nt][0], bfh[nt][1]);
                    mma_tf32(c[mt][nt][0], c[mt][nt][1], c[mt][nt][2], c[mt][nt][3],
                             afh[mt][0], afh[mt][1], afh[mt][2], afh[mt][3],
                             bfl[nt][0], bfl[nt][1]);
                    mma_tf32(c[mt][nt][0], c[mt][nt][1], c[mt][nt][2], c[mt][nt][3],
                             afl[mt][0], afl[mt][1], afl[mt][2], afl[mt][3],
                             bfh[nt][0], bfh[nt][1]);
                }
        }
    }

    #pragma unroll
    for (int mt = 0; mt < 2; mt++) {
        #pragma unroll
        for (int nt = 0; nt < 8; nt++) {
            int row = bm0 + wm0 + mt * 16 + gr;
            int col = bn0 + wn0 + nt * 8 + gc * 2;
            #pragma unroll
            for (int half = 0; half < 2; half++) {
                int r = row + half * 8;
                float vx = c[mt][nt][half * 2 + 0];
                float vy = c[mt][nt][half * 2 + 1];
                size_t idx = (size_t)r * N + col;
                if (EPI == 1) {
                    float2 rr = *(const float2*)(R + idx);
                    vx += rr.x; vy += rr.y;
                } else if (EPI == 2) {
                    vx = vx / (1.f + __expf(-vx));
                    vy = vy / (1.f + __expf(-vy));
                }
                float2 ov; ov.x = vx; ov.y = vy;
                *(float2*)(C + idx) = ov;
            }
        }
    }
}

// ================= LM head GEMM: single-pass tf32, double-buffered =================
__global__ __launch_bounds__(256) void gemm_lm(const float* __restrict__ A,
                                               const float* __restrict__ B,
                                               float* __restrict__ C,
                                               int N, int K)
{
    __shared__ uint32_t Ah[2][128][20];
    __shared__ uint32_t Bh[2][128][20];

    int t    = threadIdx.x;
    int lane = t & 31;
    int wid  = t >> 5;
    int bm0  = blockIdx.y * 128;
    int bn0  = blockIdx.x * 128;
    int wm0  = (wid & 3) * 32;
    int wn0  = (wid >> 2) * 64;

    int lrow = t >> 1;
    int lk   = (t & 1) * 8;

    const float* Ap = A + (size_t)(bm0 + lrow) * K + lk;
    const float* Bp = B + (size_t)(bn0 + lrow) * K + lk;

    float c[2][8][4];
    #pragma unroll
    for (int i = 0; i < 2; i++)
        #pragma unroll
        for (int j = 0; j < 8; j++)
            #pragma unroll
            for (int q = 0; q < 4; q++) c[i][j][q] = 0.f;

    int gr = lane >> 2;
    int gc = lane & 3;

    // prologue: stage 0
    {
        float4 ra0 = *(const float4*)(Ap);
        float4 ra1 = *(const float4*)(Ap + 4);
        float4 rb0 = *(const float4*)(Bp);
        float4 rb1 = *(const float4*)(Bp + 4);
        uint4 h0 = { cvt_tf32(ra0.x), cvt_tf32(ra0.y), cvt_tf32(ra0.z), cvt_tf32(ra0.w) };
        uint4 h1 = { cvt_tf32(ra1.x), cvt_tf32(ra1.y), cvt_tf32(ra1.z), cvt_tf32(ra1.w) };
        *(uint4*)&Ah[0][lrow][lk]     = h0;
        *(uint4*)&Ah[0][lrow][lk + 4] = h1;
        uint4 g0 = { cvt_tf32(rb0.x), cvt_tf32(rb0.y), cvt_tf32(rb0.z), cvt_tf32(rb0.w) };
        uint4 g1 = { cvt_tf32(rb1.x), cvt_tf32(rb1.y), cvt_tf32(rb1.z), cvt_tf32(rb1.w) };
        *(uint4*)&Bh[0][lrow][lk]     = g0;
        *(uint4*)&Bh[0][lrow][lk + 4] = g1;
    }

    int cur = 0;
    for (int k0 = 0; k0 < K; k0 += 16) {
        __syncthreads();
        bool hasnext = (k0 + 16 < K);
        float4 ra0, ra1, rb0, rb1;
        if (hasnext) {
            ra0 = *(const float4*)(Ap + k0 + 16);
            ra1 = *(const float4*)(Ap + k0 + 20);
            rb0 = *(const float4*)(Bp + k0 + 16);
            rb1 = *(const float4*)(Bp + k0 + 20);
        }

        #pragma unroll
        for (int kk = 0; kk < 16; kk += 8) {
            uint32_t afh[2][4], bfh[8][2];
            #pragma unroll
            for (int mt = 0; mt < 2; mt++) {
                int rr = wm0 + mt * 16 + gr;
                afh[mt][0] = Ah[cur][rr][kk + gc];
                afh[mt][1] = Ah[cur][rr + 8][kk + gc];
                afh[mt][2] = Ah[cur][rr][kk + 4 + gc];
                afh[mt][3] = Ah[cur][rr + 8][kk + 4 + gc];
            }
            #pragma unroll
            for (int nt = 0; nt < 8; nt++) {
                int n0 = wn0 + nt * 8 + gr;
                bfh[nt][0] = Bh[cur][n0][kk + gc];
                bfh[nt][1] = Bh[cur][n0][kk + 4 + gc];
            }
            #pragma unroll
            for (int mt = 0; mt < 2; mt++)
                #pragma unroll
                for (int nt = 0; nt < 8; nt++)
                    mma_tf32(c[mt][nt][0], c[mt][nt][1], c[mt][nt][2], c[mt][nt][3],
                             afh[mt][0], afh[mt][1], afh[mt][2], afh[mt][3],
                             bfh[nt][0], bfh[nt][1]);
        }

        if (hasnext) {
            int nxt = cur ^ 1;
            uint4 h0 = { cvt_tf32(ra0.x), cvt_tf32(ra0.y), cvt_tf32(ra0.z), cvt_tf32(ra0.w) };
            uint4 h1 = { cvt_tf32(ra1.x), cvt_tf32(ra1.y), cvt_tf32(ra1.z), cvt_tf32(ra1.w) };
            *(uint4*)&Ah[nxt][lrow][lk]     = h0;
            *(uint4*)&Ah[nxt][lrow][lk + 4] = h1;
            uint4 g0 = { cvt_tf32(rb0.x), cvt_tf32(rb0.y), cvt_tf32(rb0.z), cvt_tf32(rb0.w) };
            uint4 g1 = { cvt_tf32(rb1.x), cvt_tf32(rb1.y), cvt_tf32(rb1.z), cvt_tf32(rb1.w) };
            *(uint4*)&Bh[nxt][lrow][lk]     = g0;
            *(uint4*)&Bh[nxt][lrow][lk + 4] = g1;
        }
        cur ^= 1;
    }

    #pragma unroll
    for (int mt = 0; mt < 2; mt++) {
        #pragma unroll
        for (int nt = 0; nt < 8; nt++) {
            int row = bm0 + wm0 + mt * 16 + gr;
            int col = bn0 + wn0 + nt * 8 + gc * 2;
            #pragma unroll
            for (int half = 0; half < 2; half++) {
                int r = row + half * 8;
                float2 ov;
                ov.x = c[mt][nt][half * 2 + 0];
                ov.y = c[mt][nt][half * 2 + 1];
                *(float2*)(C + (size_t)r * N + col) = ov;
            }
        }
    }
}

// ---------------- classifier heads ----------------
__global__ void heads_kernel(const float* __restrict__ XN,
                             const float* __restrict__ rw, const float* __restrict__ rb,
                             const float* __restrict__ mw, const float* __restrict__ mb,
                             float* __restrict__ out)
{
    int w = threadIdx.x >> 5, lane = threadIdx.x & 31;
    if (w >= Bk) return;
    const float* x = XN + (size_t)w * Lk * Dk;
    float sr = 0.f, sm = 0.f;
    for (int d = lane; d < Dk; d += 32) {
        float xv = x[d];
        sr += xv * rw[d];
        sm += xv * mw[d];
    }
    #pragma unroll
    for (int o = 16; o > 0; o >>= 1) {
        sr += __shfl_down_sync(0xffffffffu, sr, o);
        sm += __shfl_down_sync(0xffffffffu, sm, o);
    }
    if (lane == 0) {
        out[w]      = sr + rb[0];
        out[Bk + w] = sm + mb[0];
    }
}

// ---------------- launch ----------------
extern "C" void kernel_launch(void* const* d_in, const int* in_sizes, int n_in,
                              void* d_out, int out_size)
{
    const int*   ids      = (const int*)d_in[0];
    const int*   tts      = (const int*)d_in[1];
    const int*   mask     = (const int*)d_in[2];
    const float* tok_emb  = (const float*)d_in[3];
    const float* type_emb = (const float*)d_in[4];
    const float* norm1    = (const float*)d_in[5];
    const float* wq       = (const float*)d_in[6];
    const float* wk       = (const float*)d_in[7];
    const float* wv       = (const float*)d_in[8];
    const float* wo       = (const float*)d_in[9];
    const float* norm2    = (const float*)d_in[10];
    const float* fw1      = (const float*)d_in[11];
    const float* fw2      = (const float*)d_in[12];
    const float* fnorm    = (const float*)d_in[13];
    const float* lmw      = (const float*)d_in[14];
    const float* rw       = (const float*)d_in[15];
    const float* rbias    = (const float*)d_in[16];
    const float* mw       = (const float*)d_in[17];
    const float* mbias    = (const float*)d_in[18];
    float* out = (float*)d_out;

    float *X, *XN, *Q, *K, *V, *AO, *F1;
    cudaGetSymbolAddress((void**)&X,  g_X);
    cudaGetSymbolAddress((void**)&XN, g_XN);
    cudaGetSymbolAddress((void**)&Q,  g_Q);
    cudaGetSymbolAddress((void**)&K,  g_K);
    cudaGetSymbolAddress((void**)&V,  g_V);
    cudaGetSymbolAddress((void**)&AO, g_AO);
    cudaGetSymbolAddress((void**)&F1, g_F1);

    embed_kernel<<<(MR * Dk) / 256, 256>>>(ids, tts, tok_emb, type_emb, X);

    dim3 gqkv(Dk  / 128, MR / 128, 3);
    dim3 gs  (Dk  / 128, MR / 128, 1);
    dim3 gf1 (FFD / 128, MR / 128, 1);
    dim3 glm (Vk  / 128, MR / 128);
    dim3 ga  (Lk / 64, Hk, Bk);
    dim3 grp ((MR * Hk * 32) / 256, 2);

    for (int i = 0; i < NLk; i++) {
        const float* wqi = wq + (size_t)i * Dk * Dk;
        const float* wki = wk + (size_t)i * Dk * Dk;
        const float* wvi = wv + (size_t)i * Dk * Dk;
        const float* woi = wo + (size_t)i * Dk * Dk;
        const float* f1i = fw1 + (size_t)i * FFD * Dk;
        const float* f2i = fw2 + (size_t)i * Dk * FFD;

        rmsnorm_kernel<<<MR, 256>>>(X, norm1 + (size_t)i * Dk, XN);
        gemm_tf32<0><<<gqkv, 256>>>(XN, wqi, wki, wvi, nullptr, Q, K, V, Dk, Dk);
        rope2_kernel<<<grp, 256>>>(Q, K);
        attn_fa<<<ga, 128>>>(Q, K, V, mask, AO);
        gemm_tf32<1><<<gs, 256>>>(AO, woi, woi, woi, X, X, X, X, Dk, Dk);
        rmsnorm_kernel<<<MR, 256>>>(X, norm2 + (size_t)i * Dk, XN);
        gemm_tf32<2><<<gf1, 256>>>(XN, f1i, f1i, f1i, nullptr, F1, F1, F1, FFD, Dk);
        gemm_tf32<1><<<gs, 256>>>(F1, f2i, f2i, f2i, X, X, X, X, Dk, FFD);
    }

    rmsnorm_kernel<<<MR, 256>>>(X, fnorm, XN);
    gemm_lm<<<glm, 256>>>(XN, lmw, out, Vk, Dk);
    heads_kernel<<<1, 128>>>(XN, rw, rbias, mw, mbias, out + (size_t)Bk * Lk * Vk);
}

// round 4
// speedup vs baseline: 2.5896x; 1.0575x over previous
#include <cuda_runtime.h>
#include <math.h>
#include <stdint.h>

// Problem constants
#define Bk   4
#define Lk   2048
#define Dk   256
#define Hk   4
#define NLk  4
#define Vk   32000
#define DHk  64
#define MR   (Bk*Lk)      // 8192 rows
#define FFD  (4*Dk)       // 1024

// ---------------- scratch ----------------
__device__ float g_X [MR*Dk];
__device__ float g_XN[MR*Dk];
__device__ float g_Q [MR*Dk];
__device__ float g_K [MR*Dk];
__device__ float g_V [MR*Dk];
__device__ float g_AO[MR*Dk];      // reused as tf32-converted XN for LM head
__device__ float g_F1[MR*FFD];
__device__ float g_LW32[Vk*Dk];    // tf32-converted lm_w

// ---------------- helpers ----------------
__device__ __forceinline__ uint32_t cvt_tf32(float x) {
    uint32_t r;
    asm("cvt.rna.tf32.f32 %0, %1;" : "=r"(r) : "f"(x));
    return r;
}

__device__ __forceinline__ void mma_tf32(float& c0, float& c1, float& c2, float& c3,
                                         uint32_t a0, uint32_t a1, uint32_t a2, uint32_t a3,
                                         uint32_t b0, uint32_t b1)
{
    asm volatile("mma.sync.aligned.m16n8k8.row.col.f32.tf32.tf32.f32 "
                 "{%0,%1,%2,%3},{%4,%5,%6,%7},{%8,%9},{%0,%1,%2,%3};"
                 : "+f"(c0), "+f"(c1), "+f"(c2), "+f"(c3)
                 : "r"(a0), "r"(a1), "r"(a2), "r"(a3), "r"(b0), "r"(b1));
}

__device__ __forceinline__ void cp16(uint32_t smem, const void* gmem) {
    asm volatile("cp.async.ca.shared.global [%0], [%1], 16;\n" :: "r"(smem), "l"(gmem));
}
#define CP_COMMIT() asm volatile("cp.async.commit_group;\n" ::: "memory")
#define CP_WAIT1()  asm volatile("cp.async.wait_group 1;\n" ::: "memory")

// ---------------- embedding ----------------
__global__ void embed_kernel(const int* __restrict__ ids, const int* __restrict__ tts,
                             const float* __restrict__ te, const float* __restrict__ ye,
                             float* __restrict__ X)
{
    int i = blockIdx.x * 256 + threadIdx.x;
    int row = i >> 8;
    int d   = i & 255;
    X[i] = te[(size_t)ids[row] * Dk + d] + ye[(size_t)tts[row] * Dk + d];
}

// ---------------- elementwise tf32 pre-convert ----------------
__global__ void cvt_kernel(const float* __restrict__ src, float* __restrict__ dst, int n)
{
    int i = blockIdx.x * 256 + threadIdx.x;
    if (i < n) dst[i] = __uint_as_float(cvt_tf32(src[i]));
}

// ---------------- RMSNorm ----------------
__global__ __launch_bounds__(256) void rmsnorm_kernel(const float* __restrict__ X,
                                                      const float* __restrict__ w,
                                                      float* __restrict__ Y)
{
    int r = blockIdx.x;
    int t = threadIdx.x;
    float v = X[(size_t)r * Dk + t];
    float s = v * v;
    #pragma unroll
    for (int o = 16; o > 0; o >>= 1) s += __shfl_down_sync(0xffffffffu, s, o);
    __shared__ float ws[8];
    __shared__ float tot;
    int lane = t & 31, wi = t >> 5;
    if (lane == 0) ws[wi] = s;
    __syncthreads();
    if (t == 0) {
        float a = 0.f;
        #pragma unroll
        for (int i = 0; i < 8; i++) a += ws[i];
        tot = a;
    }
    __syncthreads();
    float rs = rsqrtf(tot * (1.0f / Dk) + 1.1920929e-07f);
    Y[(size_t)r * Dk + t] = v * rs * w[t];
}

// ---------------- RoPE (Q and K in one launch via blockIdx.y) ----------------
__global__ void rope2_kernel(float* __restrict__ Q, float* __restrict__ K)
{
    float* P = blockIdx.y ? K : Q;
    int i   = blockIdx.x * 256 + threadIdx.x;
    int t   = i & 31;
    int h   = (i >> 5) & 3;
    int row = i >> 7;
    int pos = row & (Lk - 1);
    float inv = exp2f(-(float)t * (13.287712379549449f / 32.0f));
    float ang = (float)pos * inv;
    float sn, cs;
    sincosf(ang, &sn, &cs);
    size_t base = (size_t)row * Dk + h * DHk;
    float a = P[base + t];
    float b = P[base + t + 32];
    P[base + t]      = a * cs - b * sn;
    P[base + t + 32] = b * cs + a * sn;
}

// ---------------- tensor-core flash attention ----------------
#define APAD 68
__global__ __launch_bounds__(128) void attn_fa(const float* __restrict__ Q,
                                               const float* __restrict__ K,
                                               const float* __restrict__ V,
                                               const int*   __restrict__ mask,
                                               float* __restrict__ O)
{
    __shared__ uint32_t KP[64][APAD];   // K tile, later aliased as P
    __shared__ uint32_t Vs[64][APAD];   // V transposed: Vs[d][key]
    __shared__ float    mkf[64];

    int b  = blockIdx.z, h = blockIdx.y;
    int q0 = blockIdx.x * 64;
    int tid = threadIdx.x;
    int lane = tid & 31, wid = tid >> 5;
    int gr = lane >> 2, gc = lane & 3;
    int wr = wid * 16;

    const int* mrow = mask + (size_t)b * Lk;

    #pragma unroll
    for (int it = 0; it < 8; it++) {
        int pos = tid + it * 128;
        int row = pos >> 4, d4 = pos & 15;
        float4 qv = *(const float4*)(Q + ((size_t)(b*Lk + q0 + row))*Dk + h*DHk + d4*4);
        uint4 u = { cvt_tf32(qv.x*0.125f), cvt_tf32(qv.y*0.125f),
                    cvt_tf32(qv.z*0.125f), cvt_tf32(qv.w*0.125f) };
        *(uint4*)&KP[row][d4*4] = u;
    }
    __syncthreads();
    uint32_t qa[8][4];
    #pragma unroll
    for (int kk = 0; kk < 8; kk++) {
        qa[kk][0] = KP[wr+gr  ][kk*8+gc];
        qa[kk][1] = KP[wr+gr+8][kk*8+gc];
        qa[kk][2] = KP[wr+gr  ][kk*8+gc+4];
        qa[kk][3] = KP[wr+gr+8][kk*8+gc+4];
    }

    float o[8][4];
    #pragma unroll
    for (int nt = 0; nt < 8; nt++)
        #pragma unroll
        for (int j = 0; j < 4; j++) o[nt][j] = 0.f;
    float m0 = -1e30f, m1 = -1e30f, l0 = 0.f, l1 = 0.f;
    int r0 = q0 + wr + gr, r1 = r0 + 8;

    int ntile = blockIdx.x + 1;
    for (int kt = 0; kt < ntile; kt++) {
        int key0 = kt * 64;
        __syncthreads();
        #pragma unroll
        for (int it = 0; it < 8; it++) {
            int pos = tid + it * 128;
            int key = pos >> 4, d4 = pos & 15;
            size_t gbase = ((size_t)(b*Lk + key0 + key))*Dk + h*DHk + d4*4;
            float4 kv = *(const float4*)(K + gbase);
            uint4 u = { cvt_tf32(kv.x), cvt_tf32(kv.y), cvt_tf32(kv.z), cvt_tf32(kv.w) };
            *(uint4*)&KP[key][d4*4] = u;
            float4 vv = *(const float4*)(V + gbase);
            Vs[d4*4+0][key] = cvt_tf32(vv.x);
            Vs[d4*4+1][key] = cvt_tf32(vv.y);
            Vs[d4*4+2][key] = cvt_tf32(vv.z);
            Vs[d4*4+3][key] = cvt_tf32(vv.w);
        }
        if (tid < 64) mkf[tid] = mrow[key0 + tid] ? 0.0f : -1e30f;
        __syncthreads();

        float s[8][4];
        #pragma unroll
        for (int nt = 0; nt < 8; nt++)
            #pragma unroll
            for (int j = 0; j < 4; j++) s[nt][j] = 0.f;
        #pragma unroll
        for (int kk = 0; kk < 8; kk++) {
            #pragma unroll
            for (int nt = 0; nt < 8; nt++) {
                uint32_t b0 = KP[nt*8+gr][kk*8+gc];
                uint32_t b1 = KP[nt*8+gr][kk*8+gc+4];
                mma_tf32(s[nt][0], s[nt][1], s[nt][2], s[nt][3],
                         qa[kk][0], qa[kk][1], qa[kk][2], qa[kk][3], b0, b1);
            }
        }

        bool last = (kt == ntile - 1);
        #pragma unroll
        for (int nt = 0; nt < 8; nt++) {
            float mk0 = mkf[nt*8+gc*2], mk1 = mkf[nt*8+gc*2+1];
            s[nt][0] += mk0; s[nt][1] += mk1;
            s[nt][2] += mk0; s[nt][3] += mk1;
            if (last) {
                int c = key0 + nt*8 + gc*2;
                if (c     > r0) s[nt][0] = -1e30f;
                if (c + 1 > r0) s[nt][1] = -1e30f;
                if (c     > r1) s[nt][2] = -1e30f;
                if (c + 1 > r1) s[nt][3] = -1e30f;
            }
        }

        float rm0 = -1e30f, rm1 = -1e30f;
        #pragma unroll
        for (int nt = 0; nt < 8; nt++) {
            rm0 = fmaxf(rm0, fmaxf(s[nt][0], s[nt][1]));
            rm1 = fmaxf(rm1, fmaxf(s[nt][2], s[nt][3]));
        }
        rm0 = fmaxf(rm0, __shfl_xor_sync(0xffffffffu, rm0, 1));
        rm0 = fmaxf(rm0, __shfl_xor_sync(0xffffffffu, rm0, 2));
        rm1 = fmaxf(rm1, __shfl_xor_sync(0xffffffffu, rm1, 1));
        rm1 = fmaxf(rm1, __shfl_xor_sync(0xffffffffu, rm1, 2));

        float mn0 = fmaxf(m0, rm0), mn1 = fmaxf(m1, rm1);
        float cor0 = __expf(m0 - mn0), cor1 = __expf(m1 - mn1);
        m0 = mn0; m1 = mn1;

        __syncthreads();

        float ps0 = 0.f, ps1 = 0.f;
        #pragma unroll
        for (int nt = 0; nt < 8; nt++) {
            float p00 = __expf(s[nt][0] - mn0);
            float p01 = __expf(s[nt][1] - mn0);
            float p10 = __expf(s[nt][2] - mn1);
            float p11 = __expf(s[nt][3] - mn1);
            ps0 += p00 + p01;
            ps1 += p10 + p11;
            KP[wr+gr  ][nt*8+gc*2  ] = cvt_tf32(p00);
            KP[wr+gr  ][nt*8+gc*2+1] = cvt_tf32(p01);
            KP[wr+gr+8][nt*8+gc*2  ] = cvt_tf32(p10);
            KP[wr+gr+8][nt*8+gc*2+1] = cvt_tf32(p11);
        }
        ps0 += __shfl_xor_sync(0xffffffffu, ps0, 1);
        ps0 += __shfl_xor_sync(0xffffffffu, ps0, 2);
        ps1 += __shfl_xor_sync(0xffffffffu, ps1, 1);
        ps1 += __shfl_xor_sync(0xffffffffu, ps1, 2);
        l0 = l0 * cor0 + ps0;
        l1 = l1 * cor1 + ps1;
        #pragma unroll
        for (int nt = 0; nt < 8; nt++) {
            o[nt][0] *= cor0; o[nt][1] *= cor0;
            o[nt][2] *= cor1; o[nt][3] *= cor1;
        }
        __syncwarp();

        #pragma unroll
        for (int kk = 0; kk < 8; kk++) {
            uint32_t pa0 = KP[wr+gr  ][kk*8+gc];
            uint32_t pa1 = KP[wr+gr+8][kk*8+gc];
            uint32_t pa2 = KP[wr+gr  ][kk*8+gc+4];
            uint32_t pa3 = KP[wr+gr+8][kk*8+gc+4];
            #pragma unroll
            for (int nt = 0; nt < 8; nt++) {
                uint32_t vb0 = Vs[nt*8+gr][kk*8+gc];
                uint32_t vb1 = Vs[nt*8+gr][kk*8+gc+4];
                mma_tf32(o[nt][0], o[nt][1], o[nt][2], o[nt][3],
                         pa0, pa1, pa2, pa3, vb0, vb1);
            }
        }
    }

    float inv0 = 1.0f / l0, inv1 = 1.0f / l1;
    #pragma unroll
    for (int nt = 0; nt < 8; nt++) {
        int d = nt*8 + gc*2;
        float2 a; a.x = o[nt][0]*inv0; a.y = o[nt][1]*inv0;
        float2 c; c.x = o[nt][2]*inv1; c.y = o[nt][3]*inv1;
        *(float2*)(O + ((size_t)(b*Lk + r0))*Dk + h*DHk + d) = a;
        *(float2*)(O + ((size_t)(b*Lk + r1))*Dk + h*DHk + d) = c;
    }
}

// ================= tf32 split GEMM (layers), QKV-batchable via blockIdx.z ===========
template<int EPI>
__global__ __launch_bounds__(256) void gemm_tf32(const float* __restrict__ A,
                                                 const float* __restrict__ B0,
                                                 const float* __restrict__ B1,
                                                 const float* __restrict__ B2,
                                                 const float* __restrict__ R,
                                                 float* __restrict__ C0,
                                                 float* __restrict__ C1,
                                                 float* __restrict__ C2,
                                                 int N, int K)
{
    const float* B = (blockIdx.z == 0) ? B0 : (blockIdx.z == 1 ? B1 : B2);
    float*       C = (blockIdx.z == 0) ? C0 : (blockIdx.z == 1 ? C1 : C2);

    __shared__ uint32_t Ah[128][20];
    __shared__ uint32_t Bh[128][20];
    __shared__ uint32_t Al[128][20];
    __shared__ uint32_t Bl[128][20];

    int t    = threadIdx.x;
    int lane = t & 31;
    int wid  = t >> 5;
    int bm0  = blockIdx.y * 128;
    int bn0  = blockIdx.x * 128;
    int wm0  = (wid & 3) * 32;
    int wn0  = (wid >> 2) * 64;

    int lrow = t >> 1;
    int lk   = (t & 1) * 8;

    const float* Ap = A + (size_t)(bm0 + lrow) * K + lk;
    const float* Bp = B + (size_t)(bn0 + lrow) * K + lk;

    float c[2][8][4];
    #pragma unroll
    for (int i = 0; i < 2; i++)
        #pragma unroll
        for (int j = 0; j < 8; j++)
            #pragma unroll
            for (int q = 0; q < 4; q++) c[i][j][q] = 0.f;

    float4 ra0 = *(const float4*)(Ap);
    float4 ra1 = *(const float4*)(Ap + 4);
    float4 rb0 = *(const float4*)(Bp);
    float4 rb1 = *(const float4*)(Bp + 4);

    int gr = lane >> 2;
    int gc = lane & 3;

    for (int k0 = 0; k0 < K; k0 += 16) {
        __syncthreads();
        {
            uint4 h0 = { cvt_tf32(ra0.x), cvt_tf32(ra0.y), cvt_tf32(ra0.z), cvt_tf32(ra0.w) };
            uint4 h1 = { cvt_tf32(ra1.x), cvt_tf32(ra1.y), cvt_tf32(ra1.z), cvt_tf32(ra1.w) };
            *(uint4*)&Ah[lrow][lk]     = h0;
            *(uint4*)&Ah[lrow][lk + 4] = h1;
            uint4 a0 = { cvt_tf32(ra0.x - __uint_as_float(h0.x)),
                         cvt_tf32(ra0.y - __uint_as_float(h0.y)),
                         cvt_tf32(ra0.z - __uint_as_float(h0.z)),
                         cvt_tf32(ra0.w - __uint_as_float(h0.w)) };
            uint4 a1 = { cvt_tf32(ra1.x - __uint_as_float(h1.x)),
                         cvt_tf32(ra1.y - __uint_as_float(h1.y)),
                         cvt_tf32(ra1.z - __uint_as_float(h1.z)),
                         cvt_tf32(ra1.w - __uint_as_float(h1.w)) };
            *(uint4*)&Al[lrow][lk]     = a0;
            *(uint4*)&Al[lrow][lk + 4] = a1;
            uint4 g0 = { cvt_tf32(rb0.x), cvt_tf32(rb0.y), cvt_tf32(rb0.z), cvt_tf32(rb0.w) };
            uint4 g1 = { cvt_tf32(rb1.x), cvt_tf32(rb1.y), cvt_tf32(rb1.z), cvt_tf32(rb1.w) };
            *(uint4*)&Bh[lrow][lk]     = g0;
            *(uint4*)&Bh[lrow][lk + 4] = g1;
            uint4 b0 = { cvt_tf32(rb0.x - __uint_as_float(g0.x)),
                         cvt_tf32(rb0.y - __uint_as_float(g0.y)),
                         cvt_tf32(rb0.z - __uint_as_float(g0.z)),
                         cvt_tf32(rb0.w - __uint_as_float(g0.w)) };
            uint4 b1 = { cvt_tf32(rb1.x - __uint_as_float(g1.x)),
                         cvt_tf32(rb1.y - __uint_as_float(g1.y)),
                         cvt_tf32(rb1.z - __uint_as_float(g1.z)),
                         cvt_tf32(rb1.w - __uint_as_float(g1.w)) };
            *(uint4*)&Bl[lrow][lk]     = b0;
            *(uint4*)&Bl[lrow][lk + 4] = b1;
        }
        __syncthreads();

        if (k0 + 16 < K) {
            ra0 = *(const float4*)(Ap + k0 + 16);
            ra1 = *(const float4*)(Ap + k0 + 20);
            rb0 = *(const float4*)(Bp + k0 + 16);
            rb1 = *(const float4*)(Bp + k0 + 20);
        }

        #pragma unroll
        for (int kk = 0; kk < 16; kk += 8) {
            uint32_t afh[2][4], bfh[8][2];
            uint32_t afl[2][4], bfl[8][2];
            #pragma unroll
            for (int mt = 0; mt < 2; mt++) {
                int rr = wm0 + mt * 16 + gr;
                afh[mt][0] = Ah[rr][kk + gc];
                afh[mt][1] = Ah[rr + 8][kk + gc];
                afh[mt][2] = Ah[rr][kk + 4 + gc];
                afh[mt][3] = Ah[rr + 8][kk + 4 + gc];
                afl[mt][0] = Al[rr][kk + gc];
                afl[mt][1] = Al[rr + 8][kk + gc];
                afl[mt][2] = Al[rr][kk + 4 + gc];
                afl[mt][3] = Al[rr + 8][kk + 4 + gc];
            }
            #pragma unroll
            for (int nt = 0; nt < 8; nt++) {
                int n0 = wn0 + nt * 8 + gr;
                bfh[nt][0] = Bh[n0][kk + gc];
                bfh[nt][1] = Bh[n0][kk + 4 + gc];
                bfl[nt][0] = Bl[n0][kk + gc];
                bfl[nt][1] = Bl[n0][kk + 4 + gc];
            }
            #pragma unroll
            for (int mt = 0; mt < 2; mt++)
                #pragma unroll
                for (int nt = 0; nt < 8; nt++) {
                    mma_tf32(c[mt][nt][0], c[mt][nt][1], c[mt][nt][2], c[mt][nt][3],
                             afh[mt][0], afh[mt][1], afh[mt][2], afh[mt][3],
                             bfh[nt][0], bfh[nt][1]);
                    mma_tf32(c[mt][nt][0], c[mt][nt][1], c[mt][nt][2], c[mt][nt][3],
                             afh[mt][0], afh[mt][1], afh[mt][2], afh[mt][3],
                             bfl[nt][0], bfl[nt][1]);
                    mma_tf32(c[mt][nt][0], c[mt][nt][1], c[mt][nt][2], c[mt][nt][3],
                             afl[mt][0], afl[mt][1], afl[mt][2], afl[mt][3],
                             bfh[nt][0], bfh[nt][1]);
                }
        }
    }

    #pragma unroll
    for (int mt = 0; mt < 2; mt++) {
        #pragma unroll
        for (int nt = 0; nt < 8; nt++) {
            int row = bm0 + wm0 + mt * 16 + gr;
            int col = bn0 + wn0 + nt * 8 + gc * 2;
            #pragma unroll
            for (int half = 0; half < 2; half++) {
                int r = row + half * 8;
                float vx = c[mt][nt][half * 2 + 0];
                float vy = c[mt][nt][half * 2 + 1];
                size_t idx = (size_t)r * N + col;
                if (EPI == 1) {
                    float2 rr = *(const float2*)(R + idx);
                    vx += rr.x; vy += rr.y;
                } else if (EPI == 2) {
                    vx = vx / (1.f + __expf(-vx));
                    vy = vy / (1.f + __expf(-vy));
                }
                float2 ov; ov.x = vx; ov.y = vy;
                *(float2*)(C + idx) = ov;
            }
        }
    }
}

// ================= LM head GEMM: pre-converted tf32, cp.async 2-stage =================
__global__ __launch_bounds__(256, 2) void gemm_lm(const float* __restrict__ A,
                                                  const float* __restrict__ B,
                                                  float* __restrict__ C,
                                                  int N, int K)
{
    __shared__ uint32_t sA[2][128][20];
    __shared__ uint32_t sB[2][128][20];

    int t    = threadIdx.x;
    int lane = t & 31;
    int wid  = t >> 5;
    int bm0  = blockIdx.y * 128;
    int bn0  = blockIdx.x * 128;
    int wm0  = (wid & 3) * 32;
    int wn0  = (wid >> 2) * 64;

    int lrow = t >> 1;
    int lk   = (t & 1) * 8;

    const float* Ap = A + (size_t)(bm0 + lrow) * K + lk;
    const float* Bp = B + (size_t)(bn0 + lrow) * K + lk;

    float c[2][8][4];
    #pragma unroll
    for (int i = 0; i < 2; i++)
        #pragma unroll
        for (int j = 0; j < 8; j++)
            #pragma unroll
            for (int q = 0; q < 4; q++) c[i][j][q] = 0.f;

    int gr = lane >> 2;
    int gc = lane & 3;

    uint32_t saA0 = (uint32_t)__cvta_generic_to_shared(&sA[0][lrow][lk]);
    uint32_t saB0 = (uint32_t)__cvta_generic_to_shared(&sB[0][lrow][lk]);
    const uint32_t stageStride = 128 * 20 * 4;

    // prologue: issue both stages
    #pragma unroll
    for (int s = 0; s < 2; s++) {
        int ko = s * 16;
        cp16(saA0 + s * stageStride,      Ap + ko);
        cp16(saA0 + s * stageStride + 16, Ap + ko + 4);
        cp16(saB0 + s * stageStride,      Bp + ko);
        cp16(saB0 + s * stageStride + 16, Bp + ko + 4);
        CP_COMMIT();
    }

    const int niter = K / 16;    // 16
    for (int it = 0; it < niter; it++) {
        CP_WAIT1();
        __syncthreads();
        int cur = it & 1;

        #pragma unroll
        for (int kk = 0; kk < 16; kk += 8) {
            uint32_t afh[2][4], bfh[8][2];
            #pragma unroll
            for (int mt = 0; mt < 2; mt++) {
                int rr = wm0 + mt * 16 + gr;
                afh[mt][0] = sA[cur][rr][kk + gc];
                afh[mt][1] = sA[cur][rr + 8][kk + gc];
                afh[mt][2] = sA[cur][rr][kk + 4 + gc];
                afh[mt][3] = sA[cur][rr + 8][kk + 4 + gc];
            }
            #pragma unroll
            for (int nt = 0; nt < 8; nt++) {
                int n0 = wn0 + nt * 8 + gr;
                bfh[nt][0] = sB[cur][n0][kk + gc];
                bfh[nt][1] = sB[cur][n0][kk + 4 + gc];
            }
            #pragma unroll
            for (int mt = 0; mt < 2; mt++)
                #pragma unroll
                for (int nt = 0; nt < 8; nt++)
                    mma_tf32(c[mt][nt][0], c[mt][nt][1], c[mt][nt][2], c[mt][nt][3],
                             afh[mt][0], afh[mt][1], afh[mt][2], afh[mt][3],
                             bfh[nt][0], bfh[nt][1]);
        }

        __syncthreads();
        if (it + 2 < niter) {
            int ko = (it + 2) * 16;
            cp16(saA0 + cur * stageStride,      Ap + ko);
            cp16(saA0 + cur * stageStride + 16, Ap + ko + 4);
            cp16(saB0 + cur * stageStride,      Bp + ko);
            cp16(saB0 + cur * stageStride + 16, Bp + ko + 4);
        }
        CP_COMMIT();   // empty group when no loads — keeps wait_group accounting uniform
    }

    #pragma unroll
    for (int mt = 0; mt < 2; mt++) {
        #pragma unroll
        for (int nt = 0; nt < 8; nt++) {
            int row = bm0 + wm0 + mt * 16 + gr;
            int col = bn0 + wn0 + nt * 8 + gc * 2;
            #pragma unroll
            for (int half = 0; half < 2; half++) {
                int r = row + half * 8;
                float2 ov;
                ov.x = c[mt][nt][half * 2 + 0];
                ov.y = c[mt][nt][half * 2 + 1];
                *(float2*)(C + (size_t)r * N + col) = ov;
            }
        }
    }
}

// ---------------- classifier heads ----------------
__global__ void heads_kernel(const float* __restrict__ XN,
                             const float* __restrict__ rw, const float* __restrict__ rb,
                             const float* __restrict__ mw, const float* __restrict__ mb,
                             float* __restrict__ out)
{
    int w = threadIdx.x >> 5, lane = threadIdx.x & 31;
    if (w >= Bk) return;
    const float* x = XN + (size_t)w * Lk * Dk;
    float sr = 0.f, sm = 0.f;
    for (int d = lane; d < Dk; d += 32) {
        float xv = x[d];
        sr += xv * rw[d];
        sm += xv * mw[d];
    }
    #pragma unroll
    for (int o = 16; o > 0; o >>= 1) {
        sr += __shfl_down_sync(0xffffffffu, sr, o);
        sm += __shfl_down_sync(0xffffffffu, sm, o);
    }
    if (lane == 0) {
        out[w]      = sr + rb[0];
        out[Bk + w] = sm + mb[0];
    }
}

// ---------------- launch ----------------
extern "C" void kernel_launch(void* const* d_in, const int* in_sizes, int n_in,
                              void* d_out, int out_size)
{
    const int*   ids      = (const int*)d_in[0];
    const int*   tts      = (const int*)d_in[1];
    const int*   mask     = (const int*)d_in[2];
    const float* tok_emb  = (const float*)d_in[3];
    const float* type_emb = (const float*)d_in[4];
    const float* norm1    = (const float*)d_in[5];
    const float* wq       = (const float*)d_in[6];
    const float* wk       = (const float*)d_in[7];
    const float* wv       = (const float*)d_in[8];
    const float* wo       = (const float*)d_in[9];
    const float* norm2    = (const float*)d_in[10];
    const float* fw1      = (const float*)d_in[11];
    const float* fw2      = (const float*)d_in[12];
    const float* fnorm    = (const float*)d_in[13];
    const float* lmw      = (const float*)d_in[14];
    const float* rw       = (const float*)d_in[15];
    const float* rbias    = (const float*)d_in[16];
    const float* mw       = (const float*)d_in[17];
    const float* mbias    = (const float*)d_in[18];
    float* out = (float*)d_out;

    float *X, *XN, *Q, *K, *V, *AO, *F1, *LW32;
    cudaGetSymbolAddress((void**)&X,  g_X);
    cudaGetSymbolAddress((void**)&XN, g_XN);
    cudaGetSymbolAddress((void**)&Q,  g_Q);
    cudaGetSymbolAddress((void**)&K,  g_K);
    cudaGetSymbolAddress((void**)&V,  g_V);
    cudaGetSymbolAddress((void**)&AO, g_AO);
    cudaGetSymbolAddress((void**)&F1, g_F1);
    cudaGetSymbolAddress((void**)&LW32, g_LW32);

    embed_kernel<<<(MR * Dk) / 256, 256>>>(ids, tts, tok_emb, type_emb, X);
    // pre-convert LM weights (independent of everything else: issue early)
    cvt_kernel<<<(Vk * Dk) / 256, 256>>>(lmw, LW32, Vk * Dk);

    dim3 gqkv(Dk  / 128, MR / 128, 3);
    dim3 gs  (Dk  / 128, MR / 128, 1);
    dim3 gf1 (FFD / 128, MR / 128, 1);
    dim3 glm (Vk  / 128, MR / 128);
    dim3 ga  (Lk / 64, Hk, Bk);
    dim3 grp ((MR * Hk * 32) / 256, 2);

    for (int i = 0; i < NLk; i++) {
        const float* wqi = wq + (size_t)i * Dk * Dk;
        const float* wki = wk + (size_t)i * Dk * Dk;
        const float* wvi = wv + (size_t)i * Dk * Dk;
        const float* woi = wo + (size_t)i * Dk * Dk;
        const float* f1i = fw1 + (size_t)i * FFD * Dk;
        const float* f2i = fw2 + (size_t)i * Dk * FFD;

        rmsnorm_kernel<<<MR, 256>>>(X, norm1 + (size_t)i * Dk, XN);
        gemm_tf32<0><<<gqkv, 256>>>(XN, wqi, wki, wvi, nullptr, Q, K, V, Dk, Dk);
        rope2_kernel<<<grp, 256>>>(Q, K);
        attn_fa<<<ga, 128>>>(Q, K, V, mask, AO);
        gemm_tf32<1><<<gs, 256>>>(AO, woi, woi, woi, X, X, X, X, Dk, Dk);
        rmsnorm_kernel<<<MR, 256>>>(X, norm2 + (size_t)i * Dk, XN);
        gemm_tf32<2><<<gf1, 256>>>(XN, f1i, f1i, f1i, nullptr, F1, F1, F1, FFD, Dk);
        gemm_tf32<1><<<gs, 256>>>(F1, f2i, f2i, f2i, X, X, X, X, Dk, FFD);
    }

    rmsnorm_kernel<<<MR, 256>>>(X, fnorm, XN);
    cvt_kernel<<<(MR * Dk) / 256, 256>>>(XN, AO, MR * Dk);   // AO reused as tf32 XN
    gemm_lm<<<glm, 256>>>(AO, LW32, out, Vk, Dk);
    heads_kernel<<<1, 128>>>(XN, rw, rbias, mw, mbias, out + (size_t)Bk * Lk * Vk);
}

// round 5
// speedup vs baseline: 2.5914x; 1.0007x over previous
#include <cuda_runtime.h>
#include <math.h>
#include <stdint.h>

// Problem constants
#define Bk   4
#define Lk   2048
#define Dk   256
#define Hk   4
#define NLk  4
#define Vk   32000
#define DHk  64
#define MR   (Bk*Lk)      // 8192 rows
#define FFD  (4*Dk)       // 1024

// weight-split offsets (floats)
#define OFF_WQ  0
#define OFF_WK  (NLk*Dk*Dk)          // 262144
#define OFF_WV  (2*NLk*Dk*Dk)
#define OFF_WO  (3*NLk*Dk*Dk)
#define OFF_F1  (4*NLk*Dk*Dk)        // 1048576
#define OFF_F2  (4*NLk*Dk*Dk + NLk*FFD*Dk)
#define WTOT    (4*NLk*Dk*Dk + 2*NLk*FFD*Dk)   // 3145728

// ---------------- scratch ----------------
__device__ float g_X  [MR*Dk];
__device__ float g_XNh[MR*Dk];
__device__ float g_XNl[MR*Dk];
__device__ float g_Q  [MR*Dk];
__device__ float g_K  [MR*Dk];
__device__ float g_V  [MR*Dk];
__device__ float g_AOh[MR*Dk];
__device__ float g_AOl[MR*Dk];
__device__ float g_F1h[MR*FFD];
__device__ float g_F1l[MR*FFD];
__device__ float g_Wh [WTOT];
__device__ float g_Wl [WTOT];
__device__ float g_LW32[Vk*Dk];

// ---------------- helpers ----------------
__device__ __forceinline__ uint32_t cvt_tf32(float x) {
    uint32_t r;
    asm("cvt.rna.tf32.f32 %0, %1;" : "=r"(r) : "f"(x));
    return r;
}

__device__ __forceinline__ void mma_tf32(float& c0, float& c1, float& c2, float& c3,
                                         uint32_t a0, uint32_t a1, uint32_t a2, uint32_t a3,
                                         uint32_t b0, uint32_t b1)
{
    asm volatile("mma.sync.aligned.m16n8k8.row.col.f32.tf32.tf32.f32 "
                 "{%0,%1,%2,%3},{%4,%5,%6,%7},{%8,%9},{%0,%1,%2,%3};"
                 : "+f"(c0), "+f"(c1), "+f"(c2), "+f"(c3)
                 : "r"(a0), "r"(a1), "r"(a2), "r"(a3), "r"(b0), "r"(b1));
}

__device__ __forceinline__ void cp16(uint32_t smem, const void* gmem) {
    asm volatile("cp.async.ca.shared.global [%0], [%1], 16;\n" :: "r"(smem), "l"(gmem));
}
#define CP_COMMIT() asm volatile("cp.async.commit_group;\n" ::: "memory")
#define CP_WAIT1()  asm volatile("cp.async.wait_group 1;\n" ::: "memory")

// ---------------- embedding ----------------
__global__ void embed_kernel(const int* __restrict__ ids, const int* __restrict__ tts,
                             const float* __restrict__ te, const float* __restrict__ ye,
                             float* __restrict__ X)
{
    int i = blockIdx.x * 256 + threadIdx.x;
    int row = i >> 8;
    int d   = i & 255;
    X[i] = te[(size_t)ids[row] * Dk + d] + ye[(size_t)tts[row] * Dk + d];
}

// ---------------- tf32 convert / split ----------------
__global__ void cvt_kernel(const float* __restrict__ src, float* __restrict__ dst, int n)
{
    int i = blockIdx.x * 256 + threadIdx.x;
    if (i < n) dst[i] = __uint_as_float(cvt_tf32(src[i]));
}

__global__ void split_kernel(const float* __restrict__ src,
                             float* __restrict__ dh, float* __restrict__ dl, int n)
{
    int i = blockIdx.x * 256 + threadIdx.x;
    if (i < n) {
        float x = src[i];
        uint32_t h = cvt_tf32(x);
        dh[i] = __uint_as_float(h);
        dl[i] = __uint_as_float(cvt_tf32(x - __uint_as_float(h)));
    }
}

// ---------------- RMSNorm (emits hi/lo) ----------------
__global__ __launch_bounds__(256) void rmsnorm_kernel(const float* __restrict__ X,
                                                      const float* __restrict__ w,
                                                      float* __restrict__ Yh,
                                                      float* __restrict__ Yl)
{
    int r = blockIdx.x;
    int t = threadIdx.x;
    float v = X[(size_t)r * Dk + t];
    float s = v * v;
    #pragma unroll
    for (int o = 16; o > 0; o >>= 1) s += __shfl_down_sync(0xffffffffu, s, o);
    __shared__ float ws[8];
    __shared__ float tot;
    int lane = t & 31, wi = t >> 5;
    if (lane == 0) ws[wi] = s;
    __syncthreads();
    if (t == 0) {
        float a = 0.f;
        #pragma unroll
        for (int i = 0; i < 8; i++) a += ws[i];
        tot = a;
    }
    __syncthreads();
    float rs = rsqrtf(tot * (1.0f / Dk) + 1.1920929e-07f);
    float y = v * rs * w[t];
    uint32_t h = cvt_tf32(y);
    Yh[(size_t)r * Dk + t] = __uint_as_float(h);
    Yl[(size_t)r * Dk + t] = __uint_as_float(cvt_tf32(y - __uint_as_float(h)));
}

// ---------------- RoPE ----------------
__global__ void rope2_kernel(float* __restrict__ Q, float* __restrict__ K)
{
    float* P = blockIdx.y ? K : Q;
    int i   = blockIdx.x * 256 + threadIdx.x;
    int t   = i & 31;
    int h   = (i >> 5) & 3;
    int row = i >> 7;
    int pos = row & (Lk - 1);
    float inv = exp2f(-(float)t * (13.287712379549449f / 32.0f));
    float ang = (float)pos * inv;
    float sn, cs;
    sincosf(ang, &sn, &cs);
    size_t base = (size_t)row * Dk + h * DHk;
    float a = P[base + t];
    float b = P[base + t + 32];
    P[base + t]      = a * cs - b * sn;
    P[base + t + 32] = b * cs + a * sn;
}

// ---------------- tensor-core flash attention (emits hi/lo output) ----------------
#define APAD 68
__global__ __launch_bounds__(128) void attn_fa(const float* __restrict__ Q,
                                               const float* __restrict__ K,
                                               const float* __restrict__ V,
                                               const int*   __restrict__ mask,
                                               float* __restrict__ Oh,
                                               float* __restrict__ Ol)
{
    __shared__ uint32_t KP[64][APAD];
    __shared__ uint32_t Vs[64][APAD];
    __shared__ float    mkf[64];

    int b  = blockIdx.z, h = blockIdx.y;
    int q0 = blockIdx.x * 64;
    int tid = threadIdx.x;
    int lane = tid & 31, wid = tid >> 5;
    int gr = lane >> 2, gc = lane & 3;
    int wr = wid * 16;

    const int* mrow = mask + (size_t)b * Lk;

    #pragma unroll
    for (int it = 0; it < 8; it++) {
        int pos = tid + it * 128;
        int row = pos >> 4, d4 = pos & 15;
        float4 qv = *(const float4*)(Q + ((size_t)(b*Lk + q0 + row))*Dk + h*DHk + d4*4);
        uint4 u = { cvt_tf32(qv.x*0.125f), cvt_tf32(qv.y*0.125f),
                    cvt_tf32(qv.z*0.125f), cvt_tf32(qv.w*0.125f) };
        *(uint4*)&KP[row][d4*4] = u;
    }
    __syncthreads();
    uint32_t qa[8][4];
    #pragma unroll
    for (int kk = 0; kk < 8; kk++) {
        qa[kk][0] = KP[wr+gr  ][kk*8+gc];
        qa[kk][1] = KP[wr+gr+8][kk*8+gc];
        qa[kk][2] = KP[wr+gr  ][kk*8+gc+4];
        qa[kk][3] = KP[wr+gr+8][kk*8+gc+4];
    }

    float o[8][4];
    #pragma unroll
    for (int nt = 0; nt < 8; nt++)
        #pragma unroll
        for (int j = 0; j < 4; j++) o[nt][j] = 0.f;
    float m0 = -1e30f, m1 = -1e30f, l0 = 0.f, l1 = 0.f;
    int r0 = q0 + wr + gr, r1 = r0 + 8;

    int ntile = blockIdx.x + 1;
    for (int kt = 0; kt < ntile; kt++) {
        int key0 = kt * 64;
        __syncthreads();
        #pragma unroll
        for (int it = 0; it < 8; it++) {
            int pos = tid + it * 128;
            int key = pos >> 4, d4 = pos & 15;
            size_t gbase = ((size_t)(b*Lk + key0 + key))*Dk + h*DHk + d4*4;
            float4 kv = *(const float4*)(K + gbase);
            uint4 u = { cvt_tf32(kv.x), cvt_tf32(kv.y), cvt_tf32(kv.z), cvt_tf32(kv.w) };
            *(uint4*)&KP[key][d4*4] = u;
            float4 vv = *(const float4*)(V + gbase);
            Vs[d4*4+0][key] = cvt_tf32(vv.x);
            Vs[d4*4+1][key] = cvt_tf32(vv.y);
            Vs[d4*4+2][key] = cvt_tf32(vv.z);
            Vs[d4*4+3][key] = cvt_tf32(vv.w);
        }
        if (tid < 64) mkf[tid] = mrow[key0 + tid] ? 0.0f : -1e30f;
        __syncthreads();

        float s[8][4];
        #pragma unroll
        for (int nt = 0; nt < 8; nt++)
            #pragma unroll
            for (int j = 0; j < 4; j++) s[nt][j] = 0.f;
        #pragma unroll
        for (int kk = 0; kk < 8; kk++) {
            #pragma unroll
            for (int nt = 0; nt < 8; nt++) {
                uint32_t b0 = KP[nt*8+gr][kk*8+gc];
                uint32_t b1 = KP[nt*8+gr][kk*8+gc+4];
                mma_tf32(s[nt][0], s[nt][1], s[nt][2], s[nt][3],
                         qa[kk][0], qa[kk][1], qa[kk][2], qa[kk][3], b0, b1);
            }
        }

        bool last = (kt == ntile - 1);
        #pragma unroll
        for (int nt = 0; nt < 8; nt++) {
            float mk0 = mkf[nt*8+gc*2], mk1 = mkf[nt*8+gc*2+1];
            s[nt][0] += mk0; s[nt][1] += mk1;
            s[nt][2] += mk0; s[nt][3] += mk1;
            if (last) {
                int c = key0 + nt*8 + gc*2;
                if (c     > r0) s[nt][0] = -1e30f;
                if (c + 1 > r0) s[nt][1] = -1e30f;
                if (c     > r1) s[nt][2] = -1e30f;
                if (c + 1 > r1) s[nt][3] = -1e30f;
            }
        }

        float rm0 = -1e30f, rm1 = -1e30f;
        #pragma unroll
        for (int nt = 0; nt < 8; nt++) {
            rm0 = fmaxf(rm0, fmaxf(s[nt][0], s[nt][1]));
            rm1 = fmaxf(rm1, fmaxf(s[nt][2], s[nt][3]));
        }
        rm0 = fmaxf(rm0, __shfl_xor_sync(0xffffffffu, rm0, 1));
        rm0 = fmaxf(rm0, __shfl_xor_sync(0xffffffffu, rm0, 2));
        rm1 = fmaxf(rm1, __shfl_xor_sync(0xffffffffu, rm1, 1));
        rm1 = fmaxf(rm1, __shfl_xor_sync(0xffffffffu, rm1, 2));

        float mn0 = fmaxf(m0, rm0), mn1 = fmaxf(m1, rm1);
        float cor0 = __expf(m0 - mn0), cor1 = __expf(m1 - mn1);
        m0 = mn0; m1 = mn1;

        __syncthreads();

        float ps0 = 0.f, ps1 = 0.f;
        #pragma unroll
        for (int nt = 0; nt < 8; nt++) {
            float p00 = __expf(s[nt][0] - mn0);
            float p01 = __expf(s[nt][1] - mn0);
            float p10 = __expf(s[nt][2] - mn1);
            float p11 = __expf(s[nt][3] - mn1);
            ps0 += p00 + p01;
            ps1 += p10 + p11;
            KP[wr+gr  ][nt*8+gc*2  ] = cvt_tf32(p00);
            KP[wr+gr  ][nt*8+gc*2+1] = cvt_tf32(p01);
            KP[wr+gr+8][nt*8+gc*2  ] = cvt_tf32(p10);
            KP[wr+gr+8][nt*8+gc*2+1] = cvt_tf32(p11);
        }
        ps0 += __shfl_xor_sync(0xffffffffu, ps0, 1);
        ps0 += __shfl_xor_sync(0xffffffffu, ps0, 2);
        ps1 += __shfl_xor_sync(0xffffffffu, ps1, 1);
        ps1 += __shfl_xor_sync(0xffffffffu, ps1, 2);
        l0 = l0 * cor0 + ps0;
        l1 = l1 * cor1 + ps1;
        #pragma unroll
        for (int nt = 0; nt < 8; nt++) {
            o[nt][0] *= cor0; o[nt][1] *= cor0;
            o[nt][2] *= cor1; o[nt][3] *= cor1;
        }
        __syncwarp();

        #pragma unroll
        for (int kk = 0; kk < 8; kk++) {
            uint32_t pa0 = KP[wr+gr  ][kk*8+gc];
            uint32_t pa1 = KP[wr+gr+8][kk*8+gc];
            uint32_t pa2 = KP[wr+gr  ][kk*8+gc+4];
            uint32_t pa3 = KP[wr+gr+8][kk*8+gc+4];
            #pragma unroll
            for (int nt = 0; nt < 8; nt++) {
                uint32_t vb0 = Vs[nt*8+gr][kk*8+gc];
                uint32_t vb1 = Vs[nt*8+gr][kk*8+gc+4];
                mma_tf32(o[nt][0], o[nt][1], o[nt][2], o[nt][3],
                         pa0, pa1, pa2, pa3, vb0, vb1);
            }
        }
    }

    float inv0 = 1.0f / l0, inv1 = 1.0f / l1;
    #pragma unroll
    for (int nt = 0; nt < 8; nt++) {
        int d = nt*8 + gc*2;
        size_t i0 = ((size_t)(b*Lk + r0))*Dk + h*DHk + d;
        size_t i1 = ((size_t)(b*Lk + r1))*Dk + h*DHk + d;
        float v00 = o[nt][0]*inv0, v01 = o[nt][1]*inv0;
        float v10 = o[nt][2]*inv1, v11 = o[nt][3]*inv1;
        uint32_t h00 = cvt_tf32(v00), h01 = cvt_tf32(v01);
        uint32_t h10 = cvt_tf32(v10), h11 = cvt_tf32(v11);
        float2 a; a.x = __uint_as_float(h00); a.y = __uint_as_float(h01);
        float2 c; c.x = __uint_as_float(h10); c.y = __uint_as_float(h11);
        *(float2*)(Oh + i0) = a;
        *(float2*)(Oh + i1) = c;
        float2 al; al.x = __uint_as_float(cvt_tf32(v00 - a.x));
        al.y = __uint_as_float(cvt_tf32(v01 - a.y));
        float2 cl; cl.x = __uint_as_float(cvt_tf32(v10 - c.x));
        cl.y = __uint_as_float(cvt_tf32(v11 - c.y));
        *(float2*)(Ol + i0) = al;
        *(float2*)(Ol + i1) = cl;
    }
}

// ================= split-tf32 GEMM, pre-split operands, cp.async 2-stage ===========
// C[m,n] = sum_k A[m,k]*B[n,k] (3-pass hh+hl+lh). EPI: 0 store, 1 +R, 2 silu->(Ch,Cl)
// dynamic smem: 2 stages x {Ah,Al,Bh,Bl} each 128x20 words.
#define BUFW 2560            // 128*20 words per buffer
#define STGW 10240           // 4 buffers
template<int EPI>
__global__ __launch_bounds__(256, 2) void gemm_split(const float* __restrict__ Ah_,
                                                     const float* __restrict__ Al_,
                                                     const float* __restrict__ Bh0,
                                                     const float* __restrict__ Bl0,
                                                     const float* __restrict__ Bh1,
                                                     const float* __restrict__ Bl1,
                                                     const float* __restrict__ Bh2,
                                                     const float* __restrict__ Bl2,
                                                     const float* __restrict__ R,
                                                     float* __restrict__ C0,
                                                     float* __restrict__ C1,
                                                     float* __restrict__ C2,
                                                     float* __restrict__ Cl,
                                                     int N, int K)
{
    const float* Bh = (blockIdx.z == 0) ? Bh0 : (blockIdx.z == 1 ? Bh1 : Bh2);
    const float* Bl = (blockIdx.z == 0) ? Bl0 : (blockIdx.z == 1 ? Bl1 : Bl2);
    float*       C  = (blockIdx.z == 0) ? C0  : (blockIdx.z == 1 ? C1  : C2);

    extern __shared__ uint32_t dsm[];

    int t    = threadIdx.x;
    int lane = t & 31;
    int wid  = t >> 5;
    int bm0  = blockIdx.y * 128;
    int bn0  = blockIdx.x * 128;
    int wm0  = (wid & 3) * 32;
    int wn0  = (wid >> 2) * 64;
    int gr   = lane >> 2;
    int gc   = lane & 3;

    int lrow = t >> 1;
    int lk   = (t & 1) * 8;

    const float* pAh = Ah_ + (size_t)(bm0 + lrow) * K + lk;
    const float* pAl = Al_ + (size_t)(bm0 + lrow) * K + lk;
    const float* pBh = Bh  + (size_t)(bn0 + lrow) * K + lk;
    const float* pBl = Bl  + (size_t)(bn0 + lrow) * K + lk;

    uint32_t sbase = (uint32_t)__cvta_generic_to_shared(dsm);
    uint32_t soff  = (lrow * 20 + lk) * 4;

    float c[2][8][4];
    #pragma unroll
    for (int i = 0; i < 2; i++)
        #pragma unroll
        for (int j = 0; j < 8; j++)
            #pragma unroll
            for (int q = 0; q < 4; q++) c[i][j][q] = 0.f;

    // prologue: stages 0,1
    #pragma unroll
    for (int s = 0; s < 2; s++) {
        int ko = s * 16;
        uint32_t sb = sbase + s * STGW * 4 + soff;
        cp16(sb,                 pAh + ko); cp16(sb + 16,                 pAh + ko + 4);
        cp16(sb + BUFW*4,        pAl + ko); cp16(sb + BUFW*4 + 16,        pAl + ko + 4);
        cp16(sb + 2*BUFW*4,      pBh + ko); cp16(sb + 2*BUFW*4 + 16,      pBh + ko + 4);
        cp16(sb + 3*BUFW*4,      pBl + ko); cp16(sb + 3*BUFW*4 + 16,      pBl + ko + 4);
        CP_COMMIT();
    }

    const int niter = K / 16;
    for (int it = 0; it < niter; it++) {
        CP_WAIT1();
        __syncthreads();
        int cur = it & 1;
        const uint32_t* sAh = dsm + cur * STGW;
        const uint32_t* sAl = sAh + BUFW;
        const uint32_t* sBh = sAh + 2 * BUFW;
        const uint32_t* sBl = sAh + 3 * BUFW;

        #pragma unroll
        for (int kk = 0; kk < 16; kk += 8) {
            uint32_t afh[2][4], afl[2][4];
            #pragma unroll
            for (int mt = 0; mt < 2; mt++) {
                int rr = (wm0 + mt * 16 + gr) * 20 + kk + gc;
                afh[mt][0] = sAh[rr];
                afh[mt][1] = sAh[rr + 8 * 20];
                afh[mt][2] = sAh[rr + 4];
                afh[mt][3] = sAh[rr + 8 * 20 + 4];
                afl[mt][0] = sAl[rr];
                afl[mt][1] = sAl[rr + 8 * 20];
                afl[mt][2] = sAl[rr + 4];
                afl[mt][3] = sAl[rr + 8 * 20 + 4];
            }
            #pragma unroll
            for (int nt = 0; nt < 8; nt++) {
                int nn = (wn0 + nt * 8 + gr) * 20 + kk + gc;
                uint32_t bh0 = sBh[nn], bh1 = sBh[nn + 4];
                uint32_t bl0 = sBl[nn], bl1 = sBl[nn + 4];
                #pragma unroll
                for (int mt = 0; mt < 2; mt++) {
                    mma_tf32(c[mt][nt][0], c[mt][nt][1], c[mt][nt][2], c[mt][nt][3],
                             afh[mt][0], afh[mt][1], afh[mt][2], afh[mt][3], bh0, bh1);
                    mma_tf32(c[mt][nt][0], c[mt][nt][1], c[mt][nt][2], c[mt][nt][3],
                             afh[mt][0], afh[mt][1], afh[mt][2], afh[mt][3], bl0, bl1);
                    mma_tf32(c[mt][nt][0], c[mt][nt][1], c[mt][nt][2], c[mt][nt][3],
                             afl[mt][0], afl[mt][1], afl[mt][2], afl[mt][3], bh0, bh1);
                }
            }
        }

        __syncthreads();
        if (it + 2 < niter) {
            int ko = (it + 2) * 16;
            uint32_t sb = sbase + cur * STGW * 4 + soff;
            cp16(sb,                 pAh + ko); cp16(sb + 16,                 pAh + ko + 4);
            cp16(sb + BUFW*4,        pAl + ko); cp16(sb + BUFW*4 + 16,        pAl + ko + 4);
            cp16(sb + 2*BUFW*4,      pBh + ko); cp16(sb + 2*BUFW*4 + 16,      pBh + ko + 4);
            cp16(sb + 3*BUFW*4,      pBl + ko); cp16(sb + 3*BUFW*4 + 16,      pBl + ko + 4);
        }
        CP_COMMIT();
    }

    #pragma unroll
    for (int mt = 0; mt < 2; mt++) {
        #pragma unroll
        for (int nt = 0; nt < 8; nt++) {
            int row = bm0 + wm0 + mt * 16 + gr;
            int col = bn0 + wn0 + nt * 8 + gc * 2;
            #pragma unroll
            for (int half = 0; half < 2; half++) {
                int r = row + half * 8;
                float vx = c[mt][nt][half * 2 + 0];
                float vy = c[mt][nt][half * 2 + 1];
                size_t idx = (size_t)r * N + col;
                if (EPI == 1) {
                    float2 rr = *(const float2*)(R + idx);
                    vx += rr.x; vy += rr.y;
                    float2 ov; ov.x = vx; ov.y = vy;
                    *(float2*)(C + idx) = ov;
                } else if (EPI == 2) {
                    vx = vx / (1.f + __expf(-vx));
                    vy = vy / (1.f + __expf(-vy));
                    uint32_t hx = cvt_tf32(vx), hy = cvt_tf32(vy);
                    float2 oh; oh.x = __uint_as_float(hx); oh.y = __uint_as_float(hy);
                    *(float2*)(C + idx) = oh;
                    float2 ol;
                    ol.x = __uint_as_float(cvt_tf32(vx - oh.x));
                    ol.y = __uint_as_float(cvt_tf32(vy - oh.y));
                    *(float2*)(Cl + idx) = ol;
                } else {
                    float2 ov; ov.x = vx; ov.y = vy;
                    *(float2*)(C + idx) = ov;
                }
            }
        }
    }
}

// ================= LM head GEMM: pre-converted tf32, cp.async 2-stage =================
__global__ __launch_bounds__(256, 2) void gemm_lm(const float* __restrict__ A,
                                                  const float* __restrict__ B,
                                                  float* __restrict__ C,
                                                  int N, int K)
{
    __shared__ uint32_t sA[2][128][20];
    __shared__ uint32_t sB[2][128][20];

    int t    = threadIdx.x;
    int lane = t & 31;
    int wid  = t >> 5;
    int bm0  = blockIdx.y * 128;
    int bn0  = blockIdx.x * 128;
    int wm0  = (wid & 3) * 32;
    int wn0  = (wid >> 2) * 64;

    int lrow = t >> 1;
    int lk   = (t & 1) * 8;

    const float* Ap = A + (size_t)(bm0 + lrow) * K + lk;
    const float* Bp = B + (size_t)(bn0 + lrow) * K + lk;

    float c[2][8][4];
    #pragma unroll
    for (int i = 0; i < 2; i++)
        #pragma unroll
        for (int j = 0; j < 8; j++)
            #pragma unroll
            for (int q = 0; q < 4; q++) c[i][j][q] = 0.f;

    int gr = lane >> 2;
    int gc = lane & 3;

    uint32_t saA0 = (uint32_t)__cvta_generic_to_shared(&sA[0][lrow][lk]);
    uint32_t saB0 = (uint32_t)__cvta_generic_to_shared(&sB[0][lrow][lk]);
    const uint32_t stageStride = 128 * 20 * 4;

    #pragma unroll
    for (int s = 0; s < 2; s++) {
        int ko = s * 16;
        cp16(saA0 + s * stageStride,      Ap + ko);
        cp16(saA0 + s * stageStride + 16, Ap + ko + 4);
        cp16(saB0 + s * stageStride,      Bp + ko);
        cp16(saB0 + s * stageStride + 16, Bp + ko + 4);
        CP_COMMIT();
    }

    const int niter = K / 16;
    for (int it = 0; it < niter; it++) {
        CP_WAIT1();
        __syncthreads();
        int cur = it & 1;

        #pragma unroll
        for (int kk = 0; kk < 16; kk += 8) {
            uint32_t afh[2][4], bfh[8][2];
            #pragma unroll
            for (int mt = 0; mt < 2; mt++) {
                int rr = wm0 + mt * 16 + gr;
                afh[mt][0] = sA[cur][rr][kk + gc];
                afh[mt][1] = sA[cur][rr + 8][kk + gc];
                afh[mt][2] = sA[cur][rr][kk + 4 + gc];
                afh[mt][3] = sA[cur][rr + 8][kk + 4 + gc];
            }
            #pragma unroll
            for (int nt = 0; nt < 8; nt++) {
                int n0 = wn0 + nt * 8 + gr;
                bfh[nt][0] = sB[cur][n0][kk + gc];
                bfh[nt][1] = sB[cur][n0][kk + 4 + gc];
            }
            #pragma unroll
            for (int mt = 0; mt < 2; mt++)
                #pragma unroll
                for (int nt = 0; nt < 8; nt++)
                    mma_tf32(c[mt][nt][0], c[mt][nt][1], c[mt][nt][2], c[mt][nt][3],
                             afh[mt][0], afh[mt][1], afh[mt][2], afh[mt][3],
                             bfh[nt][0], bfh[nt][1]);
        }

        __syncthreads();
        if (it + 2 < niter) {
            int ko = (it + 2) * 16;
            cp16(saA0 + cur * stageStride,      Ap + ko);
            cp16(saA0 + cur * stageStride + 16, Ap + ko + 4);
            cp16(saB0 + cur * stageStride,      Bp + ko);
            cp16(saB0 + cur * stageStride + 16, Bp + ko + 4);
        }
        CP_COMMIT();
    }

    #pragma unroll
    for (int mt = 0; mt < 2; mt++) {
        #pragma unroll
        for (int nt = 0; nt < 8; nt++) {
            int row = bm0 + wm0 + mt * 16 + gr;
            int col = bn0 + wn0 + nt * 8 + gc * 2;
            #pragma unroll
            for (int half = 0; half < 2; half++) {
                int r = row + half * 8;
                float2 ov;
                ov.x = c[mt][nt][half * 2 + 0];
                ov.y = c[mt][nt][half * 2 + 1];
                *(float2*)(C + (size_t)r * N + col) = ov;
            }
        }
    }
}

// ---------------- classifier heads (does its own final norm of X row 0) ----------------
__global__ void heads_kernel(const float* __restrict__ X,
                             const float* __restrict__ fnw,
                             const float* __restrict__ rw, const float* __restrict__ rb,
                             const float* __restrict__ mw, const float* __restrict__ mb,
                             float* __restrict__ out)
{
    int w = threadIdx.x >> 5, lane = threadIdx.x & 31;
    if (w >= Bk) return;
    const float* x = X + (size_t)w * Lk * Dk;
    float ss = 0.f;
    for (int d = lane; d < Dk; d += 32) { float v = x[d]; ss += v * v; }
    #pragma unroll
    for (int o = 16; o > 0; o >>= 1) ss += __shfl_xor_sync(0xffffffffu, ss, o);
    float rs = rsqrtf(ss * (1.0f / Dk) + 1.1920929e-07f);
    float sr = 0.f, sm = 0.f;
    for (int d = lane; d < Dk; d += 32) {
        float xn = x[d] * rs * fnw[d];
        sr += xn * rw[d];
        sm += xn * mw[d];
    }
    #pragma unroll
    for (int o = 16; o > 0; o >>= 1) {
        sr += __shfl_down_sync(0xffffffffu, sr, o);
        sm += __shfl_down_sync(0xffffffffu, sm, o);
    }
    if (lane == 0) {
        out[w]      = sr + rb[0];
        out[Bk + w] = sm + mb[0];
    }
}

// ---------------- launch ----------------
extern "C" void kernel_launch(void* const* d_in, const int* in_sizes, int n_in,
                              void* d_out, int out_size)
{
    const int*   ids      = (const int*)d_in[0];
    const int*   tts      = (const int*)d_in[1];
    const int*   mask     = (const int*)d_in[2];
    const float* tok_emb  = (const float*)d_in[3];
    const float* type_emb = (const float*)d_in[4];
    const float* norm1    = (const float*)d_in[5];
    const float* wq       = (const float*)d_in[6];
    const float* wk       = (const float*)d_in[7];
    const float* wv       = (const float*)d_in[8];
    const float* wo       = (const float*)d_in[9];
    const float* norm2    = (const float*)d_in[10];
    const float* fw1      = (const float*)d_in[11];
    const float* fw2      = (const float*)d_in[12];
    const float* fnorm    = (const float*)d_in[13];
    const float* lmw      = (const float*)d_in[14];
    const float* rw       = (const float*)d_in[15];
    const float* rbias    = (const float*)d_in[16];
    const float* mw       = (const float*)d_in[17];
    const float* mbias    = (const float*)d_in[18];
    float* out = (float*)d_out;

    float *X, *XNh, *XNl, *Q, *K, *V, *AOh, *AOl, *F1h, *F1l, *Wh, *Wl, *LW32;
    cudaGetSymbolAddress((void**)&X,   g_X);
    cudaGetSymbolAddress((void**)&XNh, g_XNh);
    cudaGetSymbolAddress((void**)&XNl, g_XNl);
    cudaGetSymbolAddress((void**)&Q,   g_Q);
    cudaGetSymbolAddress((void**)&K,   g_K);
    cudaGetSymbolAddress((void**)&V,   g_V);
    cudaGetSymbolAddress((void**)&AOh, g_AOh);
    cudaGetSymbolAddress((void**)&AOl, g_AOl);
    cudaGetSymbolAddress((void**)&F1h, g_F1h);
    cudaGetSymbolAddress((void**)&F1l, g_F1l);
    cudaGetSymbolAddress((void**)&Wh,  g_Wh);
    cudaGetSymbolAddress((void**)&Wl,  g_Wl);
    cudaGetSymbolAddress((void**)&LW32, g_LW32);

    const int dynSmem = STGW * 2 * 4;   // 81920 bytes
    cudaFuncSetAttribute(gemm_split<0>, cudaFuncAttributeMaxDynamicSharedMemorySize, dynSmem);
    cudaFuncSetAttribute(gemm_split<1>, cudaFuncAttributeMaxDynamicSharedMemorySize, dynSmem);
    cudaFuncSetAttribute(gemm_split<2>, cudaFuncAttributeMaxDynamicSharedMemorySize, dynSmem);

    embed_kernel<<<(MR * Dk) / 256, 256>>>(ids, tts, tok_emb, type_emb, X);
    cvt_kernel<<<(Vk * Dk) / 256, 256>>>(lmw, LW32, Vk * Dk);

    // pre-split all layer weights
    split_kernel<<<(NLk*Dk*Dk) / 256, 256>>>(wq,  Wh + OFF_WQ, Wl + OFF_WQ, NLk*Dk*Dk);
    split_kernel<<<(NLk*Dk*Dk) / 256, 256>>>(wk,  Wh + OFF_WK, Wl + OFF_WK, NLk*Dk*Dk);
    split_kernel<<<(NLk*Dk*Dk) / 256, 256>>>(wv,  Wh + OFF_WV, Wl + OFF_WV, NLk*Dk*Dk);
    split_kernel<<<(NLk*Dk*Dk) / 256, 256>>>(wo,  Wh + OFF_WO, Wl + OFF_WO, NLk*Dk*Dk);
    split_kernel<<<(NLk*FFD*Dk) / 256, 256>>>(fw1, Wh + OFF_F1, Wl + OFF_F1, NLk*FFD*Dk);
    split_kernel<<<(NLk*FFD*Dk) / 256, 256>>>(fw2, Wh + OFF_F2, Wl + OFF_F2, NLk*FFD*Dk);

    dim3 gqkv(Dk  / 128, MR / 128, 3);
    dim3 gs  (Dk  / 128, MR / 128, 1);
    dim3 gf1 (FFD / 128, MR / 128, 1);
    dim3 glm (Vk  / 128, MR / 128);
    dim3 ga  (Lk / 64, Hk, Bk);
    dim3 grp ((MR * Hk * 32) / 256, 2);

    for (int i = 0; i < NLk; i++) {
        size_t od = (size_t)i * Dk * Dk;
        size_t of = (size_t)i * FFD * Dk;
        const float *qh = Wh + OFF_WQ + od, *ql = Wl + OFF_WQ + od;
        const float *kh = Wh + OFF_WK + od, *kl = Wl + OFF_WK + od;
        const float *vh = Wh + OFF_WV + od, *vl = Wl + OFF_WV + od;
        const float *oh = Wh + OFF_WO + od, *ol = Wl + OFF_WO + od;
        const float *f1h = Wh + OFF_F1 + of, *f1l = Wl + OFF_F1 + of;
        const float *f2h = Wh + OFF_F2 + of, *f2l = Wl + OFF_F2 + of;

        rmsnorm_kernel<<<MR, 256>>>(X, norm1 + (size_t)i * Dk, XNh, XNl);
        gemm_split<0><<<gqkv, 256, dynSmem>>>(XNh, XNl, qh, ql, kh, kl, vh, vl,
                                              nullptr, Q, K, V, nullptr, Dk, Dk);
        rope2_kernel<<<grp, 256>>>(Q, K);
        attn_fa<<<ga, 128>>>(Q, K, V, mask, AOh, AOl);
        gemm_split<1><<<gs, 256, dynSmem>>>(AOh, AOl, oh, ol, oh, ol, oh, ol,
                                            X, X, X, X, nullptr, Dk, Dk);
        rmsnorm_kernel<<<MR, 256>>>(X, norm2 + (size_t)i * Dk, XNh, XNl);
        gemm_split<2><<<gf1, 256, dynSmem>>>(XNh, XNl, f1h, f1l, f1h, f1l, f1h, f1l,
                                             nullptr, F1h, F1h, F1h, F1l, FFD, Dk);
        gemm_split<1><<<gs, 256, dynSmem>>>(F1h, F1l, f2h, f2l, f2h, f2l, f2h, f2l,
                                            X, X, X, X, nullptr, Dk, FFD);
    }

    rmsnorm_kernel<<<MR, 256>>>(X, fnorm, XNh, XNl);
    gemm_lm<<<glm, 256>>>(XNh, LW32, out, Vk, Dk);
    heads_kernel<<<1, 128>>>(X, fnorm, rw, rbias, mw, mbias, out + (size_t)Bk * Lk * Vk);
}

// round 8
// speedup vs baseline: 3.1563x; 1.2180x over previous
#include <cuda_runtime.h>
#include <cuda_bf16.h>
#include <math.h>
#include <stdint.h>

// Problem constants
#define Bk   4
#define Lk   2048
#define Dk   256
#define Hk   4
#define NLk  4
#define Vk   32000
#define DHk  64
#define MR   (Bk*Lk)      // 8192 rows
#define FFD  (4*Dk)       // 1024

// weight-split offsets (elements)
#define OFF_WQ  0
#define OFF_WK  (NLk*Dk*Dk)
#define OFF_WV  (2*NLk*Dk*Dk)
#define OFF_WO  (3*NLk*Dk*Dk)
#define OFF_F1  (4*NLk*Dk*Dk)
#define OFF_F2  (4*NLk*Dk*Dk + NLk*FFD*Dk)
#define WTOT    (4*NLk*Dk*Dk + 2*NLk*FFD*Dk)

// ---------------- scratch ----------------
__device__ float g_X   [MR*Dk];
__device__ float g_XN32[MR*Dk];         // tf32-rounded fp32 for LM head
__device__ float g_Q   [MR*Dk];
__device__ float g_K   [MR*Dk];
__device__ float g_V   [MR*Dk];
__device__ __nv_bfloat16 g_XNh[MR*Dk];
__device__ __nv_bfloat16 g_XNl[MR*Dk];
__device__ __nv_bfloat16 g_AOh[MR*Dk];
__device__ __nv_bfloat16 g_AOl[MR*Dk];
__device__ __nv_bfloat16 g_F1h[MR*FFD];
__device__ __nv_bfloat16 g_F1l[MR*FFD];
__device__ __nv_bfloat16 g_Wh [WTOT];
__device__ __nv_bfloat16 g_Wl [WTOT];
__device__ float g_LW32[Vk*Dk];

// ---------------- helpers ----------------
__device__ __forceinline__ uint32_t cvt_tf32(float x) {
    uint32_t r;
    asm("cvt.rna.tf32.f32 %0, %1;" : "=r"(r) : "f"(x));
    return r;
}

__device__ __forceinline__ void mma_tf32(float& c0, float& c1, float& c2, float& c3,
                                         uint32_t a0, uint32_t a1, uint32_t a2, uint32_t a3,
                                         uint32_t b0, uint32_t b1)
{
    asm volatile("mma.sync.aligned.m16n8k8.row.col.f32.tf32.tf32.f32 "
                 "{%0,%1,%2,%3},{%4,%5,%6,%7},{%8,%9},{%0,%1,%2,%3};"
                 : "+f"(c0), "+f"(c1), "+f"(c2), "+f"(c3)
                 : "r"(a0), "r"(a1), "r"(a2), "r"(a3), "r"(b0), "r"(b1));
}

__device__ __forceinline__ void mma_bf16(float& c0, float& c1, float& c2, float& c3,
                                         uint32_t a0, uint32_t a1, uint32_t a2, uint32_t a3,
                                         uint32_t b0, uint32_t b1)
{
    asm volatile("mma.sync.aligned.m16n8k16.row.col.f32.bf16.bf16.f32 "
                 "{%0,%1,%2,%3},{%4,%5,%6,%7},{%8,%9},{%0,%1,%2,%3};"
                 : "+f"(c0), "+f"(c1), "+f"(c2), "+f"(c3)
                 : "r"(a0), "r"(a1), "r"(a2), "r"(a3), "r"(b0), "r"(b1));
}

__device__ __forceinline__ void cp16(uint32_t smem, const void* gmem) {
    asm volatile("cp.async.ca.shared.global [%0], [%1], 16;\n" :: "r"(smem), "l"(gmem));
}
#define CP_COMMIT() asm volatile("cp.async.commit_group;\n" ::: "memory")
#define CP_WAIT1()  asm volatile("cp.async.wait_group 1;\n" ::: "memory")

__device__ __forceinline__ void bf16_split(float v, __nv_bfloat16& h, __nv_bfloat16& l) {
    h = __float2bfloat16_rn(v);
    l = __float2bfloat16_rn(v - __bfloat162float(h));
}

// ---------------- embedding ----------------
__global__ void embed_kernel(const int* __restrict__ ids, const int* __restrict__ tts,
                             const float* __restrict__ te, const float* __restrict__ ye,
                             float* __restrict__ X)
{
    int i = blockIdx.x * 256 + threadIdx.x;
    int row = i >> 8;
    int d   = i & 255;
    X[i] = te[(size_t)ids[row] * Dk + d] + ye[(size_t)tts[row] * Dk + d];
}

// ---------------- converts ----------------
__global__ void cvt_kernel(const float* __restrict__ src, float* __restrict__ dst, int n)
{
    int i = blockIdx.x * 256 + threadIdx.x;
    if (i < n) dst[i] = __uint_as_float(cvt_tf32(src[i]));
}

__global__ void split_bf16_kernel(const float* __restrict__ src,
                                  __nv_bfloat16* __restrict__ dh,
                                  __nv_bfloat16* __restrict__ dl, int n)
{
    int i = blockIdx.x * 256 + threadIdx.x;
    if (i < n) {
        __nv_bfloat16 h, l;
        bf16_split(src[i], h, l);
        dh[i] = h; dl[i] = l;
    }
}

// ---------------- RMSNorm -> bf16 hi/lo ----------------
__global__ __launch_bounds__(256) void rmsnorm_kernel(const float* __restrict__ X,
                                                      const float* __restrict__ w,
                                                      __nv_bfloat16* __restrict__ Yh,
                                                      __nv_bfloat16* __restrict__ Yl)
{
    int r = blockIdx.x;
    int t = threadIdx.x;
    float v = X[(size_t)r * Dk + t];
    float s = v * v;
    #pragma unroll
    for (int o = 16; o > 0; o >>= 1) s += __shfl_down_sync(0xffffffffu, s, o);
    __shared__ float ws[8];
    __shared__ float tot;
    int lane = t & 31, wi = t >> 5;
    if (lane == 0) ws[wi] = s;
    __syncthreads();
    if (t == 0) {
        float a = 0.f;
        #pragma unroll
        for (int i = 0; i < 8; i++) a += ws[i];
        tot = a;
    }
    __syncthreads();
    float rs = rsqrtf(tot * (1.0f / Dk) + 1.1920929e-07f);
    float y = v * rs * w[t];
    __nv_bfloat16 h, l;
    bf16_split(y, h, l);
    Yh[(size_t)r * Dk + t] = h;
    Yl[(size_t)r * Dk + t] = l;
}

// ---------------- final RMSNorm -> tf32-rounded fp32 (LM head input) ----------------
__global__ __launch_bounds__(256) void rmsnorm_tf32_kernel(const float* __restrict__ X,
                                                           const float* __restrict__ w,
                                                           float* __restrict__ Y)
{
    int r = blockIdx.x;
    int t = threadIdx.x;
    float v = X[(size_t)r * Dk + t];
    float s = v * v;
    #pragma unroll
    for (int o = 16; o > 0; o >>= 1) s += __shfl_down_sync(0xffffffffu, s, o);
    __shared__ float ws[8];
    __shared__ float tot;
    int lane = t & 31, wi = t >> 5;
    if (lane == 0) ws[wi] = s;
    __syncthreads();
    if (t == 0) {
        float a = 0.f;
        #pragma unroll
        for (int i = 0; i < 8; i++) a += ws[i];
        tot = a;
    }
    __syncthreads();
    float rs = rsqrtf(tot * (1.0f / Dk) + 1.1920929e-07f);
    Y[(size_t)r * Dk + t] = __uint_as_float(cvt_tf32(v * rs * w[t]));
}

// ---------------- RoPE ----------------
__global__ void rope2_kernel(float* __restrict__ Q, float* __restrict__ K)
{
    float* P = blockIdx.y ? K : Q;
    int i   = blockIdx.x * 256 + threadIdx.x;
    int t   = i & 31;
    int h   = (i >> 5) & 3;
    int row = i >> 7;
    int pos = row & (Lk - 1);
    float inv = exp2f(-(float)t * (13.287712379549449f / 32.0f));
    float ang = (float)pos * inv;
    float sn, cs;
    sincosf(ang, &sn, &cs);
    size_t base = (size_t)row * Dk + h * DHk;
    float a = P[base + t];
    float b = P[base + t + 32];
    P[base + t]      = a * cs - b * sn;
    P[base + t + 32] = b * cs + a * sn;
}

// ---------------- tensor-core flash attention (tf32), bf16 hi/lo output ----------------
#define APAD 68
__global__ __launch_bounds__(128) void attn_fa(const float* __restrict__ Q,
                                               const float* __restrict__ K,
                                               const float* __restrict__ V,
                                               const int*   __restrict__ mask,
                                               __nv_bfloat16* __restrict__ Oh,
                                               __nv_bfloat16* __restrict__ Ol)
{
    __shared__ uint32_t KP[64][APAD];
    __shared__ uint32_t Vs[64][APAD];
    __shared__ float    mkf[64];

    int b  = blockIdx.z, h = blockIdx.y;
    int q0 = blockIdx.x * 64;
    int tid = threadIdx.x;
    int lane = tid & 31, wid = tid >> 5;
    int gr = lane >> 2, gc = lane & 3;
    int wr = wid * 16;

    const int* mrow = mask + (size_t)b * Lk;

    #pragma unroll
    for (int it = 0; it < 8; it++) {
        int pos = tid + it * 128;
        int row = pos >> 4, d4 = pos & 15;
        float4 qv = *(const float4*)(Q + ((size_t)(b*Lk + q0 + row))*Dk + h*DHk + d4*4);
        uint4 u = { cvt_tf32(qv.x*0.125f), cvt_tf32(qv.y*0.125f),
                    cvt_tf32(qv.z*0.125f), cvt_tf32(qv.w*0.125f) };
        *(uint4*)&KP[row][d4*4] = u;
    }
    __syncthreads();
    uint32_t qa[8][4];
    #pragma unroll
    for (int kk = 0; kk < 8; kk++) {
        qa[kk][0] = KP[wr+gr  ][kk*8+gc];
        qa[kk][1] = KP[wr+gr+8][kk*8+gc];
        qa[kk][2] = KP[wr+gr  ][kk*8+gc+4];
        qa[kk][3] = KP[wr+gr+8][kk*8+gc+4];
    }

    float o[8][4];
    #pragma unroll
    for (int nt = 0; nt < 8; nt++)
        #pragma unroll
        for (int j = 0; j < 4; j++) o[nt][j] = 0.f;
    float m0 = -1e30f, m1 = -1e30f, l0 = 0.f, l1 = 0.f;
    int r0 = q0 + wr + gr, r1 = r0 + 8;

    int ntile = blockIdx.x + 1;
    for (int kt = 0; kt < ntile; kt++) {
        int key0 = kt * 64;
        __syncthreads();
        #pragma unroll
        for (int it = 0; it < 8; it++) {
            int pos = tid + it * 128;
            int key = pos >> 4, d4 = pos & 15;
            size_t gbase = ((size_t)(b*Lk + key0 + key))*Dk + h*DHk + d4*4;
            float4 kv = *(const float4*)(K + gbase);
            uint4 u = { cvt_tf32(kv.x), cvt_tf32(kv.y), cvt_tf32(kv.z), cvt_tf32(kv.w) };
            *(uint4*)&KP[key][d4*4] = u;
            float4 vv = *(const float4*)(V + gbase);
            Vs[d4*4+0][key] = cvt_tf32(vv.x);
            Vs[d4*4+1][key] = cvt_tf32(vv.y);
            Vs[d4*4+2][key] = cvt_tf32(vv.z);
            Vs[d4*4+3][key] = cvt_tf32(vv.w);
        }
        if (tid < 64) mkf[tid] = mrow[key0 + tid] ? 0.0f : -1e30f;
        __syncthreads();

        float s[8][4];
        #pragma unroll
        for (int nt = 0; nt < 8; nt++)
            #pragma unroll
            for (int j = 0; j < 4; j++) s[nt][j] = 0.f;
        #pragma unroll
        for (int kk = 0; kk < 8; kk++) {
            #pragma unroll
            for (int nt = 0; nt < 8; nt++) {
                uint32_t b0 = KP[nt*8+gr][kk*8+gc];
                uint32_t b1 = KP[nt*8+gr][kk*8+gc+4];
                mma_tf32(s[nt][0], s[nt][1], s[nt][2], s[nt][3],
                         qa[kk][0], qa[kk][1], qa[kk][2], qa[kk][3], b0, b1);
            }
        }

        bool last = (kt == ntile - 1);
        #pragma unroll
        for (int nt = 0; nt < 8; nt++) {
            float mk0 = mkf[nt*8+gc*2], mk1 = mkf[nt*8+gc*2+1];
            s[nt][0] += mk0; s[nt][1] += mk1;
            s[nt][2] += mk0; s[nt][3] += mk1;
            if (last) {
                int c = key0 + nt*8 + gc*2;
                if (c     > r0) s[nt][0] = -1e30f;
                if (c + 1 > r0) s[nt][1] = -1e30f;
                if (c     > r1) s[nt][2] = -1e30f;
                if (c + 1 > r1) s[nt][3] = -1e30f;
            }
        }

        float rm0 = -1e30f, rm1 = -1e30f;
        #pragma unroll
        for (int nt = 0; nt < 8; nt++) {
            rm0 = fmaxf(rm0, fmaxf(s[nt][0], s[nt][1]));
            rm1 = fmaxf(rm1, fmaxf(s[nt][2], s[nt][3]));
        }
        rm0 = fmaxf(rm0, __shfl_xor_sync(0xffffffffu, rm0, 1));
        rm0 = fmaxf(rm0, __shfl_xor_sync(0xffffffffu, rm0, 2));
        rm1 = fmaxf(rm1, __shfl_xor_sync(0xffffffffu, rm1, 1));
        rm1 = fmaxf(rm1, __shfl_xor_sync(0xffffffffu, rm1, 2));

        float mn0 = fmaxf(m0, rm0), mn1 = fmaxf(m1, rm1);
        float cor0 = __expf(m0 - mn0), cor1 = __expf(m1 - mn1);
        m0 = mn0; m1 = mn1;

        __syncthreads();

        float ps0 = 0.f, ps1 = 0.f;
        #pragma unroll
        for (int nt = 0; nt < 8; nt++) {
            float p00 = __expf(s[nt][0] - mn0);
            float p01 = __expf(s[nt][1] - mn0);
            float p10 = __expf(s[nt][2] - mn1);
            float p11 = __expf(s[nt][3] - mn1);
            ps0 += p00 + p01;
            ps1 += p10 + p11;
            KP[wr+gr  ][nt*8+gc*2  ] = cvt_tf32(p00);
            KP[wr+gr  ][nt*8+gc*2+1] = cvt_tf32(p01);
            KP[wr+gr+8][nt*8+gc*2  ] = cvt_tf32(p10);
            KP[wr+gr+8][nt*8+gc*2+1] = cvt_tf32(p11);
        }
        ps0 += __shfl_xor_sync(0xffffffffu, ps0, 1);
        ps0 += __shfl_xor_sync(0xffffffffu, ps0, 2);
        ps1 += __shfl_xor_sync(0xffffffffu, ps1, 1);
        ps1 += __shfl_xor_sync(0xffffffffu, ps1, 2);
        l0 = l0 * cor0 + ps0;
        l1 = l1 * cor1 + ps1;
        #pragma unroll
        for (int nt = 0; nt < 8; nt++) {
            o[nt][0] *= cor0; o[nt][1] *= cor0;
            o[nt][2] *= cor1; o[nt][3] *= cor1;
        }
        __syncwarp();

        #pragma unroll
        for (int kk = 0; kk < 8; kk++) {
            uint32_t pa0 = KP[wr+gr  ][kk*8+gc];
            uint32_t pa1 = KP[wr+gr+8][kk*8+gc];
            uint32_t pa2 = KP[wr+gr  ][kk*8+gc+4];
            uint32_t pa3 = KP[wr+gr+8][kk*8+gc+4];
            #pragma unroll
            for (int nt = 0; nt < 8; nt++) {
                uint32_t vb0 = Vs[nt*8+gr][kk*8+gc];
                uint32_t vb1 = Vs[nt*8+gr][kk*8+gc+4];
                mma_tf32(o[nt][0], o[nt][1], o[nt][2], o[nt][3],
                         pa0, pa1, pa2, pa3, vb0, vb1);
            }
        }
    }

    float inv0 = 1.0f / l0, inv1 = 1.0f / l1;
    #pragma unroll
    for (int nt = 0; nt < 8; nt++) {
        int d = nt*8 + gc*2;
        size_t i0 = ((size_t)(b*Lk + r0))*Dk + h*DHk + d;
        size_t i1 = ((size_t)(b*Lk + r1))*Dk + h*DHk + d;
        float v00 = o[nt][0]*inv0, v01 = o[nt][1]*inv0;
        float v10 = o[nt][2]*inv1, v11 = o[nt][3]*inv1;
        __nv_bfloat16 h00, l00, h01, l01, h10, l10, h11, l11;
        bf16_split(v00, h00, l00); bf16_split(v01, h01, l01);
        bf16_split(v10, h10, l10); bf16_split(v11, h11, l11);
        __nv_bfloat162 ph0; ph0.x = h00; ph0.y = h01;
        __nv_bfloat162 ph1; ph1.x = h10; ph1.y = h11;
        __nv_bfloat162 pl0; pl0.x = l00; pl0.y = l01;
        __nv_bfloat162 pl1; pl1.x = l10; pl1.y = l11;
        *(__nv_bfloat162*)(Oh + i0) = ph0;
        *(__nv_bfloat162*)(Oh + i1) = ph1;
        *(__nv_bfloat162*)(Ol + i0) = pl0;
        *(__nv_bfloat162*)(Ol + i1) = pl1;
    }
}

// ================= bf16 3-pass split GEMM, cp.async 2-stage, K=32 per stage =========
// C[m,n] = sum_k A[m,k]*B[n,k]. EPI: 0 store fp32, 1 fp32 +R, 2 silu -> bf16 hi/lo
#define BUFW 2560            // 128*20 words per buffer
#define STGW 10240           // 4 buffers
template<int EPI>
__global__ __launch_bounds__(256, 2) void gemm_bfs(const __nv_bfloat16* __restrict__ Ah_,
                                                   const __nv_bfloat16* __restrict__ Al_,
                                                   const __nv_bfloat16* __restrict__ Bh0,
                                                   const __nv_bfloat16* __restrict__ Bl0,
                                                   const __nv_bfloat16* __restrict__ Bh1,
                                                   const __nv_bfloat16* __restrict__ Bl1,
                                                   const __nv_bfloat16* __restrict__ Bh2,
                                                   const __nv_bfloat16* __restrict__ Bl2,
                                                   const float* __restrict__ R,
                                                   float* __restrict__ C0,
                                                   float* __restrict__ C1,
                                                   float* __restrict__ C2,
                                                   __nv_bfloat16* __restrict__ Cbh,
                                                   __nv_bfloat16* __restrict__ Cbl,
                                                   int N, int K)
{
    const __nv_bfloat16* Bh = (blockIdx.z == 0) ? Bh0 : (blockIdx.z == 1 ? Bh1 : Bh2);
    const __nv_bfloat16* Bl = (blockIdx.z == 0) ? Bl0 : (blockIdx.z == 1 ? Bl1 : Bl2);
    float*               C  = (blockIdx.z == 0) ? C0  : (blockIdx.z == 1 ? C1  : C2);

    extern __shared__ uint32_t dsm[];

    int t    = threadIdx.x;
    int lane = t & 31;
    int wid  = t >> 5;
    int bm0  = blockIdx.y * 128;
    int bn0  = blockIdx.x * 128;
    int wm0  = (wid & 3) * 32;
    int wn0  = (wid >> 2) * 64;
    int gr   = lane >> 2;
    int gc   = lane & 3;

    int lrow = t >> 1;
    int lkw  = (t & 1) * 8;       // word offset within row (word = bf16x2)

    const __nv_bfloat16* pAh = Ah_ + (size_t)(bm0 + lrow) * K + lkw * 2;
    const __nv_bfloat16* pAl = Al_ + (size_t)(bm0 + lrow) * K + lkw * 2;
    const __nv_bfloat16* pBh = Bh  + (size_t)(bn0 + lrow) * K + lkw * 2;
    const __nv_bfloat16* pBl = Bl  + (size_t)(bn0 + lrow) * K + lkw * 2;

    uint32_t sbase = (uint32_t)__cvta_generic_to_shared(dsm);
    uint32_t soff  = (lrow * 20 + lkw) * 4;

    float c[2][8][4];
    #pragma unroll
    for (int i = 0; i < 2; i++)
        #pragma unroll
        for (int j = 0; j < 8; j++)
            #pragma unroll
            for (int q = 0; q < 4; q++) c[i][j][q] = 0.f;

    // prologue: stages 0,1 (each stage covers K=32 elements = 16 words/row)
    #pragma unroll
    for (int s = 0; s < 2; s++) {
        int ko = s * 32;
        uint32_t sb = sbase + s * STGW * 4 + soff;
        cp16(sb,            pAh + ko); cp16(sb + 16,            pAh + ko + 8);
        cp16(sb + BUFW*4,   pAl + ko); cp16(sb + BUFW*4 + 16,   pAl + ko + 8);
        cp16(sb + 2*BUFW*4, pBh + ko); cp16(sb + 2*BUFW*4 + 16, pBh + ko + 8);
        cp16(sb + 3*BUFW*4, pBl + ko); cp16(sb + 3*BUFW*4 + 16, pBl + ko + 8);
        CP_COMMIT();
    }

    const int niter = K / 32;
    for (int it = 0; it < niter; it++) {
        CP_WAIT1();
        __syncthreads();
        int cur = it & 1;
        const uint32_t* sAh = dsm + cur * STGW;
        const uint32_t* sAl = sAh + BUFW;
        const uint32_t* sBh = sAh + 2 * BUFW;
        const uint32_t* sBl = sAh + 3 * BUFW;

        #pragma unroll
        for (int kk = 0; kk < 16; kk += 8) {   // two k16 steps
            uint32_t afh[2][4], afl[2][4];
            #pragma unroll
            for (int mt = 0; mt < 2; mt++) {
                int rr = (wm0 + mt * 16 + gr) * 20 + kk + gc;
                afh[mt][0] = sAh[rr];
                afh[mt][1] = sAh[rr + 8 * 20];
                afh[mt][2] = sAh[rr + 4];
                afh[mt][3] = sAh[rr + 8 * 20 + 4];
                afl[mt][0] = sAl[rr];
                afl[mt][1] = sAl[rr + 8 * 20];
                afl[mt][2] = sAl[rr + 4];
                afl[mt][3] = sAl[rr + 8 * 20 + 4];
            }
            #pragma unroll
            for (int nt = 0; nt < 8; nt++) {
                int nn = (wn0 + nt * 8 + gr) * 20 + kk + gc;
                uint32_t bh0 = sBh[nn], bh1 = sBh[nn + 4];
                uint32_t bl0 = sBl[nn], bl1 = sBl[nn + 4];
                #pragma unroll
                for (int mt = 0; mt < 2; mt++) {
                    mma_bf16(c[mt][nt][0], c[mt][nt][1], c[mt][nt][2], c[mt][nt][3],
                             afh[mt][0], afh[mt][1], afh[mt][2], afh[mt][3], bh0, bh1);
                    mma_bf16(c[mt][nt][0], c[mt][nt][1], c[mt][nt][2], c[mt][nt][3],
                             afh[mt][0], afh[mt][1], afh[mt][2], afh[mt][3], bl0, bl1);
                    mma_bf16(c[mt][nt][0], c[mt][nt][1], c[mt][nt][2], c[mt][nt][3],
                             afl[mt][0], afl[mt][1], afl[mt][2], afl[mt][3], bh0, bh1);
                }
            }
        }

        __syncthreads();
        if (it + 2 < niter) {
            int ko = (it + 2) * 32;
            uint32_t sb = sbase + cur * STGW * 4 + soff;
            cp16(sb,            pAh + ko); cp16(sb + 16,            pAh + ko + 8);
            cp16(sb + BUFW*4,   pAl + ko); cp16(sb + BUFW*4 + 16,   pAl + ko + 8);
            cp16(sb + 2*BUFW*4, pBh + ko); cp16(sb + 2*BUFW*4 + 16, pBh + ko + 8);
            cp16(sb + 3*BUFW*4, pBl + ko); cp16(sb + 3*BUFW*4 + 16, pBl + ko + 8);
        }
        CP_COMMIT();
    }

    #pragma unroll
    for (int mt = 0; mt < 2; mt++) {
        #pragma unroll
        for (int nt = 0; nt < 8; nt++) {
            int row = bm0 + wm0 + mt * 16 + gr;
            int col = bn0 + wn0 + nt * 8 + gc * 2;
            #pragma unroll
            for (int half = 0; half < 2; half++) {
                int r = row + half * 8;
                float vx = c[mt][nt][half * 2 + 0];
                float vy = c[mt][nt][half * 2 + 1];
                size_t idx = (size_t)r * N + col;
                if (EPI == 1) {
                    float2 rr = *(const float2*)(R + idx);
                    vx += rr.x; vy += rr.y;
                    float2 ov; ov.x = vx; ov.y = vy;
                    *(float2*)(C + idx) = ov;
                } else if (EPI == 2) {
                    vx = vx / (1.f + __expf(-vx));
                    vy = vy / (1.f + __expf(-vy));
                    __nv_bfloat16 hx, lx, hy, ly;
                    bf16_split(vx, hx, lx);
                    bf16_split(vy, hy, ly);
                    __nv_bfloat162 ph; ph.x = hx; ph.y = hy;
                    __nv_bfloat162 pl; pl.x = lx; pl.y = ly;
                    *(__nv_bfloat162*)(Cbh + idx) = ph;
                    *(__nv_bfloat162*)(Cbl + idx) = pl;
                } else {
                    float2 ov; ov.x = vx; ov.y = vy;
                    *(float2*)(C + idx) = ov;
                }
            }
        }
    }
}

// ================= LM head GEMM: pre-converted tf32, cp.async 2-stage =================
__global__ __launch_bounds__(256, 2) void gemm_lm(const float* __restrict__ A,
                                                  const float* __restrict__ B,
                                                  float* __restrict__ C,
                                                  int N, int K)
{
    __shared__ uint32_t sA[2][128][20];
    __shared__ uint32_t sB[2][128][20];

    int t    = threadIdx.x;
    int lane = t & 31;
    int wid  = t >> 5;
    int bm0  = blockIdx.y * 128;
    int bn0  = blockIdx.x * 128;
    int wm0  = (wid & 3) * 32;
    int wn0  = (wid >> 2) * 64;

    int lrow = t >> 1;
    int lk   = (t & 1) * 8;

    const float* Ap = A + (size_t)(bm0 + lrow) * K + lk;
    const float* Bp = B + (size_t)(bn0 + lrow) * K + lk;

    float c[2][8][4];
    #pragma unroll
    for (int i = 0; i < 2; i++)
        #pragma unroll
        for (int j = 0; j < 8; j++)
            #pragma unroll
            for (int q = 0; q < 4; q++) c[i][j][q] = 0.f;

    int gr = lane >> 2;
    int gc = lane & 3;

    uint32_t saA0 = (uint32_t)__cvta_generic_to_shared(&sA[0][lrow][lk]);
    uint32_t saB0 = (uint32_t)__cvta_generic_to_shared(&sB[0][lrow][lk]);
    const uint32_t stageStride = 128 * 20 * 4;

    #pragma unroll
    for (int s = 0; s < 2; s++) {
        int ko = s * 16;
        cp16(saA0 + s * stageStride,      Ap + ko);
        cp16(saA0 + s * stageStride + 16, Ap + ko + 4);
        cp16(saB0 + s * stageStride,      Bp + ko);
        cp16(saB0 + s * stageStride + 16, Bp + ko + 4);
        CP_COMMIT();
    }

    const int niter = K / 16;
    for (int it = 0; it < niter; it++) {
        CP_WAIT1();
        __syncthreads();
        int cur = it & 1;

        #pragma unroll
        for (int kk = 0; kk < 16; kk += 8) {
            uint32_t afh[2][4], bfh[8][2];
            #pragma unroll
            for (int mt = 0; mt < 2; mt++) {
                int rr = wm0 + mt * 16 + gr;
                afh[mt][0] = sA[cur][rr][kk + gc];
                afh[mt][1] = sA[cur][rr + 8][kk + gc];
                afh[mt][2] = sA[cur][rr][kk + 4 + gc];
                afh[mt][3] = sA[cur][rr + 8][kk + 4 + gc];
            }
            #pragma unroll
            for (int nt = 0; nt < 8; nt++) {
                int n0 = wn0 + nt * 8 + gr;
                bfh[nt][0] = sB[cur][n0][kk + gc];
                bfh[nt][1] = sB[cur][n0][kk + 4 + gc];
            }
            #pragma unroll
            for (int mt = 0; mt < 2; mt++)
                #pragma unroll
                for (int nt = 0; nt < 8; nt++)
                    mma_tf32(c[mt][nt][0], c[mt][nt][1], c[mt][nt][2], c[mt][nt][3],
                             afh[mt][0], afh[mt][1], afh[mt][2], afh[mt][3],
                             bfh[nt][0], bfh[nt][1]);
        }

        __syncthreads();
        if (it + 2 < niter) {
            int ko = (it + 2) * 16;
            cp16(saA0 + cur * stageStride,      Ap + ko);
            cp16(saA0 + cur * stageStride + 16, Ap + ko + 4);
            cp16(saB0 + cur * stageStride,      Bp + ko);
            cp16(saB0 + cur * stageStride + 16, Bp + ko + 4);
        }
        CP_COMMIT();
    }

    #pragma unroll
    for (int mt = 0; mt < 2; mt++) {
        #pragma unroll
        for (int nt = 0; nt < 8; nt++) {
            int row = bm0 + wm0 + mt * 16 + gr;
            int col = bn0 + wn0 + nt * 8 + gc * 2;
            #pragma unroll
            for (int half = 0; half < 2; half++) {
                int r = row + half * 8;
                float2 ov;
                ov.x = c[mt][nt][half * 2 + 0];
                ov.y = c[mt][nt][half * 2 + 1];
                *(float2*)(C + (size_t)r * N + col) = ov;
            }
        }
    }
}

// ---------------- classifier heads ----------------
__global__ void heads_kernel(const float* __restrict__ X,
                             const float* __restrict__ fnw,
                             const float* __restrict__ rw, const float* __restrict__ rb,
                             const float* __restrict__ mw, const float* __restrict__ mb,
                             float* __restrict__ out)
{
    int w = threadIdx.x >> 5, lane = threadIdx.x & 31;
    if (w >= Bk) return;
    const float* x = X + (size_t)w * Lk * Dk;
    float ss = 0.f;
    for (int d = lane; d < Dk; d += 32) { float v = x[d]; ss += v * v; }
    #pragma unroll
    for (int o = 16; o > 0; o >>= 1) ss += __shfl_xor_sync(0xffffffffu, ss, o);
    float rs = rsqrtf(ss * (1.0f / Dk) + 1.1920929e-07f);
    float sr = 0.f, sm = 0.f;
    for (int d = lane; d < Dk; d += 32) {
        float xn = x[d] * rs * fnw[d];
        sr += xn * rw[d];
        sm += xn * mw[d];
    }
    #pragma unroll
    for (int o = 16; o > 0; o >>= 1) {
        sr += __shfl_down_sync(0xffffffffu, sr, o);
        sm += __shfl_down_sync(0xffffffffu, sm, o);
    }
    if (lane == 0) {
        out[w]      = sr + rb[0];
        out[Bk + w] = sm + mb[0];
    }
}

// ---------------- launch ----------------
extern "C" void kernel_launch(void* const* d_in, const int* in_sizes, int n_in,
                              void* d_out, int out_size)
{
    const int*   ids      = (const int*)d_in[0];
    const int*   tts      = (const int*)d_in[1];
    const int*   mask     = (const int*)d_in[2];
    const float* tok_emb  = (const float*)d_in[3];
    const float* type_emb = (const float*)d_in[4];
    const float* norm1    = (const float*)d_in[5];
    const float* wq       = (const float*)d_in[6];
    const float* wk       = (const float*)d_in[7];
    const float* wv       = (const float*)d_in[8];
    const float* wo       = (const float*)d_in[9];
    const float* norm2    = (const float*)d_in[10];
    const float* fw1      = (const float*)d_in[11];
    const float* fw2      = (const float*)d_in[12];
    const float* fnorm    = (const float*)d_in[13];
    const float* lmw      = (const float*)d_in[14];
    const float* rw       = (const float*)d_in[15];
    const float* rbias    = (const float*)d_in[16];
    const float* mw       = (const float*)d_in[17];
    const float* mbias    = (const float*)d_in[18];
    float* out = (float*)d_out;

    float *X, *XN32, *Q, *K, *V, *LW32;
    __nv_bfloat16 *XNh, *XNl, *AOh, *AOl, *F1h, *F1l, *Wh, *Wl;
    cudaGetSymbolAddress((void**)&X,    g_X);
    cudaGetSymbolAddress((void**)&XN32, g_XN32);
    cudaGetSymbolAddress((void**)&Q,    g_Q);
    cudaGetSymbolAddress((void**)&K,    g_K);
    cudaGetSymbolAddress((void**)&V,    g_V);
    cudaGetSymbolAddress((void**)&XNh,  g_XNh);
    cudaGetSymbolAddress((void**)&XNl,  g_XNl);
    cudaGetSymbolAddress((void**)&AOh,  g_AOh);
    cudaGetSymbolAddress((void**)&AOl,  g_AOl);
    cudaGetSymbolAddress((void**)&F1h,  g_F1h);
    cudaGetSymbolAddress((void**)&F1l,  g_F1l);
    cudaGetSymbolAddress((void**)&Wh,   g_Wh);
    cudaGetSymbolAddress((void**)&Wl,   g_Wl);
    cudaGetSymbolAddress((void**)&LW32, g_LW32);

    const int dynSmem = STGW * 2 * 4;   // 81920 bytes
    cudaFuncSetAttribute(gemm_bfs<0>, cudaFuncAttributeMaxDynamicSharedMemorySize, dynSmem);
    cudaFuncSetAttribute(gemm_bfs<1>, cudaFuncAttributeMaxDynamicSharedMemorySize, dynSmem);
    cudaFuncSetAttribute(gemm_bfs<2>, cudaFuncAttributeMaxDynamicSharedMemorySize, dynSmem);

    embed_kernel<<<(MR * Dk) / 256, 256>>>(ids, tts, tok_emb, type_emb, X);
    cvt_kernel<<<(Vk * Dk) / 256, 256>>>(lmw, LW32, Vk * Dk);

    // pre-split all layer weights to bf16 hi/lo
    split_bf16_kernel<<<(NLk*Dk*Dk) / 256, 256>>>(wq,  Wh + OFF_WQ, Wl + OFF_WQ, NLk*Dk*Dk);
    split_bf16_kernel<<<(NLk*Dk*Dk) / 256, 256>>>(wk,  Wh + OFF_WK, Wl + OFF_WK, NLk*Dk*Dk);
    split_bf16_kernel<<<(NLk*Dk*Dk) / 256, 256>>>(wv,  Wh + OFF_WV, Wl + OFF_WV, NLk*Dk*Dk);
    split_bf16_kernel<<<(NLk*Dk*Dk) / 256, 256>>>(wo,  Wh + OFF_WO, Wl + OFF_WO, NLk*Dk*Dk);
    split_bf16_kernel<<<(NLk*FFD*Dk) / 256, 256>>>(fw1, Wh + OFF_F1, Wl + OFF_F1, NLk*FFD*Dk);
    split_bf16_kernel<<<(NLk*FFD*Dk) / 256, 256>>>(fw2, Wh + OFF_F2, Wl + OFF_F2, NLk*FFD*Dk);

    dim3 gqkv(Dk  / 128, MR / 128, 3);
    dim3 gs  (Dk  / 128, MR / 128, 1);
    dim3 gf1 (FFD / 128, MR / 128, 1);
    dim3 glm (Vk  / 128, MR / 128);
    dim3 ga  (Lk / 64, Hk, Bk);
    dim3 grp ((MR * Hk * 32) / 256, 2);

    for (int i = 0; i < NLk; i++) {
        size_t od = (size_t)i * Dk * Dk;
        size_t of = (size_t)i * FFD * Dk;
        const __nv_bfloat16 *qh = Wh + OFF_WQ + od, *ql = Wl + OFF_WQ + od;
        const __nv_bfloat16 *kh = Wh + OFF_WK + od, *kl = Wl + OFF_WK + od;
        const __nv_bfloat16 *vh = Wh + OFF_WV + od, *vl = Wl + OFF_WV + od;
        const __nv_bfloat16 *oh = Wh + OFF_WO + od, *ol = Wl + OFF_WO + od;
        const __nv_bfloat16 *f1h = Wh + OFF_F1 + of, *f1l = Wl + OFF_F1 + of;
        const __nv_bfloat16 *f2h = Wh + OFF_F2 + of, *f2l = Wl + OFF_F2 + of;

        rmsnorm_kernel<<<MR, 256>>>(X, norm1 + (size_t)i * Dk, XNh, XNl);
        gemm_bfs<0><<<gqkv, 256, dynSmem>>>(XNh, XNl, qh, ql, kh, kl, vh, vl,
                                            nullptr, Q, K, V, nullptr, nullptr, Dk, Dk);
        rope2_kernel<<<grp, 256>>>(Q, K);
        attn_fa<<<ga, 128>>>(Q, K, V, mask, AOh, AOl);
        gemm_bfs<1><<<gs, 256, dynSmem>>>(AOh, AOl, oh, ol, oh, ol, oh, ol,
                                          X, X, X, X, nullptr, nullptr, Dk, Dk);
        rmsnorm_kernel<<<MR, 256>>>(X, norm2 + (size_t)i * Dk, XNh, XNl);
        gemm_bfs<2><<<gf1, 256, dynSmem>>>(XNh, XNl, f1h, f1l, f1h, f1l, f1h, f1l,
                                           nullptr, nullptr, nullptr, nullptr,
                                           F1h, F1l, FFD, Dk);
        gemm_bfs<1><<<gs, 256, dynSmem>>>(F1h, F1l, f2h, f2l, f2h, f2l, f2h, f2l,
                                          X, X, X, X, nullptr, nullptr, Dk, FFD);
    }

    rmsnorm_tf32_kernel<<<MR, 256>>>(X, fnorm, XN32);
    gemm_lm<<<glm, 256>>>(XN32, LW32, out, Vk, Dk);
    heads_kernel<<<1, 128>>>(X, fnorm, rw, rbias, mw, mbias, out + (size_t)Bk * Lk * Vk);
}

// round 9
// speedup vs baseline: 4.1720x; 1.3218x over previous
#include <cuda_runtime.h>
#include <cuda_bf16.h>
#include <cuda_fp16.h>
#include <math.h>
#include <stdint.h>

// Problem constants
#define Bk   4
#define Lk   2048
#define Dk   256
#define Hk   4
#define NLk  4
#define Vk   32000
#define DHk  64
#define MR   (Bk*Lk)      // 8192 rows
#define FFD  (4*Dk)       // 1024

// weight-split offsets (elements)
#define OFF_WQ  0
#define OFF_WK  (NLk*Dk*Dk)
#define OFF_WV  (2*NLk*Dk*Dk)
#define OFF_WO  (3*NLk*Dk*Dk)
#define OFF_F1  (4*NLk*Dk*Dk)
#define OFF_F2  (4*NLk*Dk*Dk + NLk*FFD*Dk)
#define WTOT    (4*NLk*Dk*Dk + 2*NLk*FFD*Dk)

// ---------------- scratch ----------------
__device__ float g_X   [MR*Dk];
__device__ float g_Q   [MR*Dk];
__device__ float g_K   [MR*Dk];
__device__ float g_V   [MR*Dk];
__device__ __nv_bfloat16 g_XNh[MR*Dk];
__device__ __nv_bfloat16 g_XNl[MR*Dk];
__device__ __nv_bfloat16 g_AOh[MR*Dk];
__device__ __nv_bfloat16 g_AOl[MR*Dk];
__device__ __nv_bfloat16 g_F1h[MR*FFD];
__device__ __nv_bfloat16 g_F1l[MR*FFD];
__device__ __nv_bfloat16 g_Wh [WTOT];
__device__ __nv_bfloat16 g_Wl [WTOT];
__device__ __half g_XNH16[MR*Dk];
__device__ __half g_LWH  [Vk*Dk];

// ---------------- helpers ----------------
__device__ __forceinline__ void mma_bf16(float& c0, float& c1, float& c2, float& c3,
                                         uint32_t a0, uint32_t a1, uint32_t a2, uint32_t a3,
                                         uint32_t b0, uint32_t b1)
{
    asm volatile("mma.sync.aligned.m16n8k16.row.col.f32.bf16.bf16.f32 "
                 "{%0,%1,%2,%3},{%4,%5,%6,%7},{%8,%9},{%0,%1,%2,%3};"
                 : "+f"(c0), "+f"(c1), "+f"(c2), "+f"(c3)
                 : "r"(a0), "r"(a1), "r"(a2), "r"(a3), "r"(b0), "r"(b1));
}

__device__ __forceinline__ void mma_fp16(float& c0, float& c1, float& c2, float& c3,
                                         uint32_t a0, uint32_t a1, uint32_t a2, uint32_t a3,
                                         uint32_t b0, uint32_t b1)
{
    asm volatile("mma.sync.aligned.m16n8k16.row.col.f32.f16.f16.f32 "
                 "{%0,%1,%2,%3},{%4,%5,%6,%7},{%8,%9},{%0,%1,%2,%3};"
                 : "+f"(c0), "+f"(c1), "+f"(c2), "+f"(c3)
                 : "r"(a0), "r"(a1), "r"(a2), "r"(a3), "r"(b0), "r"(b1));
}

__device__ __forceinline__ void cp16(uint32_t smem, const void* gmem) {
    asm volatile("cp.async.ca.shared.global [%0], [%1], 16;\n" :: "r"(smem), "l"(gmem));
}
#define CP_COMMIT() asm volatile("cp.async.commit_group;\n" ::: "memory")
#define CP_WAIT1()  asm volatile("cp.async.wait_group 1;\n" ::: "memory")

__device__ __forceinline__ void bf16_split(float v, __nv_bfloat16& h, __nv_bfloat16& l) {
    h = __float2bfloat16_rn(v);
    l = __float2bfloat16_rn(v - __bfloat162float(h));
}

__device__ __forceinline__ uint32_t pack_h2(float a, float b) {
    __half2 h = __floats2half2_rn(a, b);
    return *reinterpret_cast<uint32_t*>(&h);
}

// ---------------- embedding ----------------
__global__ void embed_kernel(const int* __restrict__ ids, const int* __restrict__ tts,
                             const float* __restrict__ te, const float* __restrict__ ye,
                             float* __restrict__ X)
{
    int i = blockIdx.x * 256 + threadIdx.x;
    int row = i >> 8;
    int d   = i & 255;
    X[i] = te[(size_t)ids[row] * Dk + d] + ye[(size_t)tts[row] * Dk + d];
}

// ---------------- converts ----------------
__global__ void cvt_f16_kernel(const float* __restrict__ src, __half* __restrict__ dst, int n)
{
    int i = blockIdx.x * 256 + threadIdx.x;
    if (i < n) dst[i] = __float2half_rn(src[i]);
}

__global__ void split_bf16_kernel(const float* __restrict__ src,
                                  __nv_bfloat16* __restrict__ dh,
                                  __nv_bfloat16* __restrict__ dl, int n)
{
    int i = blockIdx.x * 256 + threadIdx.x;
    if (i < n) {
        __nv_bfloat16 h, l;
        bf16_split(src[i], h, l);
        dh[i] = h; dl[i] = l;
    }
}

// ---------------- RMSNorm -> bf16 hi/lo ----------------
__global__ __launch_bounds__(256) void rmsnorm_kernel(const float* __restrict__ X,
                                                      const float* __restrict__ w,
                                                      __nv_bfloat16* __restrict__ Yh,
                                                      __nv_bfloat16* __restrict__ Yl)
{
    int r = blockIdx.x;
    int t = threadIdx.x;
    float v = X[(size_t)r * Dk + t];
    float s = v * v;
    #pragma unroll
    for (int o = 16; o > 0; o >>= 1) s += __shfl_down_sync(0xffffffffu, s, o);
    __shared__ float ws[8];
    __shared__ float tot;
    int lane = t & 31, wi = t >> 5;
    if (lane == 0) ws[wi] = s;
    __syncthreads();
    if (t == 0) {
        float a = 0.f;
        #pragma unroll
        for (int i = 0; i < 8; i++) a += ws[i];
        tot = a;
    }
    __syncthreads();
    float rs = rsqrtf(tot * (1.0f / Dk) + 1.1920929e-07f);
    float y = v * rs * w[t];
    __nv_bfloat16 h, l;
    bf16_split(y, h, l);
    Yh[(size_t)r * Dk + t] = h;
    Yl[(size_t)r * Dk + t] = l;
}

// ---------------- final RMSNorm -> fp16 (LM head input) ----------------
__global__ __launch_bounds__(256) void rmsnorm_f16_kernel(const float* __restrict__ X,
                                                          const float* __restrict__ w,
                                                          __half* __restrict__ Y)
{
    int r = blockIdx.x;
    int t = threadIdx.x;
    float v = X[(size_t)r * Dk + t];
    float s = v * v;
    #pragma unroll
    for (int o = 16; o > 0; o >>= 1) s += __shfl_down_sync(0xffffffffu, s, o);
    __shared__ float ws[8];
    __shared__ float tot;
    int lane = t & 31, wi = t >> 5;
    if (lane == 0) ws[wi] = s;
    __syncthreads();
    if (t == 0) {
        float a = 0.f;
        #pragma unroll
        for (int i = 0; i < 8; i++) a += ws[i];
        tot = a;
    }
    __syncthreads();
    float rs = rsqrtf(tot * (1.0f / Dk) + 1.1920929e-07f);
    Y[(size_t)r * Dk + t] = __float2half_rn(v * rs * w[t]);
}

// ---------------- RoPE ----------------
__global__ void rope2_kernel(float* __restrict__ Q, float* __restrict__ K)
{
    float* P = blockIdx.y ? K : Q;
    int i   = blockIdx.x * 256 + threadIdx.x;
    int t   = i & 31;
    int h   = (i >> 5) & 3;
    int row = i >> 7;
    int pos = row & (Lk - 1);
    float inv = exp2f(-(float)t * (13.287712379549449f / 32.0f));
    float ang = (float)pos * inv;
    float sn, cs;
    sincosf(ang, &sn, &cs);
    size_t base = (size_t)row * Dk + h * DHk;
    float a = P[base + t];
    float b = P[base + t + 32];
    P[base + t]      = a * cs - b * sn;
    P[base + t + 32] = b * cs + a * sn;
}

// ---------------- fp16 tensor-core flash attention, bf16 hi/lo output ----------------
// 64 queries/block (4 warps x 16 rows), 64-key tiles, DH=64.
// Words are half2 pairs packed along the contraction dim. Row pad = 36 words.
#define QPAD 36
__global__ __launch_bounds__(128) void attn_fa(const float* __restrict__ Q,
                                               const float* __restrict__ K,
                                               const float* __restrict__ V,
                                               const int*   __restrict__ mask,
                                               __nv_bfloat16* __restrict__ Oh,
                                               __nv_bfloat16* __restrict__ Ol)
{
    __shared__ uint32_t KP[64][QPAD];   // K tile (rows=key, words along d), then P (rows=q, words along key)
    __shared__ uint32_t Vs[64][QPAD];   // V^T: rows=d, words along key
    __shared__ float    mkf[64];

    int b  = blockIdx.z, h = blockIdx.y;
    int q0 = blockIdx.x * 64;
    int tid = threadIdx.x;
    int lane = tid & 31, wid = tid >> 5;
    int gr = lane >> 2, gc = lane & 3;
    int wr = wid * 16;

    const int* mrow = mask + (size_t)b * Lk;

    // stage Q (scaled) as fp16 pairs along d
    #pragma unroll
    for (int it = 0; it < 8; it++) {
        int pos = tid + it * 128;
        int row = pos >> 4, d4 = pos & 15;
        float4 qv = *(const float4*)(Q + ((size_t)(b*Lk + q0 + row))*Dk + h*DHk + d4*4);
        KP[row][d4*2    ] = pack_h2(qv.x*0.125f, qv.y*0.125f);
        KP[row][d4*2 + 1] = pack_h2(qv.z*0.125f, qv.w*0.125f);
    }
    __syncthreads();
    uint32_t qa[4][4];
    #pragma unroll
    for (int kw = 0; kw < 4; kw++) {
        qa[kw][0] = KP[wr+gr  ][kw*8+gc];
        qa[kw][1] = KP[wr+gr+8][kw*8+gc];
        qa[kw][2] = KP[wr+gr  ][kw*8+gc+4];
        qa[kw][3] = KP[wr+gr+8][kw*8+gc+4];
    }

    float o[8][4];
    #pragma unroll
    for (int nt = 0; nt < 8; nt++)
        #pragma unroll
        for (int j = 0; j < 4; j++) o[nt][j] = 0.f;
    float m0 = -1e30f, m1 = -1e30f, l0 = 0.f, l1 = 0.f;
    int r0 = q0 + wr + gr, r1 = r0 + 8;

    int ntile = blockIdx.x + 1;
    for (int kt = 0; kt < ntile; kt++) {
        int key0 = kt * 64;
        __syncthreads();
        #pragma unroll
        for (int it = 0; it < 8; it++) {
            int pos = tid + it * 128;
            int key = pos >> 4, d4 = pos & 15;
            size_t gbase = ((size_t)(b*Lk + key0 + key))*Dk + h*DHk + d4*4;
            float4 kv = *(const float4*)(K + gbase);
            KP[key][d4*2    ] = pack_h2(kv.x, kv.y);
            KP[key][d4*2 + 1] = pack_h2(kv.z, kv.w);
            float4 vv = *(const float4*)(V + gbase);
            __half* vh = (__half*)&Vs[0][0];   // row stride = 2*QPAD halves
            vh[(d4*4+0)*(2*QPAD) + key] = __float2half_rn(vv.x);
            vh[(d4*4+1)*(2*QPAD) + key] = __float2half_rn(vv.y);
            vh[(d4*4+2)*(2*QPAD) + key] = __float2half_rn(vv.z);
            vh[(d4*4+3)*(2*QPAD) + key] = __float2half_rn(vv.w);
        }
        if (tid < 64) mkf[tid] = mrow[key0 + tid] ? 0.0f : -1e30f;
        __syncthreads();

        // S = Q K^T  (fp16, k16 per mma)
        float s[8][4];
        #pragma unroll
        for (int nt = 0; nt < 8; nt++)
            #pragma unroll
            for (int j = 0; j < 4; j++) s[nt][j] = 0.f;
        #pragma unroll
        for (int kw = 0; kw < 4; kw++) {
            #pragma unroll
            for (int nt = 0; nt < 8; nt++) {
                uint32_t b0 = KP[nt*8+gr][kw*8+gc];
                uint32_t b1 = KP[nt*8+gr][kw*8+gc+4];
                mma_fp16(s[nt][0], s[nt][1], s[nt][2], s[nt][3],
                         qa[kw][0], qa[kw][1], qa[kw][2], qa[kw][3], b0, b1);
            }
        }

        bool last = (kt == ntile - 1);
        #pragma unroll
        for (int nt = 0; nt < 8; nt++) {
            float mk0 = mkf[nt*8+gc*2], mk1 = mkf[nt*8+gc*2+1];
            s[nt][0] += mk0; s[nt][1] += mk1;
            s[nt][2] += mk0; s[nt][3] += mk1;
            if (last) {
                int c = key0 + nt*8 + gc*2;
                if (c     > r0) s[nt][0] = -1e30f;
                if (c + 1 > r0) s[nt][1] = -1e30f;
                if (c     > r1) s[nt][2] = -1e30f;
                if (c + 1 > r1) s[nt][3] = -1e30f;
            }
        }

        float rm0 = -1e30f, rm1 = -1e30f;
        #pragma unroll
        for (int nt = 0; nt < 8; nt++) {
            rm0 = fmaxf(rm0, fmaxf(s[nt][0], s[nt][1]));
            rm1 = fmaxf(rm1, fmaxf(s[nt][2], s[nt][3]));
        }
        rm0 = fmaxf(rm0, __shfl_xor_sync(0xffffffffu, rm0, 1));
        rm0 = fmaxf(rm0, __shfl_xor_sync(0xffffffffu, rm0, 2));
        rm1 = fmaxf(rm1, __shfl_xor_sync(0xffffffffu, rm1, 1));
        rm1 = fmaxf(rm1, __shfl_xor_sync(0xffffffffu, rm1, 2));

        float mn0 = fmaxf(m0, rm0), mn1 = fmaxf(m1, rm1);
        float cor0 = __expf(m0 - mn0), cor1 = __expf(m1 - mn1);
        m0 = mn0; m1 = mn1;

        __syncthreads();   // everyone done reading K before P overwrites KP

        // P = exp(S - m), stored as fp16 pairs along key
        float ps0 = 0.f, ps1 = 0.f;
        #pragma unroll
        for (int nt = 0; nt < 8; nt++) {
            float p00 = __expf(s[nt][0] - mn0);
            float p01 = __expf(s[nt][1] - mn0);
            float p10 = __expf(s[nt][2] - mn1);
            float p11 = __expf(s[nt][3] - mn1);
            ps0 += p00 + p01;
            ps1 += p10 + p11;
            KP[wr+gr  ][nt*4+gc] = pack_h2(p00, p01);
            KP[wr+gr+8][nt*4+gc] = pack_h2(p10, p11);
        }
        ps0 += __shfl_xor_sync(0xffffffffu, ps0, 1);
        ps0 += __shfl_xor_sync(0xffffffffu, ps0, 2);
        ps1 += __shfl_xor_sync(0xffffffffu, ps1, 1);
        ps1 += __shfl_xor_sync(0xffffffffu, ps1, 2);
        l0 = l0 * cor0 + ps0;
        l1 = l1 * cor1 + ps1;
        #pragma unroll
        for (int nt = 0; nt < 8; nt++) {
            o[nt][0] *= cor0; o[nt][1] *= cor0;
            o[nt][2] *= cor1; o[nt][3] *= cor1;
        }
        __syncwarp();      // P rows read cross-lane within this warp only

        // O += P V  (fp16)
        #pragma unroll
        for (int kw = 0; kw < 4; kw++) {
            uint32_t pa0 = KP[wr+gr  ][kw*8+gc];
            uint32_t pa1 = KP[wr+gr+8][kw*8+gc];
            uint32_t pa2 = KP[wr+gr  ][kw*8+gc+4];
            uint32_t pa3 = KP[wr+gr+8][kw*8+gc+4];
            #pragma unroll
            for (int nt = 0; nt < 8; nt++) {
                uint32_t vb0 = Vs[nt*8+gr][kw*8+gc];
                uint32_t vb1 = Vs[nt*8+gr][kw*8+gc+4];
                mma_fp16(o[nt][0], o[nt][1], o[nt][2], o[nt][3],
                         pa0, pa1, pa2, pa3, vb0, vb1);
            }
        }
    }

    float inv0 = 1.0f / l0, inv1 = 1.0f / l1;
    #pragma unroll
    for (int nt = 0; nt < 8; nt++) {
        int d = nt*8 + gc*2;
        size_t i0 = ((size_t)(b*Lk + r0))*Dk + h*DHk + d;
        size_t i1 = ((size_t)(b*Lk + r1))*Dk + h*DHk + d;
        float v00 = o[nt][0]*inv0, v01 = o[nt][1]*inv0;
        float v10 = o[nt][2]*inv1, v11 = o[nt][3]*inv1;
        __nv_bfloat16 h00, l00, h01, l01, h10, l10, h11, l11;
        bf16_split(v00, h00, l00); bf16_split(v01, h01, l01);
        bf16_split(v10, h10, l10); bf16_split(v11, h11, l11);
        __nv_bfloat162 ph0; ph0.x = h00; ph0.y = h01;
        __nv_bfloat162 ph1; ph1.x = h10; ph1.y = h11;
        __nv_bfloat162 pl0; pl0.x = l00; pl0.y = l01;
        __nv_bfloat162 pl1; pl1.x = l10; pl1.y = l11;
        *(__nv_bfloat162*)(Oh + i0) = ph0;
        *(__nv_bfloat162*)(Oh + i1) = ph1;
        *(__nv_bfloat162*)(Ol + i0) = pl0;
        *(__nv_bfloat162*)(Ol + i1) = pl1;
    }
}

// ================= bf16 3-pass split GEMM, cp.async 2-stage, K=32 per stage =========
#define BUFW 2560
#define STGW 10240
template<int EPI>
__global__ __launch_bounds__(256, 2) void gemm_bfs(const __nv_bfloat16* __restrict__ Ah_,
                                                   const __nv_bfloat16* __restrict__ Al_,
                                                   const __nv_bfloat16* __restrict__ Bh0,
                                                   const __nv_bfloat16* __restrict__ Bl0,
                                                   const __nv_bfloat16* __restrict__ Bh1,
                                                   const __nv_bfloat16* __restrict__ Bl1,
                                                   const __nv_bfloat16* __restrict__ Bh2,
                                                   const __nv_bfloat16* __restrict__ Bl2,
                                                   const float* __restrict__ R,
                                                   float* __restrict__ C0,
                                                   float* __restrict__ C1,
                                                   float* __restrict__ C2,
                                                   __nv_bfloat16* __restrict__ Cbh,
                                                   __nv_bfloat16* __restrict__ Cbl,
                                                   int N, int K)
{
    const __nv_bfloat16* Bh = (blockIdx.z == 0) ? Bh0 : (blockIdx.z == 1 ? Bh1 : Bh2);
    const __nv_bfloat16* Bl = (blockIdx.z == 0) ? Bl0 : (blockIdx.z == 1 ? Bl1 : Bl2);
    float*               C  = (blockIdx.z == 0) ? C0  : (blockIdx.z == 1 ? C1  : C2);

    extern __shared__ uint32_t dsm[];

    int t    = threadIdx.x;
    int lane = t & 31;
    int wid  = t >> 5;
    int bm0  = blockIdx.y * 128;
    int bn0  = blockIdx.x * 128;
    int wm0  = (wid & 3) * 32;
    int wn0  = (wid >> 2) * 64;
    int gr   = lane >> 2;
    int gc   = lane & 3;

    int lrow = t >> 1;
    int lkw  = (t & 1) * 8;

    const __nv_bfloat16* pAh = Ah_ + (size_t)(bm0 + lrow) * K + lkw * 2;
    const __nv_bfloat16* pAl = Al_ + (size_t)(bm0 + lrow) * K + lkw * 2;
    const __nv_bfloat16* pBh = Bh  + (size_t)(bn0 + lrow) * K + lkw * 2;
    const __nv_bfloat16* pBl = Bl  + (size_t)(bn0 + lrow) * K + lkw * 2;

    uint32_t sbase = (uint32_t)__cvta_generic_to_shared(dsm);
    uint32_t soff  = (lrow * 20 + lkw) * 4;

    float c[2][8][4];
    #pragma unroll
    for (int i = 0; i < 2; i++)
        #pragma unroll
        for (int j = 0; j < 8; j++)
            #pragma unroll
            for (int q = 0; q < 4; q++) c[i][j][q] = 0.f;

    #pragma unroll
    for (int s = 0; s < 2; s++) {
        int ko = s * 32;
        uint32_t sb = sbase + s * STGW * 4 + soff;
        cp16(sb,            pAh + ko); cp16(sb + 16,            pAh + ko + 8);
        cp16(sb + BUFW*4,   pAl + ko); cp16(sb + BUFW*4 + 16,   pAl + ko + 8);
        cp16(sb + 2*BUFW*4, pBh + ko); cp16(sb + 2*BUFW*4 + 16, pBh + ko + 8);
        cp16(sb + 3*BUFW*4, pBl + ko); cp16(sb + 3*BUFW*4 + 16, pBl + ko + 8);
        CP_COMMIT();
    }

    const int niter = K / 32;
    for (int it = 0; it < niter; it++) {
        CP_WAIT1();
        __syncthreads();
        int cur = it & 1;
        const uint32_t* sAh = dsm + cur * STGW;
        const uint32_t* sAl = sAh + BUFW;
        const uint32_t* sBh = sAh + 2 * BUFW;
        const uint32_t* sBl = sAh + 3 * BUFW;

        #pragma unroll
        for (int kk = 0; kk < 16; kk += 8) {
            uint32_t afh[2][4], afl[2][4];
            #pragma unroll
            for (int mt = 0; mt < 2; mt++) {
                int rr = (wm0 + mt * 16 + gr) * 20 + kk + gc;
                afh[mt][0] = sAh[rr];
                afh[mt][1] = sAh[rr + 8 * 20];
                afh[mt][2] = sAh[rr + 4];
                afh[mt][3] = sAh[rr + 8 * 20 + 4];
                afl[mt][0] = sAl[rr];
                afl[mt][1] = sAl[rr + 8 * 20];
                afl[mt][2] = sAl[rr + 4];
                afl[mt][3] = sAl[rr + 8 * 20 + 4];
            }
            #pragma unroll
            for (int nt = 0; nt < 8; nt++) {
                int nn = (wn0 + nt * 8 + gr) * 20 + kk + gc;
                uint32_t bh0 = sBh[nn], bh1 = sBh[nn + 4];
                uint32_t bl0 = sBl[nn], bl1 = sBl[nn + 4];
                #pragma unroll
                for (int mt = 0; mt < 2; mt++) {
                    mma_bf16(c[mt][nt][0], c[mt][nt][1], c[mt][nt][2], c[mt][nt][3],
                             afh[mt][0], afh[mt][1], afh[mt][2], afh[mt][3], bh0, bh1);
                    mma_bf16(c[mt][nt][0], c[mt][nt][1], c[mt][nt][2], c[mt][nt][3],
                             afh[mt][0], afh[mt][1], afh[mt][2], afh[mt][3], bl0, bl1);
                    mma_bf16(c[mt][nt][0], c[mt][nt][1], c[mt][nt][2], c[mt][nt][3],
                             afl[mt][0], afl[mt][1], afl[mt][2], afl[mt][3], bh0, bh1);
                }
            }
        }

        __syncthreads();
        if (it + 2 < niter) {
            int ko = (it + 2) * 32;
            uint32_t sb = sbase + cur * STGW * 4 + soff;
            cp16(sb,            pAh + ko); cp16(sb + 16,            pAh + ko + 8);
            cp16(sb + BUFW*4,   pAl + ko); cp16(sb + BUFW*4 + 16,   pAl + ko + 8);
            cp16(sb + 2*BUFW*4, pBh + ko); cp16(sb + 2*BUFW*4 + 16, pBh + ko + 8);
            cp16(sb + 3*BUFW*4, pBl + ko); cp16(sb + 3*BUFW*4 + 16, pBl + ko + 8);
        }
        CP_COMMIT();
    }

    #pragma unroll
    for (int mt = 0; mt < 2; mt++) {
        #pragma unroll
        for (int nt = 0; nt < 8; nt++) {
            int row = bm0 + wm0 + mt * 16 + gr;
            int col = bn0 + wn0 + nt * 8 + gc * 2;
            #pragma unroll
            for (int half = 0; half < 2; half++) {
                int r = row + half * 8;
                float vx = c[mt][nt][half * 2 + 0];
                float vy = c[mt][nt][half * 2 + 1];
                size_t idx = (size_t)r * N + col;
                if (EPI == 1) {
                    float2 rr = *(const float2*)(R + idx);
                    vx += rr.x; vy += rr.y;
                    float2 ov; ov.x = vx; ov.y = vy;
                    *(float2*)(C + idx) = ov;
                } else if (EPI == 2) {
                    vx = vx / (1.f + __expf(-vx));
                    vy = vy / (1.f + __expf(-vy));
                    __nv_bfloat16 hx, lx, hy, ly;
                    bf16_split(vx, hx, lx);
                    bf16_split(vy, hy, ly);
                    __nv_bfloat162 ph; ph.x = hx; ph.y = hy;
                    __nv_bfloat162 pl; pl.x = lx; pl.y = ly;
                    *(__nv_bfloat162*)(Cbh + idx) = ph;
                    *(__nv_bfloat162*)(Cbl + idx) = pl;
                } else {
                    float2 ov; ov.x = vx; ov.y = vy;
                    *(float2*)(C + idx) = ov;
                }
            }
        }
    }
}

// ================= LM head GEMM: fp16 single-pass, cp.async 2-stage =================
__global__ __launch_bounds__(256, 2) void gemm_lm_h(const __half* __restrict__ A,
                                                    const __half* __restrict__ B,
                                                    float* __restrict__ C,
                                                    int N, int K)
{
    __shared__ uint32_t sA[2][128][20];
    __shared__ uint32_t sB[2][128][20];

    int t    = threadIdx.x;
    int lane = t & 31;
    int wid  = t >> 5;
    int bm0  = blockIdx.y * 128;
    int bn0  = blockIdx.x * 128;
    int wm0  = (wid & 3) * 32;
    int wn0  = (wid >> 2) * 64;
    int gr   = lane >> 2;
    int gc   = lane & 3;

    int lrow = t >> 1;
    int lkw  = (t & 1) * 8;

    const __half* Ap = A + (size_t)(bm0 + lrow) * K + lkw * 2;
    const __half* Bp = B + (size_t)(bn0 + lrow) * K + lkw * 2;

    float c[2][8][4];
    #pragma unroll
    for (int i = 0; i < 2; i++)
        #pragma unroll
        for (int j = 0; j < 8; j++)
            #pragma unroll
            for (int q = 0; q < 4; q++) c[i][j][q] = 0.f;

    uint32_t saA0 = (uint32_t)__cvta_generic_to_shared(&sA[0][lrow][lkw]);
    uint32_t saB0 = (uint32_t)__cvta_generic_to_shared(&sB[0][lrow][lkw]);
    const uint32_t stageStride = 128 * 20 * 4;

    #pragma unroll
    for (int s = 0; s < 2; s++) {
        int ko = s * 32;
        cp16(saA0 + s * stageStride,      Ap + ko);
        cp16(saA0 + s * stageStride + 16, Ap + ko + 8);
        cp16(saB0 + s * stageStride,      Bp + ko);
        cp16(saB0 + s * stageStride + 16, Bp + ko + 8);
        CP_COMMIT();
    }

    const int niter = K / 32;    // 8
    for (int it = 0; it < niter; it++) {
        CP_WAIT1();
        __syncthreads();
        int cur = it & 1;

        #pragma unroll
        for (int kk = 0; kk < 16; kk += 8) {
            uint32_t af[2][4], bf[8][2];
            #pragma unroll
            for (int mt = 0; mt < 2; mt++) {
                int rr = wm0 + mt * 16 + gr;
                af[mt][0] = sA[cur][rr][kk + gc];
                af[mt][1] = sA[cur][rr + 8][kk + gc];
                af[mt][2] = sA[cur][rr][kk + 4 + gc];
                af[mt][3] = sA[cur][rr + 8][kk + 4 + gc];
            }
            #pragma unroll
            for (int nt = 0; nt < 8; nt++) {
                int n0 = wn0 + nt * 8 + gr;
                bf[nt][0] = sB[cur][n0][kk + gc];
                bf[nt][1] = sB[cur][n0][kk + 4 + gc];
            }
            #pragma unroll
            for (int mt = 0; mt < 2; mt++)
                #pragma unroll
                for (int nt = 0; nt < 8; nt++)
                    mma_fp16(c[mt][nt][0], c[mt][nt][1], c[mt][nt][2], c[mt][nt][3],
                             af[mt][0], af[mt][1], af[mt][2], af[mt][3],
                             bf[nt][0], bf[nt][1]);
        }

        __syncthreads();
        if (it + 2 < niter) {
            int ko = (it + 2) * 32;
            cp16(saA0 + cur * stageStride,      Ap + ko);
            cp16(saA0 + cur * stageStride + 16, Ap + ko + 8);
            cp16(saB0 + cur * stageStride,      Bp + ko);
            cp16(saB0 + cur * stageStride + 16, Bp + ko + 8);
        }
        CP_COMMIT();
    }

    #pragma unroll
    for (int mt = 0; mt < 2; mt++) {
        #pragma unroll
        for (int nt = 0; nt < 8; nt++) {
            int row = bm0 + wm0 + mt * 16 + gr;
            int col = bn0 + wn0 + nt * 8 + gc * 2;
            #pragma unroll
            for (int half = 0; half < 2; half++) {
                int r = row + half * 8;
                float2 ov;
                ov.x = c[mt][nt][half * 2 + 0];
                ov.y = c[mt][nt][half * 2 + 1];
                *(float2*)(C + (size_t)r * N + col) = ov;
            }
        }
    }
}

// ---------------- classifier heads ----------------
__global__ void heads_kernel(const float* __restrict__ X,
                             const float* __restrict__ fnw,
                             const float* __restrict__ rw, const float* __restrict__ rb,
                             const float* __restrict__ mw, const float* __restrict__ mb,
                             float* __restrict__ out)
{
    int w = threadIdx.x >> 5, lane = threadIdx.x & 31;
    if (w >= Bk) return;
    const float* x = X + (size_t)w * Lk * Dk;
    float ss = 0.f;
    for (int d = lane; d < Dk; d += 32) { float v = x[d]; ss += v * v; }
    #pragma unroll
    for (int o = 16; o > 0; o >>= 1) ss += __shfl_xor_sync(0xffffffffu, ss, o);
    float rs = rsqrtf(ss * (1.0f / Dk) + 1.1920929e-07f);
    float sr = 0.f, sm = 0.f;
    for (int d = lane; d < Dk; d += 32) {
        float xn = x[d] * rs * fnw[d];
        sr += xn * rw[d];
        sm += xn * mw[d];
    }
    #pragma unroll
    for (int o = 16; o > 0; o >>= 1) {
        sr += __shfl_down_sync(0xffffffffu, sr, o);
        sm += __shfl_down_sync(0xffffffffu, sm, o);
    }
    if (lane == 0) {
        out[w]      = sr + rb[0];
        out[Bk + w] = sm + mb[0];
    }
}

// ---------------- launch ----------------
extern "C" void kernel_launch(void* const* d_in, const int* in_sizes, int n_in,
                              void* d_out, int out_size)
{
    const int*   ids      = (const int*)d_in[0];
    const int*   tts      = (const int*)d_in[1];
    const int*   mask     = (const int*)d_in[2];
    const float* tok_emb  = (const float*)d_in[3];
    const float* type_emb = (const float*)d_in[4];
    const float* norm1    = (const float*)d_in[5];
    const float* wq       = (const float*)d_in[6];
    const float* wk       = (const float*)d_in[7];
    const float* wv       = (const float*)d_in[8];
    const float* wo       = (const float*)d_in[9];
    const float* norm2    = (const float*)d_in[10];
    const float* fw1      = (const float*)d_in[11];
    const float* fw2      = (const float*)d_in[12];
    const float* fnorm    = (const float*)d_in[13];
    const float* lmw      = (const float*)d_in[14];
    const float* rw       = (const float*)d_in[15];
    const float* rbias    = (const float*)d_in[16];
    const float* mw       = (const float*)d_in[17];
    const float* mbias    = (const float*)d_in[18];
    float* out = (float*)d_out;

    float *X, *Q, *K, *V;
    __nv_bfloat16 *XNh, *XNl, *AOh, *AOl, *F1h, *F1l, *Wh, *Wl;
    __half *XNH16, *LWH;
    cudaGetSymbolAddress((void**)&X,     g_X);
    cudaGetSymbolAddress((void**)&Q,     g_Q);
    cudaGetSymbolAddress((void**)&K,     g_K);
    cudaGetSymbolAddress((void**)&V,     g_V);
    cudaGetSymbolAddress((void**)&XNh,   g_XNh);
    cudaGetSymbolAddress((void**)&XNl,   g_XNl);
    cudaGetSymbolAddress((void**)&AOh,   g_AOh);
    cudaGetSymbolAddress((void**)&AOl,   g_AOl);
    cudaGetSymbolAddress((void**)&F1h,   g_F1h);
    cudaGetSymbolAddress((void**)&F1l,   g_F1l);
    cudaGetSymbolAddress((void**)&Wh,    g_Wh);
    cudaGetSymbolAddress((void**)&Wl,    g_Wl);
    cudaGetSymbolAddress((void**)&XNH16, g_XNH16);
    cudaGetSymbolAddress((void**)&LWH,   g_LWH);

    const int dynSmem = STGW * 2 * 4;   // 81920 bytes
    cudaFuncSetAttribute(gemm_bfs<0>, cudaFuncAttributeMaxDynamicSharedMemorySize, dynSmem);
    cudaFuncSetAttribute(gemm_bfs<1>, cudaFuncAttributeMaxDynamicSharedMemorySize, dynSmem);
    cudaFuncSetAttribute(gemm_bfs<2>, cudaFuncAttributeMaxDynamicSharedMemorySize, dynSmem);

    embed_kernel<<<(MR * Dk) / 256, 256>>>(ids, tts, tok_emb, type_emb, X);
    cvt_f16_kernel<<<(Vk * Dk) / 256, 256>>>(lmw, LWH, Vk * Dk);

    split_bf16_kernel<<<(NLk*Dk*Dk) / 256, 256>>>(wq,  Wh + OFF_WQ, Wl + OFF_WQ, NLk*Dk*Dk);
    split_bf16_kernel<<<(NLk*Dk*Dk) / 256, 256>>>(wk,  Wh + OFF_WK, Wl + OFF_WK, NLk*Dk*Dk);
    split_bf16_kernel<<<(NLk*Dk*Dk) / 256, 256>>>(wv,  Wh + OFF_WV, Wl + OFF_WV, NLk*Dk*Dk);
    split_bf16_kernel<<<(NLk*Dk*Dk) / 256, 256>>>(wo,  Wh + OFF_WO, Wl + OFF_WO, NLk*Dk*Dk);
    split_bf16_kernel<<<(NLk*FFD*Dk) / 256, 256>>>(fw1, Wh + OFF_F1, Wl + OFF_F1, NLk*FFD*Dk);
    split_bf16_kernel<<<(NLk*FFD*Dk) / 256, 256>>>(fw2, Wh + OFF_F2, Wl + OFF_F2, NLk*FFD*Dk);

    dim3 gqkv(Dk  / 128, MR / 128, 3);
    dim3 gs  (Dk  / 128, MR / 128, 1);
    dim3 gf1 (FFD / 128, MR / 128, 1);
    dim3 glm (Vk  / 128, MR / 128);
    dim3 ga  (Lk / 64, Hk, Bk);
    dim3 grp ((MR * Hk * 32) / 256, 2);

    for (int i = 0; i < NLk; i++) {
        size_t od = (size_t)i * Dk * Dk;
        size_t of = (size_t)i * FFD * Dk;
        const __nv_bfloat16 *qh = Wh + OFF_WQ + od, *ql = Wl + OFF_WQ + od;
        const __nv_bfloat16 *kh = Wh + OFF_WK + od, *kl = Wl + OFF_WK + od;
        const __nv_bfloat16 *vh = Wh + OFF_WV + od, *vl = Wl + OFF_WV + od;
        const __nv_bfloat16 *oh = Wh + OFF_WO + od, *ol = Wl + OFF_WO + od;
        const __nv_bfloat16 *f1h = Wh + OFF_F1 + of, *f1l = Wl + OFF_F1 + of;
        const __nv_bfloat16 *f2h = Wh + OFF_F2 + of, *f2l = Wl + OFF_F2 + of;

        rmsnorm_kernel<<<MR, 256>>>(X, norm1 + (size_t)i * Dk, XNh, XNl);
        gemm_bfs<0><<<gqkv, 256, dynSmem>>>(XNh, XNl, qh, ql, kh, kl, vh, vl,
                                            nullptr, Q, K, V, nullptr, nullptr, Dk, Dk);
        rope2_kernel<<<grp, 256>>>(Q, K);
        attn_fa<<<ga, 128>>>(Q, K, V, mask, AOh, AOl);
        gemm_bfs<1><<<gs, 256, dynSmem>>>(AOh, AOl, oh, ol, oh, ol, oh, ol,
                                          X, X, X, X, nullptr, nullptr, Dk, Dk);
        rmsnorm_kernel<<<MR, 256>>>(X, norm2 + (size_t)i * Dk, XNh, XNl);
        gemm_bfs<2><<<gf1, 256, dynSmem>>>(XNh, XNl, f1h, f1l, f1h, f1l, f1h, f1l,
                                           nullptr, nullptr, nullptr, nullptr,
                                           F1h, F1l, FFD, Dk);
        gemm_bfs<1><<<gs, 256, dynSmem>>>(F1h, F1l, f2h, f2l, f2h, f2l, f2h, f2l,
                                          X, X, X, X, nullptr, nullptr, Dk, FFD);
    }

    rmsnorm_f16_kernel<<<MR, 256>>>(X, fnorm, XNH16);
    gemm_lm_h<<<glm, 256>>>(XNH16, LWH, out, Vk, Dk);
    heads_kernel<<<1, 128>>>(X, fnorm, rw, rbias, mw, mbias, out + (size_t)Bk * Lk * Vk);
}